// round 6
// baseline (speedup 1.0000x reference)
#include <cuda_runtime.h>
#include <cuda_bf16.h>
#include <math.h>

// Problem constants
#define BB 64
#define SS 256
#define HH 1024
#define EE 512
#define GG 4096   // 4*H

// -------- scratch (device globals: sanctioned, no allocations) --------
__device__ float g_P0[(size_t)SS * BB * GG];  // precomputed input-side gates
__device__ float g_sp[BB * GG];               // static-part gates (time-invariant)
__device__ float g_b1[GG];                    // b_ih_l1 + b_hh_l1
__device__ float g_h0[2][BB * HH];            // double-buffered recurrent h (layer 0)
__device__ float g_h1[2][BB * HH];            // double-buffered recurrent h (layer 1)
__device__ float g_c0[BB * HH];               // cell states (owner-only access)
__device__ float g_c1[BB * HH];

// -------- packed fp32x2 FMA helpers --------
typedef unsigned long long u64t;

__device__ __forceinline__ void fma2(u64t& c, u64t a, u64t b) {
    asm("fma.rn.f32x2 %0, %1, %2, %0;" : "+l"(c) : "l"(a), "l"(b));
}
__device__ __forceinline__ float hsum2(u64t v) {
    return __uint_as_float((unsigned)(v & 0xffffffffu)) +
           __uint_as_float((unsigned)(v >> 32));
}
__device__ __forceinline__ float sigf(float x) { return 1.0f / (1.0f + expf(-x)); }

// =====================================================================
// k_init
// =====================================================================
__global__ void k_init(const float* __restrict__ enc_h, const float* __restrict__ enc_c,
                       const float* __restrict__ b_ih1, const float* __restrict__ b_hh1) {
    int i = blockIdx.x * blockDim.x + threadIdx.x;
    const int n = BB * HH;
    if (i < n) {
        g_h0[0][i] = enc_h[i];
        g_c0[i]    = enc_c[i];
        g_h1[0][i] = enc_h[n + i];
        g_c1[i]    = enc_c[n + i];
    }
    if (i < GG) g_b1[i] = b_ih1[i] + b_hh1[i];
}

// =====================================================================
// k_static: one-time static-part gates (small; unchanged from R4)
// =====================================================================
__global__ void __launch_bounds__(256) k_static(
    const float* __restrict__ enc_outs, const int* __restrict__ src_lang,
    const float* __restrict__ embed, const float* __restrict__ W0,
    const float* __restrict__ b_ih0, const float* __restrict__ b_hh0) {
    __shared__ float sC[8][EE];
    __shared__ float sL[8][EE];
    const int tid = threadIdx.x;
    const int b0 = blockIdx.y * 8;

    for (int i = tid; i < 8 * EE; i += 256) {
        int b = i >> 9, k = i & (EE - 1);
        sC[b][k] = enc_outs[((size_t)(b0 + b) * 128 + 127) * EE + k];
        sL[b][k] = embed[(size_t)src_lang[b0 + b] * EE + k];
    }
    __syncthreads();

    const int g = blockIdx.x * 256 + tid;
    const float* wr = W0 + (size_t)g * 1536;
    float acc[8];
#pragma unroll
    for (int i = 0; i < 8; i++) acc[i] = 0.0f;

    for (int k = 0; k < EE; k += 4) {
        float4 wc = *reinterpret_cast<const float4*>(wr + 512 + k);
        float4 wl = *reinterpret_cast<const float4*>(wr + 1024 + k);
#pragma unroll
        for (int b = 0; b < 8; b++) {
            float4 c4 = *reinterpret_cast<const float4*>(&sC[b][k]);
            float4 l4 = *reinterpret_cast<const float4*>(&sL[b][k]);
            acc[b] += wc.x * c4.x + wc.y * c4.y + wc.z * c4.z + wc.w * c4.w;
            acc[b] += wl.x * l4.x + wl.y * l4.y + wl.z * l4.z + wl.w * l4.w;
        }
    }
    float bias = b_ih0[g] + b_hh0[g];
#pragma unroll
    for (int b = 0; b < 8; b++) g_sp[(b0 + b) * GG + g] = acc[b] + bias;
}

// =====================================================================
// k_precompute: P0[t][b][g] = embed[tok[b][t]][:512] @ W_ih0[g][:512] + sp[b][g]
// W now staged via smem (coalesced) with register double-buffering.
// grid (SS, GG/32), 256 threads.
// =====================================================================
__global__ void __launch_bounds__(256) k_precompute(
    const int* __restrict__ tokens, const float* __restrict__ embed,
    const float* __restrict__ W0) {
    __shared__ __align__(16) float sA[64][68];
    __shared__ __align__(16) float sW[32][68];
    __shared__ int sTok[64];
    const int tid = threadIdx.x;
    const int t = blockIdx.x;
    const int col0 = blockIdx.y * 32;

    const int j = tid & 31, mg = tid >> 5;

    // A-load mapping: row = tid>>2, 4 float4 per thread
    const int ar = tid >> 2, al = tid & 3;
    // W-load mapping: row = tid>>3, 8 contiguous floats at (tid&7)*8
    const int wri = tid >> 3, wci = (tid & 7) * 8;
    const float* wgrow = W0 + (size_t)(col0 + wri) * 1536 + wci;

    if (tid < 64) sTok[tid] = tokens[tid * SS + t];
    __syncthreads();
    const float* arow = embed + (size_t)sTok[ar] * EE;

    u64t acc[8];
#pragma unroll
    for (int i = 0; i < 8; i++) acc[i] = 0ull;

    float4 pA[4], pW[2];
    // prefetch chunk 0
#pragma unroll
    for (int q = 0; q < 4; q++)
        pA[q] = *reinterpret_cast<const float4*>(arow + (al + 4 * q) * 4);
    pW[0] = *reinterpret_cast<const float4*>(wgrow);
    pW[1] = *reinterpret_cast<const float4*>(wgrow + 4);

#pragma unroll 1
    for (int c = 0; c < EE / 64; c++) {
#pragma unroll
        for (int q = 0; q < 4; q++)
            *reinterpret_cast<float4*>(&sA[ar][(al + 4 * q) * 4]) = pA[q];
        *reinterpret_cast<float4*>(&sW[wri][wci]) = pW[0];
        *reinterpret_cast<float4*>(&sW[wri][wci + 4]) = pW[1];
        __syncthreads();

        if (c + 1 < EE / 64) {
            int k1 = (c + 1) * 64;
#pragma unroll
            for (int q = 0; q < 4; q++)
                pA[q] = *reinterpret_cast<const float4*>(arow + k1 + (al + 4 * q) * 4);
            pW[0] = *reinterpret_cast<const float4*>(wgrow + k1);
            pW[1] = *reinterpret_cast<const float4*>(wgrow + k1 + 4);
        }

#pragma unroll
        for (int kk = 0; kk < 64; kk += 4) {
            ulonglong2 w = *reinterpret_cast<const ulonglong2*>(&sW[j][kk]);
#pragma unroll
            for (int mi = 0; mi < 8; mi++) {
                ulonglong2 a = *reinterpret_cast<const ulonglong2*>(&sA[mg * 8 + mi][kk]);
                fma2(acc[mi], a.x, w.x);
                fma2(acc[mi], a.y, w.y);
            }
        }
        __syncthreads();
    }

    const int col = col0 + j;
#pragma unroll
    for (int mi = 0; mi < 8; mi++) {
        int m = mg * 8 + mi;
        g_P0[((size_t)t * BB + m) * GG + col] = hsum2(acc[mi]) + g_sp[m * GG + col];
    }
}

// =====================================================================
// k_layer0: one step of LSTM layer 0, W via smem + reg double-buffer.
// grid 128, 256 threads. Block owns 8 hidden units (32 gate cols).
// =====================================================================
__global__ void __launch_bounds__(256) k_layer0(int t, const float* __restrict__ W) {
    __shared__ __align__(16) float sA[64][68];
    __shared__ __align__(16) float sW[32][68];
    __shared__ float sg[64][32];
    const int tid = threadIdx.x;
    const int hu0 = blockIdx.x * 8;
    const int rd = t & 1, wrb = 1 - rd;

    const int j = tid & 31, mg = tid >> 5;

    const int ar = tid >> 2, al = tid & 3;
    const int wri = tid >> 3, wci = (tid & 7) * 8;
    // gate-col for W row wri (same (q,hh) encoding as j)
    const int gcol_w = (wri >> 3) * HH + hu0 + (wri & 7);
    const float* wgrow = W + (size_t)gcol_w * HH + wci;
    const float* arow = g_h0[rd] + ar * HH;

    u64t acc[8];
#pragma unroll
    for (int i = 0; i < 8; i++) acc[i] = 0ull;

    float4 pA[4], pW[2];
#pragma unroll
    for (int q = 0; q < 4; q++)
        pA[q] = *reinterpret_cast<const float4*>(arow + (al + 4 * q) * 4);
    pW[0] = *reinterpret_cast<const float4*>(wgrow);
    pW[1] = *reinterpret_cast<const float4*>(wgrow + 4);

#pragma unroll 1
    for (int c = 0; c < HH / 64; c++) {
#pragma unroll
        for (int q = 0; q < 4; q++)
            *reinterpret_cast<float4*>(&sA[ar][(al + 4 * q) * 4]) = pA[q];
        *reinterpret_cast<float4*>(&sW[wri][wci]) = pW[0];
        *reinterpret_cast<float4*>(&sW[wri][wci + 4]) = pW[1];
        __syncthreads();

        if (c + 1 < HH / 64) {
            int k1 = (c + 1) * 64;
#pragma unroll
            for (int q = 0; q < 4; q++)
                pA[q] = *reinterpret_cast<const float4*>(arow + k1 + (al + 4 * q) * 4);
            pW[0] = *reinterpret_cast<const float4*>(wgrow + k1);
            pW[1] = *reinterpret_cast<const float4*>(wgrow + k1 + 4);
        }

#pragma unroll
        for (int kk = 0; kk < 64; kk += 4) {
            ulonglong2 w = *reinterpret_cast<const ulonglong2*>(&sW[j][kk]);
#pragma unroll
            for (int mi = 0; mi < 8; mi++) {
                ulonglong2 a = *reinterpret_cast<const ulonglong2*>(&sA[mg * 8 + mi][kk]);
                fma2(acc[mi], a.x, w.x);
                fma2(acc[mi], a.y, w.y);
            }
        }
        __syncthreads();
    }

    const int q = j >> 3, hh = j & 7;
    const int col = q * HH + hu0 + hh;
    const float* p0 = g_P0 + (size_t)t * BB * GG;
#pragma unroll
    for (int mi = 0; mi < 8; mi++) {
        int m = mg * 8 + mi;
        sg[m][j] = hsum2(acc[mi]) + p0[m * GG + col];
    }
    __syncthreads();

    for (int cc = tid; cc < 512; cc += 256) {
        int m = cc >> 3, h2 = cc & 7;
        float gi = sg[m][h2];
        float gf = sg[m][8 + h2];
        float gg = sg[m][16 + h2];
        float go = sg[m][24 + h2];
        int idx = m * HH + hu0 + h2;
        float cn = sigf(gf) * g_c0[idx] + sigf(gi) * tanhf(gg);
        g_c0[idx] = cn;
        g_h0[wrb][idx] = sigf(go) * tanhf(cn);
    }
}

// =====================================================================
// k_layer1: one step of layer 1. Two GEMM phases (h0_new@Wih1, h1_prev@Whh1),
// 32 chunks total, same smem staging + prefetch.
// =====================================================================
__global__ void __launch_bounds__(256) k_layer1(int t, const float* __restrict__ Wih1,
                                                const float* __restrict__ Whh1,
                                                float* __restrict__ out) {
    __shared__ __align__(16) float sA[64][68];
    __shared__ __align__(16) float sW[32][68];
    __shared__ float sg[64][32];
    const int tid = threadIdx.x;
    const int hu0 = blockIdx.x * 8;
    const int rd = t & 1, wrb = 1 - rd;

    const int j = tid & 31, mg = tid >> 5;

    const int ar = tid >> 2, al = tid & 3;
    const int wri = tid >> 3, wci = (tid & 7) * 8;
    const int gcol_w = (wri >> 3) * HH + hu0 + (wri & 7);
    const size_t woff = (size_t)gcol_w * HH + wci;

    const float* Ab[2] = { g_h0[wrb], g_h1[rd] };
    const float* Wb[2] = { Wih1 + woff, Whh1 + woff };

    u64t acc[8];
#pragma unroll
    for (int i = 0; i < 8; i++) acc[i] = 0ull;

    float4 pA[4], pW[2];
    {
        const float* arow = Ab[0] + ar * HH;
#pragma unroll
        for (int q = 0; q < 4; q++)
            pA[q] = *reinterpret_cast<const float4*>(arow + (al + 4 * q) * 4);
        pW[0] = *reinterpret_cast<const float4*>(Wb[0]);
        pW[1] = *reinterpret_cast<const float4*>(Wb[0] + 4);
    }

#pragma unroll 1
    for (int c = 0; c < 32; c++) {
#pragma unroll
        for (int q = 0; q < 4; q++)
            *reinterpret_cast<float4*>(&sA[ar][(al + 4 * q) * 4]) = pA[q];
        *reinterpret_cast<float4*>(&sW[wri][wci]) = pW[0];
        *reinterpret_cast<float4*>(&sW[wri][wci + 4]) = pW[1];
        __syncthreads();

        if (c + 1 < 32) {
            int cn = c + 1;
            int ph = cn >> 4;
            int k1 = (cn & 15) * 64;
            const float* arow = Ab[ph] + ar * HH + k1;
#pragma unroll
            for (int q = 0; q < 4; q++)
                pA[q] = *reinterpret_cast<const float4*>(arow + (al + 4 * q) * 4);
            pW[0] = *reinterpret_cast<const float4*>(Wb[ph] + k1);
            pW[1] = *reinterpret_cast<const float4*>(Wb[ph] + k1 + 4);
        }

#pragma unroll
        for (int kk = 0; kk < 64; kk += 4) {
            ulonglong2 w = *reinterpret_cast<const ulonglong2*>(&sW[j][kk]);
#pragma unroll
            for (int mi = 0; mi < 8; mi++) {
                ulonglong2 a = *reinterpret_cast<const ulonglong2*>(&sA[mg * 8 + mi][kk]);
                fma2(acc[mi], a.x, w.x);
                fma2(acc[mi], a.y, w.y);
            }
        }
        __syncthreads();
    }

    const int q = j >> 3, hh = j & 7;
    const int col = q * HH + hu0 + hh;
#pragma unroll
    for (int mi = 0; mi < 8; mi++) {
        int m = mg * 8 + mi;
        sg[m][j] = hsum2(acc[mi]) + g_b1[col];
    }
    __syncthreads();

    for (int cc = tid; cc < 512; cc += 256) {
        int m = cc >> 3, h2 = cc & 7;
        float gi = sg[m][h2];
        float gf = sg[m][8 + h2];
        float gg = sg[m][16 + h2];
        float go = sg[m][24 + h2];
        int idx = m * HH + hu0 + h2;
        float cn = sigf(gf) * g_c1[idx] + sigf(gi) * tanhf(gg);
        g_c1[idx] = cn;
        float hn = sigf(go) * tanhf(cn);
        g_h1[wrb][idx] = hn;
        out[(size_t)t * BB * HH + idx] = hn;
    }
}

// =====================================================================
extern "C" void kernel_launch(void* const* d_in, const int* in_sizes, int n_in,
                              void* d_out, int out_size) {
    const int*   tok      = (const int*)d_in[0];
    const int*   src      = (const int*)d_in[1];
    const float* enc_outs = (const float*)d_in[2];
    const float* enc_h    = (const float*)d_in[3];
    const float* enc_c    = (const float*)d_in[4];
    const float* embed    = (const float*)d_in[5];
    const float* W_ih0    = (const float*)d_in[6];
    const float* W_hh0    = (const float*)d_in[7];
    const float* b_ih0    = (const float*)d_in[8];
    const float* b_hh0    = (const float*)d_in[9];
    const float* W_ih1    = (const float*)d_in[10];
    const float* W_hh1    = (const float*)d_in[11];
    const float* b_ih1    = (const float*)d_in[12];
    const float* b_hh1    = (const float*)d_in[13];
    float* out = (float*)d_out;

    k_init<<<(BB * HH + 255) / 256, 256>>>(enc_h, enc_c, b_ih1, b_hh1);
    k_static<<<dim3(GG / 256, BB / 8), 256>>>(enc_outs, src, embed, W_ih0, b_ih0, b_hh0);
    k_precompute<<<dim3(SS, GG / 32), 256>>>(tok, embed, W_ih0);

    for (int t = 0; t < SS; t++) {
        k_layer0<<<HH / 8, 256>>>(t, W_hh0);
        k_layer1<<<HH / 8, 256>>>(t, W_ih1, W_hh1, out);
    }
}

// round 8
// speedup vs baseline: 1.4330x; 1.4330x over previous
#include <cuda_runtime.h>
#include <cuda_bf16.h>
#include <math.h>
#include <stdint.h>

#define BB 64
#define SS 256
#define HH 1024
#define EE 512
#define GG 4096
#define NCTA 64
#define UPC 16

// dynamic smem layout (bytes):
//  A stage s: SA_OFF(s) (hi at +0, lo at +9216), 64 rows x 72 bf16 (144B rows)
//  B stage s: SB_OFF(s) likewise
//  D tile: 64 x 66 f32
#define SA_OFF(s) ((s) * 18432)
#define SB_OFF(s) (36864 + (s) * 18432)
#define SD_OFF 73728
#define DYN_SMEM 90624

// -------- device-global scratch --------
__device__ float g_P0[(size_t)SS * BB * GG];
__device__ float g_sp[BB * GG];
__device__ float g_b1[GG];
__device__ float g_c0[BB * HH];
__device__ float g_c1[BB * HH];
__device__ __nv_bfloat16 g_h0hi[2][BB * HH];
__device__ __nv_bfloat16 g_h0lo[2][BB * HH];
__device__ __nv_bfloat16 g_h1hi[2][BB * HH];
__device__ __nv_bfloat16 g_h1lo[2][BB * HH];
// pre-gathered dense weight tiles [cta][slot][64n][64k] bf16
__device__ __align__(16) __nv_bfloat16 g_B0hi[(size_t)NCTA * 16 * 4096];
__device__ __align__(16) __nv_bfloat16 g_B0lo[(size_t)NCTA * 16 * 4096];
__device__ __align__(16) __nv_bfloat16 g_B1hi[(size_t)NCTA * 32 * 4096];
__device__ __align__(16) __nv_bfloat16 g_B1lo[(size_t)NCTA * 32 * 4096];

typedef unsigned long long u64t;
union F4 { float4 v; float f[4]; };
union P8 { __nv_bfloat16 h[8]; uint4 v; };

__device__ __forceinline__ void fma2(u64t& c, u64t a, u64t b) {
    asm("fma.rn.f32x2 %0, %1, %2, %0;" : "+l"(c) : "l"(a), "l"(b));
}
__device__ __forceinline__ float hsum2(u64t v) {
    return __uint_as_float((unsigned)(v & 0xffffffffu)) +
           __uint_as_float((unsigned)(v >> 32));
}
__device__ __forceinline__ float sigf(float x) { return 1.0f / (1.0f + expf(-x)); }

__device__ __forceinline__ uint32_t smem_u32(const void* p) {
    uint32_t a;
    asm("{ .reg .u64 t; cvta.to.shared.u64 t, %1; cvt.u32.u64 %0, t; }" : "=r"(a) : "l"(p));
    return a;
}
__device__ __forceinline__ void cpa16(uint32_t d, const void* s) {
    asm volatile("cp.async.cg.shared.global [%0], [%1], 16;" :: "r"(d), "l"(s));
}
#define CP_COMMIT() asm volatile("cp.async.commit_group;" ::: "memory")

__device__ __forceinline__ void ldsm4(uint32_t* r, uint32_t a) {
    asm volatile("ldmatrix.sync.aligned.m8n8.x4.shared.b16 {%0,%1,%2,%3}, [%4];"
                 : "=r"(r[0]), "=r"(r[1]), "=r"(r[2]), "=r"(r[3]) : "r"(a));
}
__device__ __forceinline__ void mma_bf16(float* d, const uint32_t* a, uint32_t b0, uint32_t b1) {
    asm volatile(
        "mma.sync.aligned.m16n8k16.row.col.f32.bf16.bf16.f32 "
        "{%0,%1,%2,%3}, {%4,%5,%6,%7}, {%8,%9}, {%0,%1,%2,%3};"
        : "+f"(d[0]), "+f"(d[1]), "+f"(d[2]), "+f"(d[3])
        : "r"(a[0]), "r"(a[1]), "r"(a[2]), "r"(a[3]), "r"(b0), "r"(b1));
}

// =====================================================================
// k_init: states + bias fold + bf16 hi/lo conversion of initial h
// =====================================================================
__global__ void k_init(const float* __restrict__ enc_h, const float* __restrict__ enc_c,
                       const float* __restrict__ b_ih1, const float* __restrict__ b_hh1) {
    int i = blockIdx.x * blockDim.x + threadIdx.x;
    const int n = BB * HH;
    if (i < n) {
        float h0v = enc_h[i], h1v = enc_h[n + i];
        __nv_bfloat16 a = __float2bfloat16(h0v);
        g_h0hi[0][i] = a;
        g_h0lo[0][i] = __float2bfloat16(h0v - __bfloat162float(a));
        __nv_bfloat16 b = __float2bfloat16(h1v);
        g_h1hi[0][i] = b;
        g_h1lo[0][i] = __float2bfloat16(h1v - __bfloat162float(b));
        g_c0[i] = enc_c[i];
        g_c1[i] = enc_c[n + i];
    }
    if (i < GG) g_b1[i] = b_ih1[i] + b_hh1[i];
}

// =====================================================================
// k_static (proven, unchanged)
// =====================================================================
__global__ void __launch_bounds__(256) k_static(
    const float* __restrict__ enc_outs, const int* __restrict__ src_lang,
    const float* __restrict__ embed, const float* __restrict__ W0,
    const float* __restrict__ b_ih0, const float* __restrict__ b_hh0) {
    __shared__ float sC[8][EE];
    __shared__ float sL[8][EE];
    const int tid = threadIdx.x;
    const int b0 = blockIdx.y * 8;
    for (int i = tid; i < 8 * EE; i += 256) {
        int b = i >> 9, k = i & (EE - 1);
        sC[b][k] = enc_outs[((size_t)(b0 + b) * 128 + 127) * EE + k];
        sL[b][k] = embed[(size_t)src_lang[b0 + b] * EE + k];
    }
    __syncthreads();
    const int g = blockIdx.x * 256 + tid;
    const float* wr = W0 + (size_t)g * 1536;
    float acc[8];
#pragma unroll
    for (int i = 0; i < 8; i++) acc[i] = 0.0f;
    for (int k = 0; k < EE; k += 4) {
        float4 wc = *reinterpret_cast<const float4*>(wr + 512 + k);
        float4 wl = *reinterpret_cast<const float4*>(wr + 1024 + k);
#pragma unroll
        for (int b = 0; b < 8; b++) {
            float4 c4 = *reinterpret_cast<const float4*>(&sC[b][k]);
            float4 l4 = *reinterpret_cast<const float4*>(&sL[b][k]);
            acc[b] += wc.x * c4.x + wc.y * c4.y + wc.z * c4.z + wc.w * c4.w;
            acc[b] += wl.x * l4.x + wl.y * l4.y + wl.z * l4.z + wl.w * l4.w;
        }
    }
    float bias = b_ih0[g] + b_hh0[g];
#pragma unroll
    for (int b = 0; b < 8; b++) g_sp[(b0 + b) * GG + g] = acc[b] + bias;
}

// =====================================================================
// k_precompute (proven, unchanged)
// =====================================================================
__global__ void __launch_bounds__(256) k_precompute(
    const int* __restrict__ tokens, const float* __restrict__ embed,
    const float* __restrict__ W0) {
    __shared__ __align__(16) float sA[64][68];
    __shared__ __align__(16) float sW[32][68];
    __shared__ int sTok[64];
    const int tid = threadIdx.x;
    const int t = blockIdx.x;
    const int col0 = blockIdx.y * 32;
    const int j = tid & 31, mg = tid >> 5;
    const int ar = tid >> 2, al = tid & 3;
    const int wri = tid >> 3, wci = (tid & 7) * 8;
    const float* wgrow = W0 + (size_t)(col0 + wri) * 1536 + wci;

    if (tid < 64) sTok[tid] = tokens[tid * SS + t];
    __syncthreads();
    const float* arow = embed + (size_t)sTok[ar] * EE;

    u64t acc[8];
#pragma unroll
    for (int i = 0; i < 8; i++) acc[i] = 0ull;

    float4 pA[4], pW[2];
#pragma unroll
    for (int q = 0; q < 4; q++)
        pA[q] = *reinterpret_cast<const float4*>(arow + (al + 4 * q) * 4);
    pW[0] = *reinterpret_cast<const float4*>(wgrow);
    pW[1] = *reinterpret_cast<const float4*>(wgrow + 4);

#pragma unroll 1
    for (int c = 0; c < EE / 64; c++) {
#pragma unroll
        for (int q = 0; q < 4; q++)
            *reinterpret_cast<float4*>(&sA[ar][(al + 4 * q) * 4]) = pA[q];
        *reinterpret_cast<float4*>(&sW[wri][wci]) = pW[0];
        *reinterpret_cast<float4*>(&sW[wri][wci + 4]) = pW[1];
        __syncthreads();
        if (c + 1 < EE / 64) {
            int k1 = (c + 1) * 64;
#pragma unroll
            for (int q = 0; q < 4; q++)
                pA[q] = *reinterpret_cast<const float4*>(arow + k1 + (al + 4 * q) * 4);
            pW[0] = *reinterpret_cast<const float4*>(wgrow + k1);
            pW[1] = *reinterpret_cast<const float4*>(wgrow + k1 + 4);
        }
#pragma unroll
        for (int kk = 0; kk < 64; kk += 4) {
            ulonglong2 w = *reinterpret_cast<const ulonglong2*>(&sW[j][kk]);
#pragma unroll
            for (int mi = 0; mi < 8; mi++) {
                ulonglong2 a = *reinterpret_cast<const ulonglong2*>(&sA[mg * 8 + mi][kk]);
                fma2(acc[mi], a.x, w.x);
                fma2(acc[mi], a.y, w.y);
            }
        }
        __syncthreads();
    }
    const int col = col0 + j;
#pragma unroll
    for (int mi = 0; mi < 8; mi++) {
        int m = mg * 8 + mi;
        g_P0[((size_t)t * BB + m) * GG + col] = hsum2(acc[mi]) + g_sp[m * GG + col];
    }
}

// =====================================================================
// k_prep: gather W rows into dense per-CTA [64n][64k] bf16 hi/lo tiles.
// grid (16, NCTA); which: 0->B0, 1->B1 slots[0,16), 2->B1 slots[16,32)
// local n = q*16+u  <->  global row q*HH + cta*16 + u
// =====================================================================
__global__ void __launch_bounds__(256) k_prep(const float* __restrict__ W, int which) {
    const int c = blockIdx.x, cta = blockIdx.y, tid = threadIdx.x;
    const int nloc = tid >> 2, ks = (tid & 3) * 16;
    const int grow = (nloc >> 4) * HH + cta * UPC + (nloc & 15);
    const float* s = W + (size_t)grow * HH + c * 64 + ks;
    float x[16];
#pragma unroll
    for (int i = 0; i < 4; i++)
        *reinterpret_cast<float4*>(x + 4 * i) = *reinterpret_cast<const float4*>(s + 4 * i);
    P8 ph[2], pl[2];
#pragma unroll
    for (int u = 0; u < 16; u++) {
        __nv_bfloat16 hi = __float2bfloat16(x[u]);
        ph[u >> 3].h[u & 7] = hi;
        pl[u >> 3].h[u & 7] = __float2bfloat16(x[u] - __bfloat162float(hi));
    }
    __nv_bfloat16 *Gh, *Gl;
    size_t base;
    if (which == 0) { Gh = g_B0hi; Gl = g_B0lo; base = ((size_t)cta * 16 + c) * 4096; }
    else { Gh = g_B1hi; Gl = g_B1lo; base = ((size_t)cta * 32 + (which == 2 ? 16 : 0) + c) * 4096; }
    size_t off = base + (size_t)nloc * 64 + ks;
    *reinterpret_cast<uint4*>(Gh + off)     = ph[0].v;
    *reinterpret_cast<uint4*>(Gh + off + 8) = ph[1].v;
    *reinterpret_cast<uint4*>(Gl + off)     = pl[0].v;
    *reinterpret_cast<uint4*>(Gl + off + 8) = pl[1].v;
}

// =====================================================================
// step-kernel building blocks
// =====================================================================
__device__ __forceinline__ void copy_chunk(
    uint32_t smb, int stage, int tid,
    const __nv_bfloat16* gAh, const __nv_bfloat16* gAl, int kbase,
    const __nv_bfloat16* gBh, const __nv_bfloat16* gBl) {
    const uint32_t dA = smb + SA_OFF(stage);
    const uint32_t dB = smb + SB_OFF(stage);
#pragma unroll
    for (int i = tid; i < 512; i += 256) {
        int row = i >> 3, s = i & 7;
        uint32_t so = (uint32_t)row * 144 + (s << 4);
        const char* ah = (const char*)(gAh + (size_t)row * HH + kbase) + (s << 4);
        const char* al = (const char*)(gAl + (size_t)row * HH + kbase) + (s << 4);
        cpa16(dA + so, ah);
        cpa16(dA + 9216 + so, al);
        cpa16(dB + so, (const char*)gBh + ((size_t)i << 4));
        cpa16(dB + 9216 + so, (const char*)gBl + ((size_t)i << 4));
    }
    CP_COMMIT();
}

__device__ __forceinline__ void compute_chunk(uint32_t smb, int stage, int lane,
                                              int M0, int N0, float acc[4][4]) {
    const uint32_t sA = smb + SA_OFF(stage);
    const uint32_t sB = smb + SB_OFF(stage);
    const uint32_t aoff = (uint32_t)(M0 + (lane & 15)) * 144 + ((lane >> 4) << 4);
    const uint32_t boff = (uint32_t)(N0 + (((lane >> 4) & 1) << 3) + (lane & 7)) * 144 +
                          (((lane >> 3) & 1) << 4);
#pragma unroll
    for (int ksi = 0; ksi < 4; ksi++) {
        const uint32_t kb = ksi << 5;
        uint32_t ah[4], al[4], bh[8], bl[8];
        ldsm4(ah, sA + aoff + kb);
        ldsm4(al, sA + 9216 + aoff + kb);
        ldsm4(bh, sB + boff + kb);
        ldsm4(bh + 4, sB + boff + 2304 + kb);
        ldsm4(bl, sB + 9216 + boff + kb);
        ldsm4(bl + 4, sB + 9216 + boff + 2304 + kb);
#pragma unroll
        for (int nt = 0; nt < 4; nt++) {
            mma_bf16(acc[nt], ah, bh[2 * nt], bh[2 * nt + 1]);
            mma_bf16(acc[nt], al, bh[2 * nt], bh[2 * nt + 1]);
            mma_bf16(acc[nt], ah, bl[2 * nt], bl[2 * nt + 1]);
            mma_bf16(acc[nt], al, bl[2 * nt], bl[2 * nt + 1]);
        }
    }
}

__device__ __forceinline__ void store_accums(char* sm, int lane, int M0, int N0,
                                             float acc[4][4]) {
    float* sD = (float*)(sm + SD_OFF);
    int r0 = M0 + (lane >> 2);
#pragma unroll
    for (int nt = 0; nt < 4; nt++) {
        int col = N0 + nt * 8 + (lane & 3) * 2;
        *reinterpret_cast<float2*>(&sD[r0 * 66 + col]) = make_float2(acc[nt][0], acc[nt][1]);
        *reinterpret_cast<float2*>(&sD[(r0 + 8) * 66 + col]) = make_float2(acc[nt][2], acc[nt][3]);
    }
}

// =====================================================================
// k_l0: LSTM layer-0 step. grid NCTA(64), 256 threads.
// =====================================================================
__global__ void __launch_bounds__(256) k_l0(int t) {
    extern __shared__ char sm[];
    const uint32_t smb = smem_u32(sm);
    const int tid = threadIdx.x, lane = tid & 31, warp = tid >> 5;
    const int cta = blockIdx.x, hu0 = cta * UPC;
    const int rd = t & 1, wrb = 1 - rd;
    const int M0 = (warp & 3) * 16, N0 = (warp >> 2) * 32;

    const __nv_bfloat16* gAh = g_h0hi[rd];
    const __nv_bfloat16* gAl = g_h0lo[rd];
    const __nv_bfloat16* gBh = g_B0hi + (size_t)cta * 16 * 4096;
    const __nv_bfloat16* gBl = g_B0lo + (size_t)cta * 16 * 4096;

    float acc[4][4];
#pragma unroll
    for (int i = 0; i < 4; i++)
#pragma unroll
        for (int j = 0; j < 4; j++) acc[i][j] = 0.0f;

    copy_chunk(smb, 0, tid, gAh, gAl, 0, gBh, gBl);
#pragma unroll 1
    for (int c = 0; c < 16; c++) {
        if (c < 15) {
            copy_chunk(smb, (c + 1) & 1, tid, gAh, gAl, (c + 1) * 64,
                       gBh + (size_t)(c + 1) * 4096, gBl + (size_t)(c + 1) * 4096);
            asm volatile("cp.async.wait_group 1;" ::: "memory");
        } else {
            asm volatile("cp.async.wait_group 0;" ::: "memory");
        }
        __syncthreads();
        compute_chunk(smb, c & 1, lane, M0, N0, acc);
        __syncthreads();
    }
    store_accums(sm, lane, M0, N0, acc);
    __syncthreads();

    if (tid < 64) {
        const int m = tid;
        const float* sDr = (const float*)(sm + SD_OFF) + m * 66;
        const float* p0 = g_P0 + ((size_t)t * BB + m) * GG;
        F4 P[4][4], C[4];
#pragma unroll
        for (int q = 0; q < 4; q++)
#pragma unroll
            for (int i = 0; i < 4; i++)
                P[q][i].v = *reinterpret_cast<const float4*>(p0 + q * HH + hu0 + i * 4);
#pragma unroll
        for (int i = 0; i < 4; i++)
            C[i].v = *reinterpret_cast<const float4*>(g_c0 + m * HH + hu0 + i * 4);
        float hv[16];
#pragma unroll
        for (int u = 0; u < 16; u++) {
            float gi = sDr[u]      + P[0][u >> 2].f[u & 3];
            float gf = sDr[16 + u] + P[1][u >> 2].f[u & 3];
            float gg = sDr[32 + u] + P[2][u >> 2].f[u & 3];
            float go = sDr[48 + u] + P[3][u >> 2].f[u & 3];
            float cn = sigf(gf) * C[u >> 2].f[u & 3] + sigf(gi) * tanhf(gg);
            C[u >> 2].f[u & 3] = cn;
            hv[u] = sigf(go) * tanhf(cn);
        }
#pragma unroll
        for (int i = 0; i < 4; i++)
            *reinterpret_cast<float4*>(g_c0 + m * HH + hu0 + i * 4) = C[i].v;
        P8 hh[2], hl[2];
#pragma unroll
        for (int u = 0; u < 16; u++) {
            __nv_bfloat16 hi = __float2bfloat16(hv[u]);
            hh[u >> 3].h[u & 7] = hi;
            hl[u >> 3].h[u & 7] = __float2bfloat16(hv[u] - __bfloat162float(hi));
        }
        __nv_bfloat16* dh = g_h0hi[wrb] + m * HH + hu0;
        __nv_bfloat16* dl = g_h0lo[wrb] + m * HH + hu0;
        *reinterpret_cast<uint4*>(dh)     = hh[0].v;
        *reinterpret_cast<uint4*>(dh + 8) = hh[1].v;
        *reinterpret_cast<uint4*>(dl)     = hl[0].v;
        *reinterpret_cast<uint4*>(dl + 8) = hl[1].v;
    }
}

// =====================================================================
// k_l1: LSTM layer-1 step. 32 chunks: [0,16)=h0_new@W_ih1, [16,32)=h1_prev@W_hh1.
// =====================================================================
__global__ void __launch_bounds__(256) k_l1(int t, float* __restrict__ out) {
    extern __shared__ char sm[];
    const uint32_t smb = smem_u32(sm);
    const int tid = threadIdx.x, lane = tid & 31, warp = tid >> 5;
    const int cta = blockIdx.x, hu0 = cta * UPC;
    const int rd = t & 1, wrb = 1 - rd;
    const int M0 = (warp & 3) * 16, N0 = (warp >> 2) * 32;

    const __nv_bfloat16* Ah[2] = { g_h0hi[wrb], g_h1hi[rd] };
    const __nv_bfloat16* Al[2] = { g_h0lo[wrb], g_h1lo[rd] };
    const __nv_bfloat16* gBh = g_B1hi + (size_t)cta * 32 * 4096;
    const __nv_bfloat16* gBl = g_B1lo + (size_t)cta * 32 * 4096;

    float acc[4][4];
#pragma unroll
    for (int i = 0; i < 4; i++)
#pragma unroll
        for (int j = 0; j < 4; j++) acc[i][j] = 0.0f;

    copy_chunk(smb, 0, tid, Ah[0], Al[0], 0, gBh, gBl);
#pragma unroll 1
    for (int c = 0; c < 32; c++) {
        if (c < 31) {
            int cn = c + 1, ph = cn >> 4, kb = (cn & 15) * 64;
            copy_chunk(smb, cn & 1, tid, Ah[ph], Al[ph], kb,
                       gBh + (size_t)cn * 4096, gBl + (size_t)cn * 4096);
            asm volatile("cp.async.wait_group 1;" ::: "memory");
        } else {
            asm volatile("cp.async.wait_group 0;" ::: "memory");
        }
        __syncthreads();
        compute_chunk(smb, c & 1, lane, M0, N0, acc);
        __syncthreads();
    }
    store_accums(sm, lane, M0, N0, acc);
    __syncthreads();

    if (tid < 64) {
        const int m = tid;
        const float* sDr = (const float*)(sm + SD_OFF) + m * 66;
        F4 P[4][4], C[4], Hv[4];
#pragma unroll
        for (int q = 0; q < 4; q++)
#pragma unroll
            for (int i = 0; i < 4; i++)
                P[q][i].v = *reinterpret_cast<const float4*>(g_b1 + q * HH + hu0 + i * 4);
#pragma unroll
        for (int i = 0; i < 4; i++)
            C[i].v = *reinterpret_cast<const float4*>(g_c1 + m * HH + hu0 + i * 4);
#pragma unroll
        for (int u = 0; u < 16; u++) {
            float gi = sDr[u]      + P[0][u >> 2].f[u & 3];
            float gf = sDr[16 + u] + P[1][u >> 2].f[u & 3];
            float gg = sDr[32 + u] + P[2][u >> 2].f[u & 3];
            float go = sDr[48 + u] + P[3][u >> 2].f[u & 3];
            float cn = sigf(gf) * C[u >> 2].f[u & 3] + sigf(gi) * tanhf(gg);
            C[u >> 2].f[u & 3] = cn;
            Hv[u >> 2].f[u & 3] = sigf(go) * tanhf(cn);
        }
#pragma unroll
        for (int i = 0; i < 4; i++)
            *reinterpret_cast<float4*>(g_c1 + m * HH + hu0 + i * 4) = C[i].v;
        P8 hh[2], hl[2];
#pragma unroll
        for (int u = 0; u < 16; u++) {
            float hvv = Hv[u >> 2].f[u & 3];
            __nv_bfloat16 hi = __float2bfloat16(hvv);
            hh[u >> 3].h[u & 7] = hi;
            hl[u >> 3].h[u & 7] = __float2bfloat16(hvv - __bfloat162float(hi));
        }
        __nv_bfloat16* dh = g_h1hi[wrb] + m * HH + hu0;
        __nv_bfloat16* dl = g_h1lo[wrb] + m * HH + hu0;
        *reinterpret_cast<uint4*>(dh)     = hh[0].v;
        *reinterpret_cast<uint4*>(dh + 8) = hh[1].v;
        *reinterpret_cast<uint4*>(dl)     = hl[0].v;
        *reinterpret_cast<uint4*>(dl + 8) = hl[1].v;
        float* op = out + (size_t)t * BB * HH + m * HH + hu0;
#pragma unroll
        for (int i = 0; i < 4; i++)
            *reinterpret_cast<float4*>(op + i * 4) = Hv[i].v;
    }
}

// =====================================================================
extern "C" void kernel_launch(void* const* d_in, const int* in_sizes, int n_in,
                              void* d_out, int out_size) {
    const int*   tok      = (const int*)d_in[0];
    const int*   src      = (const int*)d_in[1];
    const float* enc_outs = (const float*)d_in[2];
    const float* enc_h    = (const float*)d_in[3];
    const float* enc_c    = (const float*)d_in[4];
    const float* embed    = (const float*)d_in[5];
    const float* W_ih0    = (const float*)d_in[6];
    const float* W_hh0    = (const float*)d_in[7];
    const float* b_ih0    = (const float*)d_in[8];
    const float* b_hh0    = (const float*)d_in[9];
    const float* W_ih1    = (const float*)d_in[10];
    const float* W_hh1    = (const float*)d_in[11];
    const float* b_ih1    = (const float*)d_in[12];
    const float* b_hh1    = (const float*)d_in[13];
    float* out = (float*)d_out;

    cudaFuncSetAttribute(k_l0, cudaFuncAttributeMaxDynamicSharedMemorySize, DYN_SMEM);
    cudaFuncSetAttribute(k_l1, cudaFuncAttributeMaxDynamicSharedMemorySize, DYN_SMEM);

    k_init<<<(BB * HH + 255) / 256, 256>>>(enc_h, enc_c, b_ih1, b_hh1);
    k_static<<<dim3(GG / 256, BB / 8), 256>>>(enc_outs, src, embed, W_ih0, b_ih0, b_hh0);
    k_precompute<<<dim3(SS, GG / 32), 256>>>(tok, embed, W_ih0);
    k_prep<<<dim3(16, NCTA), 256>>>(W_hh0, 0);
    k_prep<<<dim3(16, NCTA), 256>>>(W_ih1, 1);
    k_prep<<<dim3(16, NCTA), 256>>>(W_hh1, 2);

    for (int t = 0; t < SS; t++) {
        k_l0<<<NCTA, 256, DYN_SMEM>>>(t);
        k_l1<<<NCTA, 256, DYN_SMEM>>>(t, out);
    }
}

// round 9
// speedup vs baseline: 2.0164x; 1.4071x over previous
#include <cuda_runtime.h>
#include <cuda_bf16.h>
#include <math.h>
#include <stdint.h>

#define BB 64
#define SS 256
#define HH 1024
#define EE 512
#define GG 4096
#define NCTA 128
#define UPC 8     // hidden units per CTA (N = 32 gate cols)

// dynamic smem (bytes), 2 stages of 27648:
//   stage s at s*27648: Ahi(64x144)=9216 | Alo +9216 | Bhi(32x144)=4608 at +18432 | Blo +23040
// D tile at 55296: 64 x 34 f32 = 8704
#define STG 27648
#define SD_OFF 55296
#define DYN_SMEM 64000

// -------- device-global scratch --------
__device__ float g_P0[(size_t)SS * BB * GG];
__device__ float g_sp[BB * GG];
__device__ float g_b1[GG];
__device__ float g_c0[BB * HH];
__device__ float g_c1[BB * HH];
__device__ __nv_bfloat16 g_h0hi[2][BB * HH];
__device__ __nv_bfloat16 g_h0lo[2][BB * HH];
__device__ __nv_bfloat16 g_h1hi[2][BB * HH];
__device__ __nv_bfloat16 g_h1lo[2][BB * HH];
// pre-gathered dense weight tiles [cta][slot][32n][64k] bf16
__device__ __align__(16) __nv_bfloat16 g_B0hi[(size_t)NCTA * 16 * 2048];
__device__ __align__(16) __nv_bfloat16 g_B0lo[(size_t)NCTA * 16 * 2048];
__device__ __align__(16) __nv_bfloat16 g_B1hi[(size_t)NCTA * 32 * 2048];
__device__ __align__(16) __nv_bfloat16 g_B1lo[(size_t)NCTA * 32 * 2048];

typedef unsigned long long u64t;
union F4 { float4 v; float f[4]; };
union P8 { __nv_bfloat16 h[8]; uint4 v; };

__device__ __forceinline__ void fma2(u64t& c, u64t a, u64t b) {
    asm("fma.rn.f32x2 %0, %1, %2, %0;" : "+l"(c) : "l"(a), "l"(b));
}
__device__ __forceinline__ float hsum2(u64t v) {
    return __uint_as_float((unsigned)(v & 0xffffffffu)) +
           __uint_as_float((unsigned)(v >> 32));
}
__device__ __forceinline__ float sigf(float x) { return 1.0f / (1.0f + expf(-x)); }

__device__ __forceinline__ uint32_t smem_u32(const void* p) {
    uint32_t a;
    asm("{ .reg .u64 t; cvta.to.shared.u64 t, %1; cvt.u32.u64 %0, t; }" : "=r"(a) : "l"(p));
    return a;
}
__device__ __forceinline__ void cpa16(uint32_t d, const void* s) {
    asm volatile("cp.async.cg.shared.global [%0], [%1], 16;" :: "r"(d), "l"(s));
}
#define CP_COMMIT() asm volatile("cp.async.commit_group;" ::: "memory")

__device__ __forceinline__ void ldsm4(uint32_t* r, uint32_t a) {
    asm volatile("ldmatrix.sync.aligned.m8n8.x4.shared.b16 {%0,%1,%2,%3}, [%4];"
                 : "=r"(r[0]), "=r"(r[1]), "=r"(r[2]), "=r"(r[3]) : "r"(a));
}
__device__ __forceinline__ void mma_bf16(float* d, const uint32_t* a, uint32_t b0, uint32_t b1) {
    asm volatile(
        "mma.sync.aligned.m16n8k16.row.col.f32.bf16.bf16.f32 "
        "{%0,%1,%2,%3}, {%4,%5,%6,%7}, {%8,%9}, {%0,%1,%2,%3};"
        : "+f"(d[0]), "+f"(d[1]), "+f"(d[2]), "+f"(d[3])
        : "r"(a[0]), "r"(a[1]), "r"(a[2]), "r"(a[3]), "r"(b0), "r"(b1));
}

// =====================================================================
// k_init: states + bias fold + bf16 hi/lo conversion of initial h
// =====================================================================
__global__ void k_init(const float* __restrict__ enc_h, const float* __restrict__ enc_c,
                       const float* __restrict__ b_ih1, const float* __restrict__ b_hh1) {
    int i = blockIdx.x * blockDim.x + threadIdx.x;
    const int n = BB * HH;
    if (i < n) {
        float h0v = enc_h[i], h1v = enc_h[n + i];
        __nv_bfloat16 a = __float2bfloat16(h0v);
        g_h0hi[0][i] = a;
        g_h0lo[0][i] = __float2bfloat16(h0v - __bfloat162float(a));
        __nv_bfloat16 b = __float2bfloat16(h1v);
        g_h1hi[0][i] = b;
        g_h1lo[0][i] = __float2bfloat16(h1v - __bfloat162float(b));
        g_c0[i] = enc_c[i];
        g_c1[i] = enc_c[n + i];
    }
    if (i < GG) g_b1[i] = b_ih1[i] + b_hh1[i];
}

// =====================================================================
// k_static (proven, unchanged)
// =====================================================================
__global__ void __launch_bounds__(256) k_static(
    const float* __restrict__ enc_outs, const int* __restrict__ src_lang,
    const float* __restrict__ embed, const float* __restrict__ W0,
    const float* __restrict__ b_ih0, const float* __restrict__ b_hh0) {
    __shared__ float sC[8][EE];
    __shared__ float sL[8][EE];
    const int tid = threadIdx.x;
    const int b0 = blockIdx.y * 8;
    for (int i = tid; i < 8 * EE; i += 256) {
        int b = i >> 9, k = i & (EE - 1);
        sC[b][k] = enc_outs[((size_t)(b0 + b) * 128 + 127) * EE + k];
        sL[b][k] = embed[(size_t)src_lang[b0 + b] * EE + k];
    }
    __syncthreads();
    const int g = blockIdx.x * 256 + tid;
    const float* wr = W0 + (size_t)g * 1536;
    float acc[8];
#pragma unroll
    for (int i = 0; i < 8; i++) acc[i] = 0.0f;
    for (int k = 0; k < EE; k += 4) {
        float4 wc = *reinterpret_cast<const float4*>(wr + 512 + k);
        float4 wl = *reinterpret_cast<const float4*>(wr + 1024 + k);
#pragma unroll
        for (int b = 0; b < 8; b++) {
            float4 c4 = *reinterpret_cast<const float4*>(&sC[b][k]);
            float4 l4 = *reinterpret_cast<const float4*>(&sL[b][k]);
            acc[b] += wc.x * c4.x + wc.y * c4.y + wc.z * c4.z + wc.w * c4.w;
            acc[b] += wl.x * l4.x + wl.y * l4.y + wl.z * l4.z + wl.w * l4.w;
        }
    }
    float bias = b_ih0[g] + b_hh0[g];
#pragma unroll
    for (int b = 0; b < 8; b++) g_sp[(b0 + b) * GG + g] = acc[b] + bias;
}

// =====================================================================
// k_precompute (proven, unchanged)
// =====================================================================
__global__ void __launch_bounds__(256) k_precompute(
    const int* __restrict__ tokens, const float* __restrict__ embed,
    const float* __restrict__ W0) {
    __shared__ __align__(16) float sA[64][68];
    __shared__ __align__(16) float sW[32][68];
    __shared__ int sTok[64];
    const int tid = threadIdx.x;
    const int t = blockIdx.x;
    const int col0 = blockIdx.y * 32;
    const int j = tid & 31, mg = tid >> 5;
    const int ar = tid >> 2, al = tid & 3;
    const int wri = tid >> 3, wci = (tid & 7) * 8;
    const float* wgrow = W0 + (size_t)(col0 + wri) * 1536 + wci;

    if (tid < 64) sTok[tid] = tokens[tid * SS + t];
    __syncthreads();
    const float* arow = embed + (size_t)sTok[ar] * EE;

    u64t acc[8];
#pragma unroll
    for (int i = 0; i < 8; i++) acc[i] = 0ull;

    float4 pA[4], pW[2];
#pragma unroll
    for (int q = 0; q < 4; q++)
        pA[q] = *reinterpret_cast<const float4*>(arow + (al + 4 * q) * 4);
    pW[0] = *reinterpret_cast<const float4*>(wgrow);
    pW[1] = *reinterpret_cast<const float4*>(wgrow + 4);

#pragma unroll 1
    for (int c = 0; c < EE / 64; c++) {
#pragma unroll
        for (int q = 0; q < 4; q++)
            *reinterpret_cast<float4*>(&sA[ar][(al + 4 * q) * 4]) = pA[q];
        *reinterpret_cast<float4*>(&sW[wri][wci]) = pW[0];
        *reinterpret_cast<float4*>(&sW[wri][wci + 4]) = pW[1];
        __syncthreads();
        if (c + 1 < EE / 64) {
            int k1 = (c + 1) * 64;
#pragma unroll
            for (int q = 0; q < 4; q++)
                pA[q] = *reinterpret_cast<const float4*>(arow + k1 + (al + 4 * q) * 4);
            pW[0] = *reinterpret_cast<const float4*>(wgrow + k1);
            pW[1] = *reinterpret_cast<const float4*>(wgrow + k1 + 4);
        }
#pragma unroll
        for (int kk = 0; kk < 64; kk += 4) {
            ulonglong2 w = *reinterpret_cast<const ulonglong2*>(&sW[j][kk]);
#pragma unroll
            for (int mi = 0; mi < 8; mi++) {
                ulonglong2 a = *reinterpret_cast<const ulonglong2*>(&sA[mg * 8 + mi][kk]);
                fma2(acc[mi], a.x, w.x);
                fma2(acc[mi], a.y, w.y);
            }
        }
        __syncthreads();
    }
    const int col = col0 + j;
#pragma unroll
    for (int mi = 0; mi < 8; mi++) {
        int m = mg * 8 + mi;
        g_P0[((size_t)t * BB + m) * GG + col] = hsum2(acc[mi]) + g_sp[m * GG + col];
    }
}

// =====================================================================
// k_prep: gather W rows into dense per-CTA [32n][64k] bf16 hi/lo tiles.
// grid (16, NCTA); which: 0->B0, 1->B1 slots[0,16), 2->B1 slots[16,32)
// local n = q*8+u  <->  global row q*HH + cta*8 + u
// =====================================================================
__global__ void __launch_bounds__(256) k_prep(const float* __restrict__ W, int which) {
    const int c = blockIdx.x, cta = blockIdx.y, tid = threadIdx.x;
    const int nloc = tid >> 3, ks = (tid & 7) * 8;
    const int grow = (nloc >> 3) * HH + cta * UPC + (nloc & 7);
    const float* s = W + (size_t)grow * HH + c * 64 + ks;
    float x[8];
    *reinterpret_cast<float4*>(x)     = *reinterpret_cast<const float4*>(s);
    *reinterpret_cast<float4*>(x + 4) = *reinterpret_cast<const float4*>(s + 4);
    P8 ph, pl;
#pragma unroll
    for (int u = 0; u < 8; u++) {
        __nv_bfloat16 hi = __float2bfloat16(x[u]);
        ph.h[u] = hi;
        pl.h[u] = __float2bfloat16(x[u] - __bfloat162float(hi));
    }
    __nv_bfloat16 *Gh, *Gl;
    size_t base;
    if (which == 0) { Gh = g_B0hi; Gl = g_B0lo; base = ((size_t)cta * 16 + c) * 2048; }
    else { Gh = g_B1hi; Gl = g_B1lo; base = ((size_t)cta * 32 + (which == 2 ? 16 : 0) + c) * 2048; }
    size_t off = base + (size_t)nloc * 64 + ks;
    *reinterpret_cast<uint4*>(Gh + off) = ph.v;
    *reinterpret_cast<uint4*>(Gl + off) = pl.v;
}

// =====================================================================
// step-kernel building blocks (M=64, N=32 per CTA; warp tile 16x16)
// =====================================================================
__device__ __forceinline__ void copy_chunk(
    uint32_t smb, int stage, int tid,
    const __nv_bfloat16* gAh, const __nv_bfloat16* gAl, int kbase,
    const __nv_bfloat16* gBh, const __nv_bfloat16* gBl) {
    const uint32_t sb = smb + stage * STG;
#pragma unroll
    for (int i = tid; i < 512; i += 256) {
        int row = i >> 3, s = i & 7;
        uint32_t so = (uint32_t)row * 144 + (s << 4);
        const char* ah = (const char*)(gAh + (size_t)row * HH + kbase) + (s << 4);
        const char* al = (const char*)(gAl + (size_t)row * HH + kbase) + (s << 4);
        cpa16(sb + so, ah);
        cpa16(sb + 9216 + so, al);
    }
    {
        int row = tid >> 3, s = tid & 7;
        uint32_t so = (uint32_t)row * 144 + (s << 4);
        cpa16(sb + 18432 + so, (const char*)gBh + ((size_t)tid << 4));
        cpa16(sb + 23040 + so, (const char*)gBl + ((size_t)tid << 4));
    }
    CP_COMMIT();
}

__device__ __forceinline__ void compute_chunk(uint32_t smb, int stage, int lane,
                                              int M0, int N0, float acc[2][4]) {
    const uint32_t sb = smb + stage * STG;
    const uint32_t aoff = (uint32_t)(M0 + (lane & 15)) * 144 + ((lane >> 4) << 4);
    const uint32_t boff = (uint32_t)(N0 + (((lane >> 4) & 1) << 3) + (lane & 7)) * 144 +
                          (((lane >> 3) & 1) << 4);
#pragma unroll
    for (int ksi = 0; ksi < 4; ksi++) {
        const uint32_t kb = ksi << 5;
        uint32_t ah[4], al[4], bh[4], bl[4];
        ldsm4(ah, sb + aoff + kb);
        ldsm4(al, sb + 9216 + aoff + kb);
        ldsm4(bh, sb + 18432 + boff + kb);
        ldsm4(bl, sb + 23040 + boff + kb);
#pragma unroll
        for (int nt = 0; nt < 2; nt++) {
            mma_bf16(acc[nt], ah, bh[2 * nt], bh[2 * nt + 1]);
            mma_bf16(acc[nt], al, bh[2 * nt], bh[2 * nt + 1]);
            mma_bf16(acc[nt], ah, bl[2 * nt], bl[2 * nt + 1]);
        }
    }
}

__device__ __forceinline__ void store_accums(char* sm, int lane, int M0, int N0,
                                             float acc[2][4]) {
    float* sD = (float*)(sm + SD_OFF);
    int r0 = M0 + (lane >> 2);
#pragma unroll
    for (int nt = 0; nt < 2; nt++) {
        int col = N0 + nt * 8 + (lane & 3) * 2;
        *reinterpret_cast<float2*>(&sD[r0 * 34 + col]) = make_float2(acc[nt][0], acc[nt][1]);
        *reinterpret_cast<float2*>(&sD[(r0 + 8) * 34 + col]) = make_float2(acc[nt][2], acc[nt][3]);
    }
}

// =====================================================================
// k_l0: LSTM layer-0 step. grid NCTA(128), 256 threads.
// =====================================================================
__global__ void __launch_bounds__(256) k_l0(int t) {
    extern __shared__ char sm[];
    const uint32_t smb = smem_u32(sm);
    const int tid = threadIdx.x, lane = tid & 31, warp = tid >> 5;
    const int cta = blockIdx.x, hu0 = cta * UPC;
    const int rd = t & 1, wrb = 1 - rd;
    const int M0 = (warp & 3) * 16, N0 = (warp >> 2) * 16;

    const __nv_bfloat16* gAh = g_h0hi[rd];
    const __nv_bfloat16* gAl = g_h0lo[rd];
    const __nv_bfloat16* gBh = g_B0hi + (size_t)cta * 16 * 2048;
    const __nv_bfloat16* gBl = g_B0lo + (size_t)cta * 16 * 2048;

    float acc[2][4];
#pragma unroll
    for (int i = 0; i < 2; i++)
#pragma unroll
        for (int j = 0; j < 4; j++) acc[i][j] = 0.0f;

    copy_chunk(smb, 0, tid, gAh, gAl, 0, gBh, gBl);
#pragma unroll 1
    for (int c = 0; c < 16; c++) {
        if (c < 15) {
            copy_chunk(smb, (c + 1) & 1, tid, gAh, gAl, (c + 1) * 64,
                       gBh + (size_t)(c + 1) * 2048, gBl + (size_t)(c + 1) * 2048);
            asm volatile("cp.async.wait_group 1;" ::: "memory");
        } else {
            asm volatile("cp.async.wait_group 0;" ::: "memory");
        }
        __syncthreads();
        compute_chunk(smb, c & 1, lane, M0, N0, acc);
        __syncthreads();
    }
    store_accums(sm, lane, M0, N0, acc);
    __syncthreads();

    if (tid < 64) {
        const int m = tid;
        const float* sDr = (const float*)(sm + SD_OFF) + m * 34;
        const float* p0 = g_P0 + ((size_t)t * BB + m) * GG;
        F4 P[4][2], C[2];
#pragma unroll
        for (int q = 0; q < 4; q++) {
            P[q][0].v = *reinterpret_cast<const float4*>(p0 + q * HH + hu0);
            P[q][1].v = *reinterpret_cast<const float4*>(p0 + q * HH + hu0 + 4);
        }
        C[0].v = *reinterpret_cast<const float4*>(g_c0 + m * HH + hu0);
        C[1].v = *reinterpret_cast<const float4*>(g_c0 + m * HH + hu0 + 4);
        float hv[8];
#pragma unroll
        for (int u = 0; u < 8; u++) {
            float gi = sDr[u]      + P[0][u >> 2].f[u & 3];
            float gf = sDr[8 + u]  + P[1][u >> 2].f[u & 3];
            float gg = sDr[16 + u] + P[2][u >> 2].f[u & 3];
            float go = sDr[24 + u] + P[3][u >> 2].f[u & 3];
            float cn = sigf(gf) * C[u >> 2].f[u & 3] + sigf(gi) * tanhf(gg);
            C[u >> 2].f[u & 3] = cn;
            hv[u] = sigf(go) * tanhf(cn);
        }
        *reinterpret_cast<float4*>(g_c0 + m * HH + hu0)     = C[0].v;
        *reinterpret_cast<float4*>(g_c0 + m * HH + hu0 + 4) = C[1].v;
        P8 hh, hl;
#pragma unroll
        for (int u = 0; u < 8; u++) {
            __nv_bfloat16 hi = __float2bfloat16(hv[u]);
            hh.h[u] = hi;
            hl.h[u] = __float2bfloat16(hv[u] - __bfloat162float(hi));
        }
        *reinterpret_cast<uint4*>(g_h0hi[wrb] + m * HH + hu0) = hh.v;
        *reinterpret_cast<uint4*>(g_h0lo[wrb] + m * HH + hu0) = hl.v;
    }
}

// =====================================================================
// k_l1: LSTM layer-1 step. 32 chunks: [0,16)=h0_new@W_ih1, [16,32)=h1_prev@W_hh1.
// =====================================================================
__global__ void __launch_bounds__(256) k_l1(int t, float* __restrict__ out) {
    extern __shared__ char sm[];
    const uint32_t smb = smem_u32(sm);
    const int tid = threadIdx.x, lane = tid & 31, warp = tid >> 5;
    const int cta = blockIdx.x, hu0 = cta * UPC;
    const int rd = t & 1, wrb = 1 - rd;
    const int M0 = (warp & 3) * 16, N0 = (warp >> 2) * 16;

    const __nv_bfloat16* Ah[2] = { g_h0hi[wrb], g_h1hi[rd] };
    const __nv_bfloat16* Al[2] = { g_h0lo[wrb], g_h1lo[rd] };
    const __nv_bfloat16* gBh = g_B1hi + (size_t)cta * 32 * 2048;
    const __nv_bfloat16* gBl = g_B1lo + (size_t)cta * 32 * 2048;

    float acc[2][4];
#pragma unroll
    for (int i = 0; i < 2; i++)
#pragma unroll
        for (int j = 0; j < 4; j++) acc[i][j] = 0.0f;

    copy_chunk(smb, 0, tid, Ah[0], Al[0], 0, gBh, gBl);
#pragma unroll 1
    for (int c = 0; c < 32; c++) {
        if (c < 31) {
            int cn = c + 1, ph = cn >> 4, kb = (cn & 15) * 64;
            copy_chunk(smb, cn & 1, tid, Ah[ph], Al[ph], kb,
                       gBh + (size_t)cn * 2048, gBl + (size_t)cn * 2048);
            asm volatile("cp.async.wait_group 1;" ::: "memory");
        } else {
            asm volatile("cp.async.wait_group 0;" ::: "memory");
        }
        __syncthreads();
        compute_chunk(smb, c & 1, lane, M0, N0, acc);
        __syncthreads();
    }
    store_accums(sm, lane, M0, N0, acc);
    __syncthreads();

    if (tid < 64) {
        const int m = tid;
        const float* sDr = (const float*)(sm + SD_OFF) + m * 34;
        F4 P[4][2], C[2], Hv[2];
#pragma unroll
        for (int q = 0; q < 4; q++) {
            P[q][0].v = *reinterpret_cast<const float4*>(g_b1 + q * HH + hu0);
            P[q][1].v = *reinterpret_cast<const float4*>(g_b1 + q * HH + hu0 + 4);
        }
        C[0].v = *reinterpret_cast<const float4*>(g_c1 + m * HH + hu0);
        C[1].v = *reinterpret_cast<const float4*>(g_c1 + m * HH + hu0 + 4);
#pragma unroll
        for (int u = 0; u < 8; u++) {
            float gi = sDr[u]      + P[0][u >> 2].f[u & 3];
            float gf = sDr[8 + u]  + P[1][u >> 2].f[u & 3];
            float gg = sDr[16 + u] + P[2][u >> 2].f[u & 3];
            float go = sDr[24 + u] + P[3][u >> 2].f[u & 3];
            float cn = sigf(gf) * C[u >> 2].f[u & 3] + sigf(gi) * tanhf(gg);
            C[u >> 2].f[u & 3] = cn;
            Hv[u >> 2].f[u & 3] = sigf(go) * tanhf(cn);
        }
        *reinterpret_cast<float4*>(g_c1 + m * HH + hu0)     = C[0].v;
        *reinterpret_cast<float4*>(g_c1 + m * HH + hu0 + 4) = C[1].v;
        P8 hh, hl;
#pragma unroll
        for (int u = 0; u < 8; u++) {
            float hvv = Hv[u >> 2].f[u & 3];
            __nv_bfloat16 hi = __float2bfloat16(hvv);
            hh.h[u] = hi;
            hl.h[u] = __float2bfloat16(hvv - __bfloat162float(hi));
        }
        *reinterpret_cast<uint4*>(g_h1hi[wrb] + m * HH + hu0) = hh.v;
        *reinterpret_cast<uint4*>(g_h1lo[wrb] + m * HH + hu0) = hl.v;
        float* op = out + (size_t)t * BB * HH + m * HH + hu0;
        *reinterpret_cast<float4*>(op)     = Hv[0].v;
        *reinterpret_cast<float4*>(op + 4) = Hv[1].v;
    }
}

// =====================================================================
extern "C" void kernel_launch(void* const* d_in, const int* in_sizes, int n_in,
                              void* d_out, int out_size) {
    const int*   tok      = (const int*)d_in[0];
    const int*   src      = (const int*)d_in[1];
    const float* enc_outs = (const float*)d_in[2];
    const float* enc_h    = (const float*)d_in[3];
    const float* enc_c    = (const float*)d_in[4];
    const float* embed    = (const float*)d_in[5];
    const float* W_ih0    = (const float*)d_in[6];
    const float* W_hh0    = (const float*)d_in[7];
    const float* b_ih0    = (const float*)d_in[8];
    const float* b_hh0    = (const float*)d_in[9];
    const float* W_ih1    = (const float*)d_in[10];
    const float* W_hh1    = (const float*)d_in[11];
    const float* b_ih1    = (const float*)d_in[12];
    const float* b_hh1    = (const float*)d_in[13];
    float* out = (float*)d_out;

    cudaFuncSetAttribute(k_l0, cudaFuncAttributeMaxDynamicSharedMemorySize, DYN_SMEM);
    cudaFuncSetAttribute(k_l1, cudaFuncAttributeMaxDynamicSharedMemorySize, DYN_SMEM);

    k_init<<<(BB * HH + 255) / 256, 256>>>(enc_h, enc_c, b_ih1, b_hh1);
    k_static<<<dim3(GG / 256, BB / 8), 256>>>(enc_outs, src, embed, W_ih0, b_ih0, b_hh0);
    k_precompute<<<dim3(SS, GG / 32), 256>>>(tok, embed, W_ih0);
    k_prep<<<dim3(16, NCTA), 256>>>(W_hh0, 0);
    k_prep<<<dim3(16, NCTA), 256>>>(W_ih1, 1);
    k_prep<<<dim3(16, NCTA), 256>>>(W_hh1, 2);

    for (int t = 0; t < SS; t++) {
        k_l0<<<NCTA, 256, DYN_SMEM>>>(t);
        k_l1<<<NCTA, 256, DYN_SMEM>>>(t, out);
    }
}

// round 10
// speedup vs baseline: 2.1137x; 1.0482x over previous
#include <cuda_runtime.h>
#include <cuda_bf16.h>
#include <math.h>
#include <stdint.h>

#define BB 64
#define SS 256
#define HH 1024
#define EE 512
#define GG 4096
#define NCTA 128
#define UPC 8     // hidden units per CTA (N = 32 gate cols)

// dynamic smem (bytes), 3 stages of 27648:
//   stage s at s*27648: Ahi(64x144)=9216 | Alo +9216 | Bhi(32x144) +18432 | Blo +23040
#define STGSZ 27648
#define SD_OFF  82944   // D tile 64 x 34 f32 = 8704
#define SP_OFF  91648   // P0 prefetch 64 x 32 f32 = 8192
#define SC0_OFF 99840   // c0 state 512 f32
#define SC1_OFF 101888  // c1 state 512 f32
#define SB1_OFF 103936  // layer1 bias 32 f32
#define DYN_SMEM 104448

// -------- device-global scratch --------
__device__ float g_P0[(size_t)SS * BB * GG];
__device__ float g_sp[BB * GG];
__device__ __nv_bfloat16 g_h0hi[2][BB * HH];
__device__ __nv_bfloat16 g_h0lo[2][BB * HH];
__device__ __nv_bfloat16 g_h1hi[2][BB * HH];
__device__ __nv_bfloat16 g_h1lo[2][BB * HH];
// pre-gathered dense weight tiles [cta][slot][32n][64k] bf16
__device__ __align__(16) __nv_bfloat16 g_B0hi[(size_t)NCTA * 16 * 2048];
__device__ __align__(16) __nv_bfloat16 g_B0lo[(size_t)NCTA * 16 * 2048];
__device__ __align__(16) __nv_bfloat16 g_B1hi[(size_t)NCTA * 32 * 2048];
__device__ __align__(16) __nv_bfloat16 g_B1lo[(size_t)NCTA * 32 * 2048];
// grid barrier state
__device__ unsigned g_bcnt;
__device__ unsigned g_bgen;

typedef unsigned long long u64t;
union F4 { float4 v; float f[4]; };
union P8 { __nv_bfloat16 h[8]; uint4 v; };

__device__ __forceinline__ void fma2(u64t& c, u64t a, u64t b) {
    asm("fma.rn.f32x2 %0, %1, %2, %0;" : "+l"(c) : "l"(a), "l"(b));
}
__device__ __forceinline__ float hsum2(u64t v) {
    return __uint_as_float((unsigned)(v & 0xffffffffu)) +
           __uint_as_float((unsigned)(v >> 32));
}
__device__ __forceinline__ float sigf(float x) { return 1.0f / (1.0f + expf(-x)); }

__device__ __forceinline__ uint32_t smem_u32(const void* p) {
    uint32_t a;
    asm("{ .reg .u64 t; cvta.to.shared.u64 t, %1; cvt.u32.u64 %0, t; }" : "=r"(a) : "l"(p));
    return a;
}
__device__ __forceinline__ void cpa16(uint32_t d, const void* s) {
    asm volatile("cp.async.cg.shared.global [%0], [%1], 16;" :: "r"(d), "l"(s));
}
#define CP_COMMIT() asm volatile("cp.async.commit_group;" ::: "memory")
template<int N> __device__ __forceinline__ void cp_wait() {
    asm volatile("cp.async.wait_group %0;" :: "n"(N) : "memory");
}

__device__ __forceinline__ void ldsm4(uint32_t* r, uint32_t a) {
    asm volatile("ldmatrix.sync.aligned.m8n8.x4.shared.b16 {%0,%1,%2,%3}, [%4];"
                 : "=r"(r[0]), "=r"(r[1]), "=r"(r[2]), "=r"(r[3]) : "r"(a));
}
__device__ __forceinline__ void mma_bf16(float* d, const uint32_t* a, uint32_t b0, uint32_t b1) {
    asm volatile(
        "mma.sync.aligned.m16n8k16.row.col.f32.bf16.bf16.f32 "
        "{%0,%1,%2,%3}, {%4,%5,%6,%7}, {%8,%9}, {%0,%1,%2,%3};"
        : "+f"(d[0]), "+f"(d[1]), "+f"(d[2]), "+f"(d[3])
        : "r"(a[0]), "r"(a[1]), "r"(a[2]), "r"(a[3]), "r"(b0), "r"(b1));
}

// grid-wide barrier: all 128 CTAs co-resident (1/SM on 148 SMs).
__device__ __forceinline__ void grid_bar(int tid, unsigned gen) {
    __threadfence();
    __syncthreads();
    if (tid == 0) {
        if (atomicAdd(&g_bcnt, 1u) == NCTA - 1) {
            atomicExch(&g_bcnt, 0u);
            __threadfence();
            atomicExch(&g_bgen, gen);
        } else {
            while (atomicOr(&g_bgen, 0u) < gen) {}
            __threadfence();
        }
    }
    __syncthreads();
}

// =====================================================================
// k_init: h hi/lo conversion + barrier reset
// =====================================================================
__global__ void k_init(const float* __restrict__ enc_h) {
    int i = blockIdx.x * blockDim.x + threadIdx.x;
    const int n = BB * HH;
    if (i == 0) { g_bcnt = 0; g_bgen = 0; }
    if (i < n) {
        float h0v = enc_h[i], h1v = enc_h[n + i];
        __nv_bfloat16 a = __float2bfloat16(h0v);
        g_h0hi[0][i] = a;
        g_h0lo[0][i] = __float2bfloat16(h0v - __bfloat162float(a));
        __nv_bfloat16 b = __float2bfloat16(h1v);
        g_h1hi[0][i] = b;
        g_h1lo[0][i] = __float2bfloat16(h1v - __bfloat162float(b));
    }
}

// =====================================================================
// k_static (proven, unchanged)
// =====================================================================
__global__ void __launch_bounds__(256) k_static(
    const float* __restrict__ enc_outs, const int* __restrict__ src_lang,
    const float* __restrict__ embed, const float* __restrict__ W0,
    const float* __restrict__ b_ih0, const float* __restrict__ b_hh0) {
    __shared__ float sC[8][EE];
    __shared__ float sL[8][EE];
    const int tid = threadIdx.x;
    const int b0 = blockIdx.y * 8;
    for (int i = tid; i < 8 * EE; i += 256) {
        int b = i >> 9, k = i & (EE - 1);
        sC[b][k] = enc_outs[((size_t)(b0 + b) * 128 + 127) * EE + k];
        sL[b][k] = embed[(size_t)src_lang[b0 + b] * EE + k];
    }
    __syncthreads();
    const int g = blockIdx.x * 256 + tid;
    const float* wr = W0 + (size_t)g * 1536;
    float acc[8];
#pragma unroll
    for (int i = 0; i < 8; i++) acc[i] = 0.0f;
    for (int k = 0; k < EE; k += 4) {
        float4 wc = *reinterpret_cast<const float4*>(wr + 512 + k);
        float4 wl = *reinterpret_cast<const float4*>(wr + 1024 + k);
#pragma unroll
        for (int b = 0; b < 8; b++) {
            float4 c4 = *reinterpret_cast<const float4*>(&sC[b][k]);
            float4 l4 = *reinterpret_cast<const float4*>(&sL[b][k]);
            acc[b] += wc.x * c4.x + wc.y * c4.y + wc.z * c4.z + wc.w * c4.w;
            acc[b] += wl.x * l4.x + wl.y * l4.y + wl.z * l4.z + wl.w * l4.w;
        }
    }
    float bias = b_ih0[g] + b_hh0[g];
#pragma unroll
    for (int b = 0; b < 8; b++) g_sp[(b0 + b) * GG + g] = acc[b] + bias;
}

// =====================================================================
// k_precompute (proven, unchanged)
// =====================================================================
__global__ void __launch_bounds__(256) k_precompute(
    const int* __restrict__ tokens, const float* __restrict__ embed,
    const float* __restrict__ W0) {
    __shared__ __align__(16) float sA[64][68];
    __shared__ __align__(16) float sW[32][68];
    __shared__ int sTok[64];
    const int tid = threadIdx.x;
    const int t = blockIdx.x;
    const int col0 = blockIdx.y * 32;
    const int j = tid & 31, mg = tid >> 5;
    const int ar = tid >> 2, al = tid & 3;
    const int wri = tid >> 3, wci = (tid & 7) * 8;
    const float* wgrow = W0 + (size_t)(col0 + wri) * 1536 + wci;

    if (tid < 64) sTok[tid] = tokens[tid * SS + t];
    __syncthreads();
    const float* arow = embed + (size_t)sTok[ar] * EE;

    u64t acc[8];
#pragma unroll
    for (int i = 0; i < 8; i++) acc[i] = 0ull;

    float4 pA[4], pW[2];
#pragma unroll
    for (int q = 0; q < 4; q++)
        pA[q] = *reinterpret_cast<const float4*>(arow + (al + 4 * q) * 4);
    pW[0] = *reinterpret_cast<const float4*>(wgrow);
    pW[1] = *reinterpret_cast<const float4*>(wgrow + 4);

#pragma unroll 1
    for (int c = 0; c < EE / 64; c++) {
#pragma unroll
        for (int q = 0; q < 4; q++)
            *reinterpret_cast<float4*>(&sA[ar][(al + 4 * q) * 4]) = pA[q];
        *reinterpret_cast<float4*>(&sW[wri][wci]) = pW[0];
        *reinterpret_cast<float4*>(&sW[wri][wci + 4]) = pW[1];
        __syncthreads();
        if (c + 1 < EE / 64) {
            int k1 = (c + 1) * 64;
#pragma unroll
            for (int q = 0; q < 4; q++)
                pA[q] = *reinterpret_cast<const float4*>(arow + k1 + (al + 4 * q) * 4);
            pW[0] = *reinterpret_cast<const float4*>(wgrow + k1);
            pW[1] = *reinterpret_cast<const float4*>(wgrow + k1 + 4);
        }
#pragma unroll
        for (int kk = 0; kk < 64; kk += 4) {
            ulonglong2 w = *reinterpret_cast<const ulonglong2*>(&sW[j][kk]);
#pragma unroll
            for (int mi = 0; mi < 8; mi++) {
                ulonglong2 a = *reinterpret_cast<const ulonglong2*>(&sA[mg * 8 + mi][kk]);
                fma2(acc[mi], a.x, w.x);
                fma2(acc[mi], a.y, w.y);
            }
        }
        __syncthreads();
    }
    const int col = col0 + j;
#pragma unroll
    for (int mi = 0; mi < 8; mi++) {
        int m = mg * 8 + mi;
        g_P0[((size_t)t * BB + m) * GG + col] = hsum2(acc[mi]) + g_sp[m * GG + col];
    }
}

// =====================================================================
// weight prep: gather W rows into dense per-CTA [32n][64k] bf16 hi/lo tiles.
// =====================================================================
__device__ __forceinline__ void prep_body(const float* W, int which, int c, int cta, int tid) {
    const int nloc = tid >> 3, ks = (tid & 7) * 8;
    const int grow = (nloc >> 3) * HH + cta * UPC + (nloc & 7);
    const float* s = W + (size_t)grow * HH + c * 64 + ks;
    float x[8];
    *reinterpret_cast<float4*>(x)     = *reinterpret_cast<const float4*>(s);
    *reinterpret_cast<float4*>(x + 4) = *reinterpret_cast<const float4*>(s + 4);
    P8 ph, pl;
#pragma unroll
    for (int u = 0; u < 8; u++) {
        __nv_bfloat16 hi = __float2bfloat16(x[u]);
        ph.h[u] = hi;
        pl.h[u] = __float2bfloat16(x[u] - __bfloat162float(hi));
    }
    __nv_bfloat16 *Gh, *Gl;
    size_t base;
    if (which == 0) { Gh = g_B0hi; Gl = g_B0lo; base = ((size_t)cta * 16 + c) * 2048; }
    else { Gh = g_B1hi; Gl = g_B1lo; base = ((size_t)cta * 32 + (which == 2 ? 16 : 0) + c) * 2048; }
    size_t off = base + (size_t)nloc * 64 + ks;
    *reinterpret_cast<uint4*>(Gh + off) = ph.v;
    *reinterpret_cast<uint4*>(Gl + off) = pl.v;
}

__global__ void __launch_bounds__(256) k_prep0(const float* __restrict__ W) {
    prep_body(W, 0, blockIdx.x, blockIdx.y, threadIdx.x);
}
__global__ void __launch_bounds__(256) k_prep12(const float* __restrict__ Wih1,
                                               const float* __restrict__ Whh1) {
    if (blockIdx.z == 0) prep_body(Wih1, 1, blockIdx.x, blockIdx.y, threadIdx.x);
    else                 prep_body(Whh1, 2, blockIdx.x, blockIdx.y, threadIdx.x);
}

// =====================================================================
// persistent step-kernel building blocks (M=64, N=32; warp tile 16x16)
// =====================================================================
__device__ __forceinline__ void copy_chunk(
    uint32_t smb, int stage, int tid,
    const __nv_bfloat16* gAh, const __nv_bfloat16* gAl, int kbase,
    const __nv_bfloat16* gBh, const __nv_bfloat16* gBl) {
    const uint32_t sb = smb + stage * STGSZ;
#pragma unroll
    for (int i = tid; i < 512; i += 256) {
        int row = i >> 3, s = i & 7;
        uint32_t so = (uint32_t)row * 144 + (s << 4);
        const char* ah = (const char*)(gAh + (size_t)row * HH + kbase) + (s << 4);
        const char* al = (const char*)(gAl + (size_t)row * HH + kbase) + (s << 4);
        cpa16(sb + so, ah);
        cpa16(sb + 9216 + so, al);
    }
    {
        int row = tid >> 3, s = tid & 7;
        uint32_t so = (uint32_t)row * 144 + (s << 4);
        cpa16(sb + 18432 + so, (const char*)gBh + ((size_t)tid << 4));
        cpa16(sb + 23040 + so, (const char*)gBl + ((size_t)tid << 4));
    }
}

__device__ __forceinline__ void compute_chunk(uint32_t smb, int stage, int lane,
                                              int M0, int N0, float acc[2][4]) {
    const uint32_t sb = smb + stage * STGSZ;
    const uint32_t aoff = (uint32_t)(M0 + (lane & 15)) * 144 + ((lane >> 4) << 4);
    const uint32_t boff = (uint32_t)(N0 + (((lane >> 4) & 1) << 3) + (lane & 7)) * 144 +
                          (((lane >> 3) & 1) << 4);
#pragma unroll
    for (int ksi = 0; ksi < 4; ksi++) {
        const uint32_t kb = ksi << 5;
        uint32_t ah[4], al[4], bh[4], bl[4];
        ldsm4(ah, sb + aoff + kb);
        ldsm4(al, sb + 9216 + aoff + kb);
        ldsm4(bh, sb + 18432 + boff + kb);
        ldsm4(bl, sb + 23040 + boff + kb);
#pragma unroll
        for (int nt = 0; nt < 2; nt++) {
            mma_bf16(acc[nt], ah, bh[2 * nt], bh[2 * nt + 1]);
            mma_bf16(acc[nt], al, bh[2 * nt], bh[2 * nt + 1]);
            mma_bf16(acc[nt], ah, bl[2 * nt], bl[2 * nt + 1]);
        }
    }
}

__device__ __forceinline__ void store_accums(char* sm, int lane, int M0, int N0,
                                             float acc[2][4]) {
    float* sD = (float*)(sm + SD_OFF);
    int r0 = M0 + (lane >> 2);
#pragma unroll
    for (int nt = 0; nt < 2; nt++) {
        int col = N0 + nt * 8 + (lane & 3) * 2;
        *reinterpret_cast<float2*>(&sD[r0 * 34 + col]) = make_float2(acc[nt][0], acc[nt][1]);
        *reinterpret_cast<float2*>(&sD[(r0 + 8) * 34 + col]) = make_float2(acc[nt][2], acc[nt][3]);
    }
}

// =====================================================================
// k_steps: persistent recurrent kernel. grid 128, 256 threads.
// =====================================================================
__global__ void __launch_bounds__(256, 1) k_steps(
    const float* __restrict__ enc_c,
    const float* __restrict__ b_ih1, const float* __restrict__ b_hh1,
    float* __restrict__ out) {
    extern __shared__ char sm[];
    const uint32_t smb = smem_u32(sm);
    const int tid = threadIdx.x, lane = tid & 31, warp = tid >> 5;
    const int cta = blockIdx.x, hu0 = cta * UPC;
    const int M0 = (warp & 3) * 16, N0 = (warp >> 2) * 16;

    float* sD  = (float*)(sm + SD_OFF);
    float* sP  = (float*)(sm + SP_OFF);
    float* sc0 = (float*)(sm + SC0_OFF);
    float* sc1 = (float*)(sm + SC1_OFF);
    float* sB1 = (float*)(sm + SB1_OFF);

    // init CTA-private state
    for (int i = tid; i < 512; i += 256) {
        int m = i >> 3, u = i & 7;
        sc0[i] = enc_c[m * HH + hu0 + u];
        sc1[i] = enc_c[BB * HH + m * HH + hu0 + u];
    }
    if (tid < 32) {
        int col = (tid >> 3) * HH + hu0 + (tid & 7);
        sB1[tid] = b_ih1[col] + b_hh1[col];
    }
    __syncthreads();

    const __nv_bfloat16* gB0h = g_B0hi + (size_t)cta * 16 * 2048;
    const __nv_bfloat16* gB0l = g_B0lo + (size_t)cta * 16 * 2048;
    const __nv_bfloat16* gB1h = g_B1hi + (size_t)cta * 32 * 2048;
    const __nv_bfloat16* gB1l = g_B1lo + (size_t)cta * 32 * 2048;

    const int ep_m = tid >> 2, ep_u0 = (tid & 3) * 2;
    unsigned gen = 1;

#pragma unroll 1
    for (int t = 0; t < SS; t++) {
        const int rd = t & 1, wrb = 1 - rd;

        // ================= phase L0 =================
        {
            const __nv_bfloat16* gAh = g_h0hi[rd];
            const __nv_bfloat16* gAl = g_h0lo[rd];
            float acc[2][4];
#pragma unroll
            for (int i = 0; i < 2; i++)
#pragma unroll
                for (int j = 0; j < 4; j++) acc[i][j] = 0.0f;

            // group 0: chunk 0 + P0-row prefetch
            copy_chunk(smb, 0, tid, gAh, gAl, 0, gB0h, gB0l);
            {
                const float* src = g_P0 + ((size_t)t * BB + ep_m) * GG +
                                   (tid & 3) * HH + hu0;
                uint32_t dst = smb + SP_OFF + (uint32_t)tid * 32;
                cpa16(dst, src);
                cpa16(dst + 16, src + 4);
            }
            CP_COMMIT();
            copy_chunk(smb, 1, tid, gAh, gAl, 64, gB0h + 2048, gB0l + 2048);
            CP_COMMIT();

#pragma unroll 1
            for (int c = 0; c < 16; c++) {
                if (c < 15) cp_wait<1>(); else cp_wait<0>();
                __syncthreads();
                compute_chunk(smb, c % 3, lane, M0, N0, acc);
                if (c + 2 < 16) {
                    copy_chunk(smb, (c + 2) % 3, tid, gAh, gAl, (c + 2) * 64,
                               gB0h + (size_t)(c + 2) * 2048, gB0l + (size_t)(c + 2) * 2048);
                    CP_COMMIT();
                }
            }
            store_accums(sm, lane, M0, N0, acc);
            __syncthreads();

            // epilogue: all 256 threads, 2 cells each
            const float* sDr = sD + ep_m * 34;
            const float* sPm = sP + ep_m * 32;
            float hv[2];
#pragma unroll
            for (int e = 0; e < 2; e++) {
                int u = ep_u0 + e;
                float gi = sDr[u]      + sPm[u];
                float gf = sDr[8 + u]  + sPm[8 + u];
                float gg = sDr[16 + u] + sPm[16 + u];
                float go = sDr[24 + u] + sPm[24 + u];
                float cn = sigf(gf) * sc0[ep_m * 8 + u] + sigf(gi) * tanhf(gg);
                sc0[ep_m * 8 + u] = cn;
                hv[e] = sigf(go) * tanhf(cn);
            }
            __nv_bfloat16 a0 = __float2bfloat16(hv[0]);
            __nv_bfloat16 a1 = __float2bfloat16(hv[1]);
            unsigned hp = (unsigned)__bfloat16_as_ushort(a0) |
                          ((unsigned)__bfloat16_as_ushort(a1) << 16);
            __nv_bfloat16 l0v = __float2bfloat16(hv[0] - __bfloat162float(a0));
            __nv_bfloat16 l1v = __float2bfloat16(hv[1] - __bfloat162float(a1));
            unsigned lp = (unsigned)__bfloat16_as_ushort(l0v) |
                          ((unsigned)__bfloat16_as_ushort(l1v) << 16);
            int hidx = ep_m * HH + hu0 + ep_u0;
            *reinterpret_cast<unsigned*>(&g_h0hi[wrb][hidx]) = hp;
            *reinterpret_cast<unsigned*>(&g_h0lo[wrb][hidx]) = lp;
        }
        grid_bar(tid, gen++);

        // ================= phase L1 =================
        {
            const __nv_bfloat16* Ah[2] = { g_h0hi[wrb], g_h1hi[rd] };
            const __nv_bfloat16* Al[2] = { g_h0lo[wrb], g_h1lo[rd] };
            float acc[2][4];
#pragma unroll
            for (int i = 0; i < 2; i++)
#pragma unroll
                for (int j = 0; j < 4; j++) acc[i][j] = 0.0f;

            copy_chunk(smb, 0, tid, Ah[0], Al[0], 0, gB1h, gB1l);
            CP_COMMIT();
            copy_chunk(smb, 1, tid, Ah[0], Al[0], 64, gB1h + 2048, gB1l + 2048);
            CP_COMMIT();

#pragma unroll 1
            for (int c = 0; c < 32; c++) {
                if (c < 31) cp_wait<1>(); else cp_wait<0>();
                __syncthreads();
                compute_chunk(smb, c % 3, lane, M0, N0, acc);
                if (c + 2 < 32) {
                    int cn = c + 2, ph = cn >> 4, kb = (cn & 15) * 64;
                    copy_chunk(smb, cn % 3, tid, Ah[ph], Al[ph], kb,
                               gB1h + (size_t)cn * 2048, gB1l + (size_t)cn * 2048);
                    CP_COMMIT();
                }
            }
            store_accums(sm, lane, M0, N0, acc);
            __syncthreads();

            const float* sDr = sD + ep_m * 34;
            float hv[2];
#pragma unroll
            for (int e = 0; e < 2; e++) {
                int u = ep_u0 + e;
                float gi = sDr[u]      + sB1[u];
                float gf = sDr[8 + u]  + sB1[8 + u];
                float gg = sDr[16 + u] + sB1[16 + u];
                float go = sDr[24 + u] + sB1[24 + u];
                float cn = sigf(gf) * sc1[ep_m * 8 + u] + sigf(gi) * tanhf(gg);
                sc1[ep_m * 8 + u] = cn;
                hv[e] = sigf(go) * tanhf(cn);
            }
            __nv_bfloat16 a0 = __float2bfloat16(hv[0]);
            __nv_bfloat16 a1 = __float2bfloat16(hv[1]);
            unsigned hp = (unsigned)__bfloat16_as_ushort(a0) |
                          ((unsigned)__bfloat16_as_ushort(a1) << 16);
            __nv_bfloat16 l0v = __float2bfloat16(hv[0] - __bfloat162float(a0));
            __nv_bfloat16 l1v = __float2bfloat16(hv[1] - __bfloat162float(a1));
            unsigned lp = (unsigned)__bfloat16_as_ushort(l0v) |
                          ((unsigned)__bfloat16_as_ushort(l1v) << 16);
            int hidx = ep_m * HH + hu0 + ep_u0;
            *reinterpret_cast<unsigned*>(&g_h1hi[wrb][hidx]) = hp;
            *reinterpret_cast<unsigned*>(&g_h1lo[wrb][hidx]) = lp;
            *reinterpret_cast<float2*>(out + (size_t)t * BB * HH + hidx) =
                make_float2(hv[0], hv[1]);
        }
        grid_bar(tid, gen++);
    }
}

// =====================================================================
extern "C" void kernel_launch(void* const* d_in, const int* in_sizes, int n_in,
                              void* d_out, int out_size) {
    const int*   tok      = (const int*)d_in[0];
    const int*   src      = (const int*)d_in[1];
    const float* enc_outs = (const float*)d_in[2];
    const float* enc_h    = (const float*)d_in[3];
    const float* enc_c    = (const float*)d_in[4];
    const float* embed    = (const float*)d_in[5];
    const float* W_ih0    = (const float*)d_in[6];
    const float* W_hh0    = (const float*)d_in[7];
    const float* b_ih0    = (const float*)d_in[8];
    const float* b_hh0    = (const float*)d_in[9];
    const float* W_ih1    = (const float*)d_in[10];
    const float* W_hh1    = (const float*)d_in[11];
    const float* b_ih1    = (const float*)d_in[12];
    const float* b_hh1    = (const float*)d_in[13];
    float* out = (float*)d_out;

    cudaFuncSetAttribute(k_steps, cudaFuncAttributeMaxDynamicSharedMemorySize, DYN_SMEM);

    // launch order fixed so ncu (-s 5 -c 1) captures k_steps (launch #6)
    k_init<<<(BB * HH + 255) / 256, 256>>>(enc_h);
    k_static<<<dim3(GG / 256, BB / 8), 256>>>(enc_outs, src, embed, W_ih0, b_ih0, b_hh0);
    k_precompute<<<dim3(SS, GG / 32), 256>>>(tok, embed, W_ih0);
    k_prep0<<<dim3(16, NCTA), 256>>>(W_hh0);
    k_prep12<<<dim3(16, NCTA, 2), 256>>>(W_ih1, W_hh1);
    k_steps<<<NCTA, 256, DYN_SMEM>>>(enc_c, b_ih1, b_hh1, out);
}

// round 11
// speedup vs baseline: 2.4355x; 1.1523x over previous
#include <cuda_runtime.h>
#include <cuda_bf16.h>
#include <cuda_fp16.h>
#include <math.h>
#include <stdint.h>

#define BB 64
#define SS 256
#define HH 1024
#define EE 512
#define GG 4096
#define NCTA 128
#define UPC 8     // hidden units per CTA (N = 32 gate cols)

// dynamic smem (bytes), 3 stages of 23040:
//   stage s at s*23040: Ahi(64x144)=9216 | Alo +9216 | Bh(32x144)=4608 at +18432
#define STGSZ 23040
#define SD_OFF  69120   // D tile 64 x 34 f32 = 8704
#define SP_OFF  77824   // P0 prefetch 64 x 32 f32 = 8192
#define SC0_OFF 86016   // c0 state 512 f32
#define SC1_OFF 88064   // c1 state 512 f32
#define SB1_OFF 90112   // layer1 bias 32 f32
#define DYN_SMEM 90368

// -------- device-global scratch --------
__device__ float g_P0[(size_t)SS * BB * GG];
__device__ float g_sp[BB * GG];
__device__ __half g_h0hi[2][BB * HH];
__device__ __half g_h0lo[2][BB * HH];   // lo scaled by 2^10
__device__ __half g_h1hi[2][BB * HH];
__device__ __half g_h1lo[2][BB * HH];
// pre-gathered dense fp16 weight tiles [cta][slot][32n][64k]
__device__ __align__(16) __half g_B0h[(size_t)NCTA * 16 * 2048];
__device__ __align__(16) __half g_B1h[(size_t)NCTA * 32 * 2048];
// grid barrier state
__device__ unsigned g_bcnt;
__device__ unsigned g_bgen;

typedef unsigned long long u64t;
union F4 { float4 v; float f[4]; };
union P8 { __half h[8]; uint4 v; };

__device__ __forceinline__ void fma2(u64t& c, u64t a, u64t b) {
    asm("fma.rn.f32x2 %0, %1, %2, %0;" : "+l"(c) : "l"(a), "l"(b));
}
__device__ __forceinline__ float hsum2(u64t v) {
    return __uint_as_float((unsigned)(v & 0xffffffffu)) +
           __uint_as_float((unsigned)(v >> 32));
}
__device__ __forceinline__ float sigf(float x) { return 1.0f / (1.0f + expf(-x)); }

__device__ __forceinline__ uint32_t smem_u32(const void* p) {
    uint32_t a;
    asm("{ .reg .u64 t; cvta.to.shared.u64 t, %1; cvt.u32.u64 %0, t; }" : "=r"(a) : "l"(p));
    return a;
}
__device__ __forceinline__ void cpa16(uint32_t d, const void* s) {
    asm volatile("cp.async.cg.shared.global [%0], [%1], 16;" :: "r"(d), "l"(s));
}
#define CP_COMMIT() asm volatile("cp.async.commit_group;" ::: "memory")
template<int N> __device__ __forceinline__ void cp_wait() {
    asm volatile("cp.async.wait_group %0;" :: "n"(N) : "memory");
}

__device__ __forceinline__ void ldsm4(uint32_t* r, uint32_t a) {
    asm volatile("ldmatrix.sync.aligned.m8n8.x4.shared.b16 {%0,%1,%2,%3}, [%4];"
                 : "=r"(r[0]), "=r"(r[1]), "=r"(r[2]), "=r"(r[3]) : "r"(a));
}
__device__ __forceinline__ void mma_f16(float* d, const uint32_t* a, uint32_t b0, uint32_t b1) {
    asm volatile(
        "mma.sync.aligned.m16n8k16.row.col.f32.f16.f16.f32 "
        "{%0,%1,%2,%3}, {%4,%5,%6,%7}, {%8,%9}, {%0,%1,%2,%3};"
        : "+f"(d[0]), "+f"(d[1]), "+f"(d[2]), "+f"(d[3])
        : "r"(a[0]), "r"(a[1]), "r"(a[2]), "r"(a[3]), "r"(b0), "r"(b1));
}

// grid-wide barrier: all 128 CTAs co-resident (1/SM on 148 SMs).
__device__ __forceinline__ void grid_bar(int tid, unsigned gen) {
    __threadfence();
    __syncthreads();
    if (tid == 0) {
        if (atomicAdd(&g_bcnt, 1u) == NCTA - 1) {
            atomicExch(&g_bcnt, 0u);
            __threadfence();
            atomicExch(&g_bgen, gen);
        } else {
            while (atomicOr(&g_bgen, 0u) < gen) {}
            __threadfence();
        }
    }
    __syncthreads();
}

// =====================================================================
// k_static (proven, unchanged)
// =====================================================================
__global__ void __launch_bounds__(256) k_static(
    const float* __restrict__ enc_outs, const int* __restrict__ src_lang,
    const float* __restrict__ embed, const float* __restrict__ W0,
    const float* __restrict__ b_ih0, const float* __restrict__ b_hh0) {
    __shared__ float sC[8][EE];
    __shared__ float sL[8][EE];
    const int tid = threadIdx.x;
    const int b0 = blockIdx.y * 8;
    for (int i = tid; i < 8 * EE; i += 256) {
        int b = i >> 9, k = i & (EE - 1);
        sC[b][k] = enc_outs[((size_t)(b0 + b) * 128 + 127) * EE + k];
        sL[b][k] = embed[(size_t)src_lang[b0 + b] * EE + k];
    }
    __syncthreads();
    const int g = blockIdx.x * 256 + tid;
    const float* wr = W0 + (size_t)g * 1536;
    float acc[8];
#pragma unroll
    for (int i = 0; i < 8; i++) acc[i] = 0.0f;
    for (int k = 0; k < EE; k += 4) {
        float4 wc = *reinterpret_cast<const float4*>(wr + 512 + k);
        float4 wl = *reinterpret_cast<const float4*>(wr + 1024 + k);
#pragma unroll
        for (int b = 0; b < 8; b++) {
            float4 c4 = *reinterpret_cast<const float4*>(&sC[b][k]);
            float4 l4 = *reinterpret_cast<const float4*>(&sL[b][k]);
            acc[b] += wc.x * c4.x + wc.y * c4.y + wc.z * c4.z + wc.w * c4.w;
            acc[b] += wl.x * l4.x + wl.y * l4.y + wl.z * l4.z + wl.w * l4.w;
        }
    }
    float bias = b_ih0[g] + b_hh0[g];
#pragma unroll
    for (int b = 0; b < 8; b++) g_sp[(b0 + b) * GG + g] = acc[b] + bias;
}

// =====================================================================
// k_precompute (proven, unchanged)
// =====================================================================
__global__ void __launch_bounds__(256) k_precompute(
    const int* __restrict__ tokens, const float* __restrict__ embed,
    const float* __restrict__ W0) {
    __shared__ __align__(16) float sA[64][68];
    __shared__ __align__(16) float sW[32][68];
    __shared__ int sTok[64];
    const int tid = threadIdx.x;
    const int t = blockIdx.x;
    const int col0 = blockIdx.y * 32;
    const int j = tid & 31, mg = tid >> 5;
    const int ar = tid >> 2, al = tid & 3;
    const int wri = tid >> 3, wci = (tid & 7) * 8;
    const float* wgrow = W0 + (size_t)(col0 + wri) * 1536 + wci;

    if (tid < 64) sTok[tid] = tokens[tid * SS + t];
    __syncthreads();
    const float* arow = embed + (size_t)sTok[ar] * EE;

    u64t acc[8];
#pragma unroll
    for (int i = 0; i < 8; i++) acc[i] = 0ull;

    float4 pA[4], pW[2];
#pragma unroll
    for (int q = 0; q < 4; q++)
        pA[q] = *reinterpret_cast<const float4*>(arow + (al + 4 * q) * 4);
    pW[0] = *reinterpret_cast<const float4*>(wgrow);
    pW[1] = *reinterpret_cast<const float4*>(wgrow + 4);

#pragma unroll 1
    for (int c = 0; c < EE / 64; c++) {
#pragma unroll
        for (int q = 0; q < 4; q++)
            *reinterpret_cast<float4*>(&sA[ar][(al + 4 * q) * 4]) = pA[q];
        *reinterpret_cast<float4*>(&sW[wri][wci]) = pW[0];
        *reinterpret_cast<float4*>(&sW[wri][wci + 4]) = pW[1];
        __syncthreads();
        if (c + 1 < EE / 64) {
            int k1 = (c + 1) * 64;
#pragma unroll
            for (int q = 0; q < 4; q++)
                pA[q] = *reinterpret_cast<const float4*>(arow + k1 + (al + 4 * q) * 4);
            pW[0] = *reinterpret_cast<const float4*>(wgrow + k1);
            pW[1] = *reinterpret_cast<const float4*>(wgrow + k1 + 4);
        }
#pragma unroll
        for (int kk = 0; kk < 64; kk += 4) {
            ulonglong2 w = *reinterpret_cast<const ulonglong2*>(&sW[j][kk]);
#pragma unroll
            for (int mi = 0; mi < 8; mi++) {
                ulonglong2 a = *reinterpret_cast<const ulonglong2*>(&sA[mg * 8 + mi][kk]);
                fma2(acc[mi], a.x, w.x);
                fma2(acc[mi], a.y, w.y);
            }
        }
        __syncthreads();
    }
    const int col = col0 + j;
#pragma unroll
    for (int mi = 0; mi < 8; mi++) {
        int m = mg * 8 + mi;
        g_P0[((size_t)t * BB + m) * GG + col] = hsum2(acc[mi]) + g_sp[m * GG + col];
    }
}

// =====================================================================
// k_prep: grid (16, NCTA, 3). Gathers W rows into dense per-CTA fp16
// [32n][64k] tiles. z=0 blocks with flat-id < 256 also do state init.
// =====================================================================
__global__ void __launch_bounds__(256) k_prep(
    const float* __restrict__ W_hh0, const float* __restrict__ W_ih1,
    const float* __restrict__ W_hh1, const float* __restrict__ enc_h) {
    const int c = blockIdx.x, cta = blockIdx.y, which = blockIdx.z, tid = threadIdx.x;

    if (which == 0) {
        int flat = cta * 16 + c;   // 0..2047
        if (flat == 0 && tid == 0) { g_bcnt = 0; g_bgen = 0; }
        if (flat < 256) {          // h init: 65536 elems / 256 thr = 256 blocks
            int i = flat * 256 + tid;
            const int n = BB * HH;
            float h0v = enc_h[i], h1v = enc_h[n + i];
            __half a = __float2half(h0v);
            g_h0hi[0][i] = a;
            g_h0lo[0][i] = __float2half((h0v - __half2float(a)) * 1024.0f);
            __half b = __float2half(h1v);
            g_h1hi[0][i] = b;
            g_h1lo[0][i] = __float2half((h1v - __half2float(b)) * 1024.0f);
        }
    }

    const float* W = (which == 0) ? W_hh0 : (which == 1) ? W_ih1 : W_hh1;
    const int nloc = tid >> 3, ks = (tid & 7) * 8;
    const int grow = (nloc >> 3) * HH + cta * UPC + (nloc & 7);
    const float* s = W + (size_t)grow * HH + c * 64 + ks;
    float x[8];
    *reinterpret_cast<float4*>(x)     = *reinterpret_cast<const float4*>(s);
    *reinterpret_cast<float4*>(x + 4) = *reinterpret_cast<const float4*>(s + 4);
    P8 ph;
#pragma unroll
    for (int u = 0; u < 8; u++) ph.h[u] = __float2half(x[u]);
    __half* Gh;
    size_t base;
    if (which == 0) { Gh = g_B0h; base = ((size_t)cta * 16 + c) * 2048; }
    else { Gh = g_B1h; base = ((size_t)cta * 32 + (which == 2 ? 16 : 0) + c) * 2048; }
    *reinterpret_cast<uint4*>(Gh + base + (size_t)nloc * 64 + ks) = ph.v;
}

// =====================================================================
// persistent step-kernel building blocks (M=64, N=32; warp tile 16x16)
// =====================================================================
__device__ __forceinline__ void copy_chunk(
    uint32_t smb, int stage, int tid,
    const __half* gAh, const __half* gAl, int kbase, const __half* gBh) {
    const uint32_t sb = smb + stage * STGSZ;
#pragma unroll
    for (int i = tid; i < 512; i += 256) {
        int row = i >> 3, s = i & 7;
        uint32_t so = (uint32_t)row * 144 + (s << 4);
        const char* ah = (const char*)(gAh + (size_t)row * HH + kbase) + (s << 4);
        const char* al = (const char*)(gAl + (size_t)row * HH + kbase) + (s << 4);
        cpa16(sb + so, ah);
        cpa16(sb + 9216 + so, al);
    }
    {
        int row = tid >> 3, s = tid & 7;
        uint32_t so = (uint32_t)row * 144 + (s << 4);
        cpa16(sb + 18432 + so, (const char*)gBh + ((size_t)tid << 4));
    }
}

__device__ __forceinline__ void compute_chunk(uint32_t smb, int stage, int lane,
                                              int M0, int N0,
                                              float accH[2][4], float accL[2][4]) {
    const uint32_t sb = smb + stage * STGSZ;
    const uint32_t aoff = (uint32_t)(M0 + (lane & 15)) * 144 + ((lane >> 4) << 4);
    const uint32_t boff = (uint32_t)(N0 + (((lane >> 4) & 1) << 3) + (lane & 7)) * 144 +
                          (((lane >> 3) & 1) << 4);
#pragma unroll
    for (int ksi = 0; ksi < 4; ksi++) {
        const uint32_t kb = ksi << 5;
        uint32_t ah[4], al[4], bh[4];
        ldsm4(ah, sb + aoff + kb);
        ldsm4(al, sb + 9216 + aoff + kb);
        ldsm4(bh, sb + 18432 + boff + kb);
#pragma unroll
        for (int nt = 0; nt < 2; nt++) {
            mma_f16(accH[nt], ah, bh[2 * nt], bh[2 * nt + 1]);
            mma_f16(accL[nt], al, bh[2 * nt], bh[2 * nt + 1]);
        }
    }
}

__device__ __forceinline__ void store_accums(char* sm, int lane, int M0, int N0,
                                             float accH[2][4], float accL[2][4]) {
    float* sD = (float*)(sm + SD_OFF);
    const float cs = 1.0f / 1024.0f;
    int r0 = M0 + (lane >> 2);
#pragma unroll
    for (int nt = 0; nt < 2; nt++) {
        int col = N0 + nt * 8 + (lane & 3) * 2;
        *reinterpret_cast<float2*>(&sD[r0 * 34 + col]) =
            make_float2(accH[nt][0] + accL[nt][0] * cs, accH[nt][1] + accL[nt][1] * cs);
        *reinterpret_cast<float2*>(&sD[(r0 + 8) * 34 + col]) =
            make_float2(accH[nt][2] + accL[nt][2] * cs, accH[nt][3] + accL[nt][3] * cs);
    }
}

// =====================================================================
// k_steps: persistent recurrent kernel. grid 128, 256 threads.
// =====================================================================
__global__ void __launch_bounds__(256, 1) k_steps(
    const float* __restrict__ enc_c,
    const float* __restrict__ b_ih1, const float* __restrict__ b_hh1,
    float* __restrict__ out) {
    extern __shared__ char sm[];
    const uint32_t smb = smem_u32(sm);
    const int tid = threadIdx.x, lane = tid & 31, warp = tid >> 5;
    const int cta = blockIdx.x, hu0 = cta * UPC;
    const int M0 = (warp & 3) * 16, N0 = (warp >> 2) * 16;

    float* sD  = (float*)(sm + SD_OFF);
    float* sP  = (float*)(sm + SP_OFF);
    float* sc0 = (float*)(sm + SC0_OFF);
    float* sc1 = (float*)(sm + SC1_OFF);
    float* sB1 = (float*)(sm + SB1_OFF);

    for (int i = tid; i < 512; i += 256) {
        int m = i >> 3, u = i & 7;
        sc0[i] = enc_c[m * HH + hu0 + u];
        sc1[i] = enc_c[BB * HH + m * HH + hu0 + u];
    }
    if (tid < 32) {
        int col = (tid >> 3) * HH + hu0 + (tid & 7);
        sB1[tid] = b_ih1[col] + b_hh1[col];
    }
    __syncthreads();

    const __half* gB0h = g_B0h + (size_t)cta * 16 * 2048;
    const __half* gB1h = g_B1h + (size_t)cta * 32 * 2048;

    const int ep_m = tid >> 2, ep_u0 = (tid & 3) * 2;
    unsigned gen = 1;

#pragma unroll 1
    for (int t = 0; t < SS; t++) {
        const int rd = t & 1, wrb = 1 - rd;

        // ================= phase L0 =================
        {
            const __half* gAh = g_h0hi[rd];
            const __half* gAl = g_h0lo[rd];
            float accH[2][4], accL[2][4];
#pragma unroll
            for (int i = 0; i < 2; i++)
#pragma unroll
                for (int j = 0; j < 4; j++) { accH[i][j] = 0.0f; accL[i][j] = 0.0f; }

            copy_chunk(smb, 0, tid, gAh, gAl, 0, gB0h);
            {
                const float* src = g_P0 + ((size_t)t * BB + ep_m) * GG +
                                   (tid & 3) * HH + hu0;
                uint32_t dst = smb + SP_OFF + (uint32_t)tid * 32;
                cpa16(dst, src);
                cpa16(dst + 16, src + 4);
            }
            CP_COMMIT();
            copy_chunk(smb, 1, tid, gAh, gAl, 64, gB0h + 2048);
            CP_COMMIT();

#pragma unroll 1
            for (int c = 0; c < 16; c++) {
                if (c < 15) cp_wait<1>(); else cp_wait<0>();
                __syncthreads();
                compute_chunk(smb, c % 3, lane, M0, N0, accH, accL);
                if (c + 2 < 16) {
                    copy_chunk(smb, (c + 2) % 3, tid, gAh, gAl, (c + 2) * 64,
                               gB0h + (size_t)(c + 2) * 2048);
                    CP_COMMIT();
                }
            }
            store_accums(sm, lane, M0, N0, accH, accL);
            __syncthreads();

            const float* sDr = sD + ep_m * 34;
            const float* sPm = sP + ep_m * 32;
            float hv[2];
#pragma unroll
            for (int e = 0; e < 2; e++) {
                int u = ep_u0 + e;
                float gi = sDr[u]      + sPm[u];
                float gf = sDr[8 + u]  + sPm[8 + u];
                float gg = sDr[16 + u] + sPm[16 + u];
                float go = sDr[24 + u] + sPm[24 + u];
                float cn = sigf(gf) * sc0[ep_m * 8 + u] + sigf(gi) * tanhf(gg);
                sc0[ep_m * 8 + u] = cn;
                hv[e] = sigf(go) * tanhf(cn);
            }
            __half a0 = __float2half(hv[0]);
            __half a1 = __float2half(hv[1]);
            unsigned hp = (unsigned)__half_as_ushort(a0) |
                          ((unsigned)__half_as_ushort(a1) << 16);
            __half l0v = __float2half((hv[0] - __half2float(a0)) * 1024.0f);
            __half l1v = __float2half((hv[1] - __half2float(a1)) * 1024.0f);
            unsigned lp = (unsigned)__half_as_ushort(l0v) |
                          ((unsigned)__half_as_ushort(l1v) << 16);
            int hidx = ep_m * HH + hu0 + ep_u0;
            *reinterpret_cast<unsigned*>(&g_h0hi[wrb][hidx]) = hp;
            *reinterpret_cast<unsigned*>(&g_h0lo[wrb][hidx]) = lp;
        }
        grid_bar(tid, gen++);

        // ================= phase L1 =================
        {
            const __half* Ah[2] = { g_h0hi[wrb], g_h1hi[rd] };
            const __half* Al[2] = { g_h0lo[wrb], g_h1lo[rd] };
            float accH[2][4], accL[2][4];
#pragma unroll
            for (int i = 0; i < 2; i++)
#pragma unroll
                for (int j = 0; j < 4; j++) { accH[i][j] = 0.0f; accL[i][j] = 0.0f; }

            copy_chunk(smb, 0, tid, Ah[0], Al[0], 0, gB1h);
            CP_COMMIT();
            copy_chunk(smb, 1, tid, Ah[0], Al[0], 64, gB1h + 2048);
            CP_COMMIT();

#pragma unroll 1
            for (int c = 0; c < 32; c++) {
                if (c < 31) cp_wait<1>(); else cp_wait<0>();
                __syncthreads();
                compute_chunk(smb, c % 3, lane, M0, N0, accH, accL);
                if (c + 2 < 32) {
                    int cn = c + 2, ph = cn >> 4, kb = (cn & 15) * 64;
                    copy_chunk(smb, cn % 3, tid, Ah[ph], Al[ph], kb,
                               gB1h + (size_t)cn * 2048);
                    CP_COMMIT();
                }
            }
            store_accums(sm, lane, M0, N0, accH, accL);
            __syncthreads();

            const float* sDr = sD + ep_m * 34;
            float hv[2];
#pragma unroll
            for (int e = 0; e < 2; e++) {
                int u = ep_u0 + e;
                float gi = sDr[u]      + sB1[u];
                float gf = sDr[8 + u]  + sB1[8 + u];
                float gg = sDr[16 + u] + sB1[16 + u];
                float go = sDr[24 + u] + sB1[24 + u];
                float cn = sigf(gf) * sc1[ep_m * 8 + u] + sigf(gi) * tanhf(gg);
                sc1[ep_m * 8 + u] = cn;
                hv[e] = sigf(go) * tanhf(cn);
            }
            __half a0 = __float2half(hv[0]);
            __half a1 = __float2half(hv[1]);
            unsigned hp = (unsigned)__half_as_ushort(a0) |
                          ((unsigned)__half_as_ushort(a1) << 16);
            __half l0v = __float2half((hv[0] - __half2float(a0)) * 1024.0f);
            __half l1v = __float2half((hv[1] - __half2float(a1)) * 1024.0f);
            unsigned lp = (unsigned)__half_as_ushort(l0v) |
                          ((unsigned)__half_as_ushort(l1v) << 16);
            int hidx = ep_m * HH + hu0 + ep_u0;
            *reinterpret_cast<unsigned*>(&g_h1hi[wrb][hidx]) = hp;
            *reinterpret_cast<unsigned*>(&g_h1lo[wrb][hidx]) = lp;
            *reinterpret_cast<float2*>(out + (size_t)t * BB * HH + hidx) =
                make_float2(hv[0], hv[1]);
        }
        grid_bar(tid, gen++);
    }
}

// =====================================================================
extern "C" void kernel_launch(void* const* d_in, const int* in_sizes, int n_in,
                              void* d_out, int out_size) {
    const int*   tok      = (const int*)d_in[0];
    const int*   src      = (const int*)d_in[1];
    const float* enc_outs = (const float*)d_in[2];
    const float* enc_h    = (const float*)d_in[3];
    const float* enc_c    = (const float*)d_in[4];
    const float* embed    = (const float*)d_in[5];
    const float* W_ih0    = (const float*)d_in[6];
    const float* W_hh0    = (const float*)d_in[7];
    const float* b_ih0    = (const float*)d_in[8];
    const float* b_hh0    = (const float*)d_in[9];
    const float* W_ih1    = (const float*)d_in[10];
    const float* W_hh1    = (const float*)d_in[11];
    const float* b_ih1    = (const float*)d_in[12];
    const float* b_hh1    = (const float*)d_in[13];
    float* out = (float*)d_out;

    cudaFuncSetAttribute(k_steps, cudaFuncAttributeMaxDynamicSharedMemorySize, DYN_SMEM);

    k_static<<<dim3(GG / 256, BB / 8), 256>>>(enc_outs, src, embed, W_ih0, b_ih0, b_hh0);
    k_precompute<<<dim3(SS, GG / 32), 256>>>(tok, embed, W_ih0);
    k_prep<<<dim3(16, NCTA, 3), 256>>>(W_hh0, W_ih1, W_hh1, enc_h);
    k_steps<<<NCTA, 256, DYN_SMEM>>>(enc_c, b_ih1, b_hh1, out);
}

// round 12
// speedup vs baseline: 3.1197x; 1.2809x over previous
#include <cuda_runtime.h>
#include <cuda_bf16.h>
#include <cuda_fp16.h>
#include <math.h>
#include <stdint.h>

#define BB 64
#define SS 256
#define HH 1024
#define EE 512
#define GG 4096
#define NCTA 128
#define UPC 8     // hidden units per CTA (N = 32 gate cols)

// dynamic smem (bytes), 3 stages of 13824:
//   stage s at s*13824: Ah(64x144)=9216 | Bh(32x144)=4608 at +9216
#define STGSZ 13824
#define SD_OFF  41472   // D tile 64 x 34 f32 = 8704
#define SP_OFF  50176   // P0 prefetch 64 x 32 f32 = 8192
#define SC0_OFF 58368   // c0 state 512 f32
#define SC1_OFF 60416   // c1 state 512 f32
#define SB1_OFF 62464   // layer1 bias 32 f32
#define DYN_SMEM 62592

// -------- device-global scratch --------
__device__ float g_P0[(size_t)SS * BB * GG];
__device__ float g_sp[BB * GG];
__device__ __half g_h0[2][BB * HH];
__device__ __half g_h1[2][BB * HH];
// pre-gathered dense fp16 weight tiles [cta][slot][32n][64k]
__device__ __align__(16) __half g_B0h[(size_t)NCTA * 16 * 2048];
__device__ __align__(16) __half g_B1h[(size_t)NCTA * 32 * 2048];
// grid barrier state
__device__ unsigned g_bcnt;
__device__ unsigned g_bgen;

typedef unsigned long long u64t;
union F4 { float4 v; float f[4]; };
union P8 { __half h[8]; uint4 v; };

__device__ __forceinline__ void fma2(u64t& c, u64t a, u64t b) {
    asm("fma.rn.f32x2 %0, %1, %2, %0;" : "+l"(c) : "l"(a), "l"(b));
}
__device__ __forceinline__ float hsum2(u64t v) {
    return __uint_as_float((unsigned)(v & 0xffffffffu)) +
           __uint_as_float((unsigned)(v >> 32));
}
__device__ __forceinline__ float sigf(float x) { return 1.0f / (1.0f + expf(-x)); }

__device__ __forceinline__ uint32_t smem_u32(const void* p) {
    uint32_t a;
    asm("{ .reg .u64 t; cvta.to.shared.u64 t, %1; cvt.u32.u64 %0, t; }" : "=r"(a) : "l"(p));
    return a;
}
__device__ __forceinline__ void cpa16(uint32_t d, const void* s) {
    asm volatile("cp.async.cg.shared.global [%0], [%1], 16;" :: "r"(d), "l"(s));
}
#define CP_COMMIT() asm volatile("cp.async.commit_group;" ::: "memory")
template<int N> __device__ __forceinline__ void cp_wait() {
    asm volatile("cp.async.wait_group %0;" :: "n"(N) : "memory");
}

__device__ __forceinline__ void ldsm4(uint32_t* r, uint32_t a) {
    asm volatile("ldmatrix.sync.aligned.m8n8.x4.shared.b16 {%0,%1,%2,%3}, [%4];"
                 : "=r"(r[0]), "=r"(r[1]), "=r"(r[2]), "=r"(r[3]) : "r"(a));
}
__device__ __forceinline__ void mma_f16(float* d, const uint32_t* a, uint32_t b0, uint32_t b1) {
    asm volatile(
        "mma.sync.aligned.m16n8k16.row.col.f32.f16.f16.f32 "
        "{%0,%1,%2,%3}, {%4,%5,%6,%7}, {%8,%9}, {%0,%1,%2,%3};"
        : "+f"(d[0]), "+f"(d[1]), "+f"(d[2]), "+f"(d[3])
        : "r"(a[0]), "r"(a[1]), "r"(a[2]), "r"(a[3]), "r"(b0), "r"(b1));
}

// grid-wide barrier: all 128 CTAs co-resident (1/SM on 148 SMs).
__device__ __forceinline__ void grid_bar(int tid, unsigned gen) {
    __threadfence();
    __syncthreads();
    if (tid == 0) {
        if (atomicAdd(&g_bcnt, 1u) == NCTA - 1) {
            atomicExch(&g_bcnt, 0u);
            __threadfence();
            atomicExch(&g_bgen, gen);
        } else {
            while (atomicOr(&g_bgen, 0u) < gen) {}
            __threadfence();
        }
    }
    __syncthreads();
}

// =====================================================================
// k_static (proven, unchanged)
// =====================================================================
__global__ void __launch_bounds__(256) k_static(
    const float* __restrict__ enc_outs, const int* __restrict__ src_lang,
    const float* __restrict__ embed, const float* __restrict__ W0,
    const float* __restrict__ b_ih0, const float* __restrict__ b_hh0) {
    __shared__ float sC[8][EE];
    __shared__ float sL[8][EE];
    const int tid = threadIdx.x;
    const int b0 = blockIdx.y * 8;
    for (int i = tid; i < 8 * EE; i += 256) {
        int b = i >> 9, k = i & (EE - 1);
        sC[b][k] = enc_outs[((size_t)(b0 + b) * 128 + 127) * EE + k];
        sL[b][k] = embed[(size_t)src_lang[b0 + b] * EE + k];
    }
    __syncthreads();
    const int g = blockIdx.x * 256 + tid;
    const float* wr = W0 + (size_t)g * 1536;
    float acc[8];
#pragma unroll
    for (int i = 0; i < 8; i++) acc[i] = 0.0f;
    for (int k = 0; k < EE; k += 4) {
        float4 wc = *reinterpret_cast<const float4*>(wr + 512 + k);
        float4 wl = *reinterpret_cast<const float4*>(wr + 1024 + k);
#pragma unroll
        for (int b = 0; b < 8; b++) {
            float4 c4 = *reinterpret_cast<const float4*>(&sC[b][k]);
            float4 l4 = *reinterpret_cast<const float4*>(&sL[b][k]);
            acc[b] += wc.x * c4.x + wc.y * c4.y + wc.z * c4.z + wc.w * c4.w;
            acc[b] += wl.x * l4.x + wl.y * l4.y + wl.z * l4.z + wl.w * l4.w;
        }
    }
    float bias = b_ih0[g] + b_hh0[g];
#pragma unroll
    for (int b = 0; b < 8; b++) g_sp[(b0 + b) * GG + g] = acc[b] + bias;
}

// =====================================================================
// k_precompute (proven, unchanged)
// =====================================================================
__global__ void __launch_bounds__(256) k_precompute(
    const int* __restrict__ tokens, const float* __restrict__ embed,
    const float* __restrict__ W0) {
    __shared__ __align__(16) float sA[64][68];
    __shared__ __align__(16) float sW[32][68];
    __shared__ int sTok[64];
    const int tid = threadIdx.x;
    const int t = blockIdx.x;
    const int col0 = blockIdx.y * 32;
    const int j = tid & 31, mg = tid >> 5;
    const int ar = tid >> 2, al = tid & 3;
    const int wri = tid >> 3, wci = (tid & 7) * 8;
    const float* wgrow = W0 + (size_t)(col0 + wri) * 1536 + wci;

    if (tid < 64) sTok[tid] = tokens[tid * SS + t];
    __syncthreads();
    const float* arow = embed + (size_t)sTok[ar] * EE;

    u64t acc[8];
#pragma unroll
    for (int i = 0; i < 8; i++) acc[i] = 0ull;

    float4 pA[4], pW[2];
#pragma unroll
    for (int q = 0; q < 4; q++)
        pA[q] = *reinterpret_cast<const float4*>(arow + (al + 4 * q) * 4);
    pW[0] = *reinterpret_cast<const float4*>(wgrow);
    pW[1] = *reinterpret_cast<const float4*>(wgrow + 4);

#pragma unroll 1
    for (int c = 0; c < EE / 64; c++) {
#pragma unroll
        for (int q = 0; q < 4; q++)
            *reinterpret_cast<float4*>(&sA[ar][(al + 4 * q) * 4]) = pA[q];
        *reinterpret_cast<float4*>(&sW[wri][wci]) = pW[0];
        *reinterpret_cast<float4*>(&sW[wri][wci + 4]) = pW[1];
        __syncthreads();
        if (c + 1 < EE / 64) {
            int k1 = (c + 1) * 64;
#pragma unroll
            for (int q = 0; q < 4; q++)
                pA[q] = *reinterpret_cast<const float4*>(arow + k1 + (al + 4 * q) * 4);
            pW[0] = *reinterpret_cast<const float4*>(wgrow + k1);
            pW[1] = *reinterpret_cast<const float4*>(wgrow + k1 + 4);
        }
#pragma unroll
        for (int kk = 0; kk < 64; kk += 4) {
            ulonglong2 w = *reinterpret_cast<const ulonglong2*>(&sW[j][kk]);
#pragma unroll
            for (int mi = 0; mi < 8; mi++) {
                ulonglong2 a = *reinterpret_cast<const ulonglong2*>(&sA[mg * 8 + mi][kk]);
                fma2(acc[mi], a.x, w.x);
                fma2(acc[mi], a.y, w.y);
            }
        }
        __syncthreads();
    }
    const int col = col0 + j;
#pragma unroll
    for (int mi = 0; mi < 8; mi++) {
        int m = mg * 8 + mi;
        g_P0[((size_t)t * BB + m) * GG + col] = hsum2(acc[mi]) + g_sp[m * GG + col];
    }
}

// =====================================================================
// k_prep: grid (16, NCTA, 3). Gathers W rows into dense per-CTA fp16
// [32n][64k] tiles. z=0 blocks with flat-id < 256 also do state init.
// =====================================================================
__global__ void __launch_bounds__(256) k_prep(
    const float* __restrict__ W_hh0, const float* __restrict__ W_ih1,
    const float* __restrict__ W_hh1, const float* __restrict__ enc_h) {
    const int c = blockIdx.x, cta = blockIdx.y, which = blockIdx.z, tid = threadIdx.x;

    if (which == 0) {
        int flat = cta * 16 + c;   // 0..2047
        if (flat == 0 && tid == 0) { g_bcnt = 0; g_bgen = 0; }
        if (flat < 256) {          // h init: 65536 elems / 256 thr = 256 blocks
            int i = flat * 256 + tid;
            const int n = BB * HH;
            g_h0[0][i] = __float2half(enc_h[i]);
            g_h1[0][i] = __float2half(enc_h[n + i]);
        }
    }

    const float* W = (which == 0) ? W_hh0 : (which == 1) ? W_ih1 : W_hh1;
    const int nloc = tid >> 3, ks = (tid & 7) * 8;
    const int grow = (nloc >> 3) * HH + cta * UPC + (nloc & 7);
    const float* s = W + (size_t)grow * HH + c * 64 + ks;
    float x[8];
    *reinterpret_cast<float4*>(x)     = *reinterpret_cast<const float4*>(s);
    *reinterpret_cast<float4*>(x + 4) = *reinterpret_cast<const float4*>(s + 4);
    P8 ph;
#pragma unroll
    for (int u = 0; u < 8; u++) ph.h[u] = __float2half(x[u]);
    __half* Gh;
    size_t base;
    if (which == 0) { Gh = g_B0h; base = ((size_t)cta * 16 + c) * 2048; }
    else { Gh = g_B1h; base = ((size_t)cta * 32 + (which == 2 ? 16 : 0) + c) * 2048; }
    *reinterpret_cast<uint4*>(Gh + base + (size_t)nloc * 64 + ks) = ph.v;
}

// =====================================================================
// persistent step-kernel building blocks (M=64, N=32; warp tile 16x16)
// =====================================================================
__device__ __forceinline__ void copy_chunk(
    uint32_t smb, int stage, int tid,
    const __half* gA, int kbase, const __half* gBh) {
    const uint32_t sb = smb + stage * STGSZ;
#pragma unroll
    for (int i = tid; i < 512; i += 256) {
        int row = i >> 3, s = i & 7;
        uint32_t so = (uint32_t)row * 144 + (s << 4);
        cpa16(sb + so, (const char*)(gA + (size_t)row * HH + kbase) + (s << 4));
    }
    {
        int row = tid >> 3, s = tid & 7;
        uint32_t so = (uint32_t)row * 144 + (s << 4);
        cpa16(sb + 9216 + so, (const char*)gBh + ((size_t)tid << 4));
    }
}

__device__ __forceinline__ void compute_chunk(uint32_t smb, int stage, int lane,
                                              int M0, int N0, float acc[2][4]) {
    const uint32_t sb = smb + stage * STGSZ;
    const uint32_t aoff = (uint32_t)(M0 + (lane & 15)) * 144 + ((lane >> 4) << 4);
    const uint32_t boff = (uint32_t)(N0 + (((lane >> 4) & 1) << 3) + (lane & 7)) * 144 +
                          (((lane >> 3) & 1) << 4);
#pragma unroll
    for (int ksi = 0; ksi < 4; ksi++) {
        const uint32_t kb = ksi << 5;
        uint32_t ah[4], bh[4];
        ldsm4(ah, sb + aoff + kb);
        ldsm4(bh, sb + 9216 + boff + kb);
#pragma unroll
        for (int nt = 0; nt < 2; nt++)
            mma_f16(acc[nt], ah, bh[2 * nt], bh[2 * nt + 1]);
    }
}

__device__ __forceinline__ void store_accums(char* sm, int lane, int M0, int N0,
                                             float acc[2][4]) {
    float* sD = (float*)(sm + SD_OFF);
    int r0 = M0 + (lane >> 2);
#pragma unroll
    for (int nt = 0; nt < 2; nt++) {
        int col = N0 + nt * 8 + (lane & 3) * 2;
        *reinterpret_cast<float2*>(&sD[r0 * 34 + col]) = make_float2(acc[nt][0], acc[nt][1]);
        *reinterpret_cast<float2*>(&sD[(r0 + 8) * 34 + col]) = make_float2(acc[nt][2], acc[nt][3]);
    }
}

// =====================================================================
// k_steps: persistent recurrent kernel. grid 128, 256 threads.
// ONE grid barrier per step (after L0); the after-L1 barrier is subsumed
// by the next step's after-L0 barrier (hazard analysis in commit msg).
// =====================================================================
__global__ void __launch_bounds__(256, 1) k_steps(
    const float* __restrict__ enc_c,
    const float* __restrict__ b_ih1, const float* __restrict__ b_hh1,
    float* __restrict__ out) {
    extern __shared__ char sm[];
    const uint32_t smb = smem_u32(sm);
    const int tid = threadIdx.x, lane = tid & 31, warp = tid >> 5;
    const int cta = blockIdx.x, hu0 = cta * UPC;
    const int M0 = (warp & 3) * 16, N0 = (warp >> 2) * 16;

    float* sD  = (float*)(sm + SD_OFF);
    float* sP  = (float*)(sm + SP_OFF);
    float* sc0 = (float*)(sm + SC0_OFF);
    float* sc1 = (float*)(sm + SC1_OFF);
    float* sB1 = (float*)(sm + SB1_OFF);

    for (int i = tid; i < 512; i += 256) {
        int m = i >> 3, u = i & 7;
        sc0[i] = enc_c[m * HH + hu0 + u];
        sc1[i] = enc_c[BB * HH + m * HH + hu0 + u];
    }
    if (tid < 32) {
        int col = (tid >> 3) * HH + hu0 + (tid & 7);
        sB1[tid] = b_ih1[col] + b_hh1[col];
    }
    __syncthreads();

    const __half* gB0h = g_B0h + (size_t)cta * 16 * 2048;
    const __half* gB1h = g_B1h + (size_t)cta * 32 * 2048;

    const int ep_m = tid >> 2, ep_u0 = (tid & 3) * 2;

#pragma unroll 1
    for (int t = 0; t < SS; t++) {
        const int rd = t & 1, wrb = 1 - rd;

        // ================= phase L0 =================
        {
            const __half* gA = g_h0[rd];
            float acc[2][4];
#pragma unroll
            for (int i = 0; i < 2; i++)
#pragma unroll
                for (int j = 0; j < 4; j++) acc[i][j] = 0.0f;

            copy_chunk(smb, 0, tid, gA, 0, gB0h);
            {
                const float* src = g_P0 + ((size_t)t * BB + ep_m) * GG +
                                   (tid & 3) * HH + hu0;
                uint32_t dst = smb + SP_OFF + (uint32_t)tid * 32;
                cpa16(dst, src);
                cpa16(dst + 16, src + 4);
            }
            CP_COMMIT();
            copy_chunk(smb, 1, tid, gA, 64, gB0h + 2048);
            CP_COMMIT();

#pragma unroll 1
            for (int c = 0; c < 16; c++) {
                if (c < 15) cp_wait<1>(); else cp_wait<0>();
                __syncthreads();
                compute_chunk(smb, c % 3, lane, M0, N0, acc);
                if (c + 2 < 16) {
                    copy_chunk(smb, (c + 2) % 3, tid, gA, (c + 2) * 64,
                               gB0h + (size_t)(c + 2) * 2048);
                    CP_COMMIT();
                }
            }
            store_accums(sm, lane, M0, N0, acc);
            __syncthreads();

            const float* sDr = sD + ep_m * 34;
            const float* sPm = sP + ep_m * 32;
            float hv[2];
#pragma unroll
            for (int e = 0; e < 2; e++) {
                int u = ep_u0 + e;
                float gi = sDr[u]      + sPm[u];
                float gf = sDr[8 + u]  + sPm[8 + u];
                float gg = sDr[16 + u] + sPm[16 + u];
                float go = sDr[24 + u] + sPm[24 + u];
                float cn = sigf(gf) * sc0[ep_m * 8 + u] + sigf(gi) * tanhf(gg);
                sc0[ep_m * 8 + u] = cn;
                hv[e] = sigf(go) * tanhf(cn);
            }
            unsigned hp = (unsigned)__half_as_ushort(__float2half(hv[0])) |
                          ((unsigned)__half_as_ushort(__float2half(hv[1])) << 16);
            *reinterpret_cast<unsigned*>(&g_h0[wrb][ep_m * HH + hu0 + ep_u0]) = hp;
        }
        grid_bar(tid, (unsigned)(t + 1));

        // ================= phase L1 =================
        {
            const __half* Ah[2] = { g_h0[wrb], g_h1[rd] };
            float acc[2][4];
#pragma unroll
            for (int i = 0; i < 2; i++)
#pragma unroll
                for (int j = 0; j < 4; j++) acc[i][j] = 0.0f;

            copy_chunk(smb, 0, tid, Ah[0], 0, gB1h);
            CP_COMMIT();
            copy_chunk(smb, 1, tid, Ah[0], 64, gB1h + 2048);
            CP_COMMIT();

#pragma unroll 1
            for (int c = 0; c < 32; c++) {
                if (c < 31) cp_wait<1>(); else cp_wait<0>();
                __syncthreads();
                compute_chunk(smb, c % 3, lane, M0, N0, acc);
                if (c + 2 < 32) {
                    int cn = c + 2, ph = cn >> 4, kb = (cn & 15) * 64;
                    copy_chunk(smb, cn % 3, tid, Ah[ph], kb,
                               gB1h + (size_t)cn * 2048);
                    CP_COMMIT();
                }
            }
            store_accums(sm, lane, M0, N0, acc);
            __syncthreads();

            const float* sDr = sD + ep_m * 34;
            float hv[2];
#pragma unroll
            for (int e = 0; e < 2; e++) {
                int u = ep_u0 + e;
                float gi = sDr[u]      + sB1[u];
                float gf = sDr[8 + u]  + sB1[8 + u];
                float gg = sDr[16 + u] + sB1[16 + u];
                float go = sDr[24 + u] + sB1[24 + u];
                float cn = sigf(gf) * sc1[ep_m * 8 + u] + sigf(gi) * tanhf(gg);
                sc1[ep_m * 8 + u] = cn;
                hv[e] = sigf(go) * tanhf(cn);
            }
            unsigned hp = (unsigned)__half_as_ushort(__float2half(hv[0])) |
                          ((unsigned)__half_as_ushort(__float2half(hv[1])) << 16);
            int hidx = ep_m * HH + hu0 + ep_u0;
            *reinterpret_cast<unsigned*>(&g_h1[wrb][hidx]) = hp;
            *reinterpret_cast<float2*>(out + (size_t)t * BB * HH + hidx) =
                make_float2(hv[0], hv[1]);
        }
        // no barrier here: next step's after-L0 barrier orders h1 for L1(t+1)
    }
}

// =====================================================================
extern "C" void kernel_launch(void* const* d_in, const int* in_sizes, int n_in,
                              void* d_out, int out_size) {
    const int*   tok      = (const int*)d_in[0];
    const int*   src      = (const int*)d_in[1];
    const float* enc_outs = (const float*)d_in[2];
    const float* enc_h    = (const float*)d_in[3];
    const float* enc_c    = (const float*)d_in[4];
    const float* embed    = (const float*)d_in[5];
    const float* W_ih0    = (const float*)d_in[6];
    const float* W_hh0    = (const float*)d_in[7];
    const float* b_ih0    = (const float*)d_in[8];
    const float* b_hh0    = (const float*)d_in[9];
    const float* W_ih1    = (const float*)d_in[10];
    const float* W_hh1    = (const float*)d_in[11];
    const float* b_ih1    = (const float*)d_in[12];
    const float* b_hh1    = (const float*)d_in[13];
    float* out = (float*)d_out;

    cudaFuncSetAttribute(k_steps, cudaFuncAttributeMaxDynamicSharedMemorySize, DYN_SMEM);

    k_static<<<dim3(GG / 256, BB / 8), 256>>>(enc_outs, src, embed, W_ih0, b_ih0, b_hh0);
    k_precompute<<<dim3(SS, GG / 32), 256>>>(tok, embed, W_ih0);
    k_prep<<<dim3(16, NCTA, 3), 256>>>(W_hh0, W_ih1, W_hh1, enc_h);
    k_steps<<<NCTA, 256, DYN_SMEM>>>(enc_c, b_ih1, b_hh1, out);
}

// round 13
// speedup vs baseline: 4.9782x; 1.5958x over previous
#include <cuda_runtime.h>
#include <cuda_bf16.h>
#include <cuda_fp16.h>
#include <math.h>
#include <stdint.h>

#define BB 64
#define SS 256
#define HH 1024
#define EE 512
#define GG 4096
#define NCTA 128
#define UPC 8     // hidden units per CTA (N = 32 gate cols)

// ---- k_steps smem (KC=128): 3 stages of 26112:
//   stage s at s*26112: Ah(64 rows x 272B) | Bh(32 x 272B) at +17408
#define STGSZ 26112
#define SD_OFF  78336   // D tile 64 x 34 f32 = 8704
#define SP_OFF  87040   // P0 prefetch 64 x 32 f32 = 8192
#define SC0_OFF 95232   // c0 state 512 f32
#define SC1_OFF 97280   // c1 state 512 f32
#define SB1_OFF 99328   // layer1 bias 32 f32
#define DYN_STEPS 99456

// ---- k_pre smem: 2 stages of 34816 (A 64x272 | B 64x272 at +17408), tokens after
#define PC_STG 34816
#define PC_TOK 69632
#define DYN_PRE 69888

// -------- device-global scratch --------
__device__ float g_P0[(size_t)SS * BB * GG];
__device__ float g_sp[BB * GG];
__device__ __half g_h0[2][BB * HH];
__device__ __half g_h1[2][BB * HH];
__device__ __align__(16) __half g_emb16[(size_t)32000 * EE];
__device__ __align__(16) __half g_Wx[(size_t)GG * EE];          // W_ih0 x-part fp16
// pre-gathered dense fp16 weight tiles, KC=128: [cta][slot][32n x 128k]
__device__ __align__(16) __half g_B0h[(size_t)NCTA * 8 * 4096];
__device__ __align__(16) __half g_B1h[(size_t)NCTA * 16 * 4096];
// grid barrier state
__device__ unsigned g_bcnt;
__device__ unsigned g_bgen;

union P8 { __half h[8]; uint4 v; };

__device__ __forceinline__ float sigf(float x) { return 1.0f / (1.0f + expf(-x)); }

__device__ __forceinline__ uint32_t smem_u32(const void* p) {
    uint32_t a;
    asm("{ .reg .u64 t; cvta.to.shared.u64 t, %1; cvt.u32.u64 %0, t; }" : "=r"(a) : "l"(p));
    return a;
}
__device__ __forceinline__ void cpa16(uint32_t d, const void* s) {
    asm volatile("cp.async.cg.shared.global [%0], [%1], 16;" :: "r"(d), "l"(s));
}
#define CP_COMMIT() asm volatile("cp.async.commit_group;" ::: "memory")
template<int N> __device__ __forceinline__ void cp_wait() {
    asm volatile("cp.async.wait_group %0;" :: "n"(N) : "memory");
}

__device__ __forceinline__ void ldsm4(uint32_t* r, uint32_t a) {
    asm volatile("ldmatrix.sync.aligned.m8n8.x4.shared.b16 {%0,%1,%2,%3}, [%4];"
                 : "=r"(r[0]), "=r"(r[1]), "=r"(r[2]), "=r"(r[3]) : "r"(a));
}
__device__ __forceinline__ void mma_f16(float* d, const uint32_t* a, uint32_t b0, uint32_t b1) {
    asm volatile(
        "mma.sync.aligned.m16n8k16.row.col.f32.f16.f16.f32 "
        "{%0,%1,%2,%3}, {%4,%5,%6,%7}, {%8,%9}, {%0,%1,%2,%3};"
        : "+f"(d[0]), "+f"(d[1]), "+f"(d[2]), "+f"(d[3])
        : "r"(a[0]), "r"(a[1]), "r"(a[2]), "r"(a[3]), "r"(b0), "r"(b1));
}

// grid-wide barrier: all 128 CTAs co-resident (1/SM on 148 SMs).
__device__ __forceinline__ void grid_bar(int tid, unsigned gen) {
    __threadfence();
    __syncthreads();
    if (tid == 0) {
        if (atomicAdd(&g_bcnt, 1u) == NCTA - 1) {
            atomicExch(&g_bcnt, 0u);
            __threadfence();
            atomicExch(&g_bgen, gen);
        } else {
            while (atomicOr(&g_bgen, 0u) < gen) {}
            __threadfence();
        }
    }
    __syncthreads();
}

// =====================================================================
// k_emb16: embed fp32 -> fp16 (one-time, ~32MB write)
// =====================================================================
__global__ void __launch_bounds__(256) k_emb16(const float* __restrict__ embed) {
    size_t i = ((size_t)blockIdx.x * 256 + threadIdx.x) * 8;
    float x[8];
    *reinterpret_cast<float4*>(x)     = *reinterpret_cast<const float4*>(embed + i);
    *reinterpret_cast<float4*>(x + 4) = *reinterpret_cast<const float4*>(embed + i + 4);
    P8 p;
#pragma unroll
    for (int u = 0; u < 8; u++) p.h[u] = __float2half(x[u]);
    *reinterpret_cast<uint4*>(g_emb16 + i) = p.v;
}

// =====================================================================
// k_static (proven, unchanged)
// =====================================================================
__global__ void __launch_bounds__(256) k_static(
    const float* __restrict__ enc_outs, const int* __restrict__ src_lang,
    const float* __restrict__ embed, const float* __restrict__ W0,
    const float* __restrict__ b_ih0, const float* __restrict__ b_hh0) {
    __shared__ float sC[8][EE];
    __shared__ float sL[8][EE];
    const int tid = threadIdx.x;
    const int b0 = blockIdx.y * 8;
    for (int i = tid; i < 8 * EE; i += 256) {
        int b = i >> 9, k = i & (EE - 1);
        sC[b][k] = enc_outs[((size_t)(b0 + b) * 128 + 127) * EE + k];
        sL[b][k] = embed[(size_t)src_lang[b0 + b] * EE + k];
    }
    __syncthreads();
    const int g = blockIdx.x * 256 + tid;
    const float* wr = W0 + (size_t)g * 1536;
    float acc[8];
#pragma unroll
    for (int i = 0; i < 8; i++) acc[i] = 0.0f;
    for (int k = 0; k < EE; k += 4) {
        float4 wc = *reinterpret_cast<const float4*>(wr + 512 + k);
        float4 wl = *reinterpret_cast<const float4*>(wr + 1024 + k);
#pragma unroll
        for (int b = 0; b < 8; b++) {
            float4 c4 = *reinterpret_cast<const float4*>(&sC[b][k]);
            float4 l4 = *reinterpret_cast<const float4*>(&sL[b][k]);
            acc[b] += wc.x * c4.x + wc.y * c4.y + wc.z * c4.z + wc.w * c4.w;
            acc[b] += wl.x * l4.x + wl.y * l4.y + wl.z * l4.z + wl.w * l4.w;
        }
    }
    float bias = b_ih0[g] + b_hh0[g];
#pragma unroll
    for (int b = 0; b < 8; b++) g_sp[(b0 + b) * GG + g] = acc[b] + bias;
}

// =====================================================================
// k_prep: grid (8, NCTA, 4).
//  z=0: W_hh0 -> g_B0h slots [0,8)   (+ h-init on flat<256, barrier reset)
//  z=1: W_ih1 -> g_B1h slots [0,8)
//  z=2: W_hh1 -> g_B1h slots [8,16)
//  z=3: W_ih0 x-part -> g_Wx dense fp16 (flat block covers 4 rows)
// =====================================================================
__global__ void __launch_bounds__(256) k_prep(
    const float* __restrict__ W_hh0, const float* __restrict__ W_ih1,
    const float* __restrict__ W_hh1, const float* __restrict__ W_ih0,
    const float* __restrict__ enc_h) {
    const int c = blockIdx.x, cta = blockIdx.y, which = blockIdx.z, tid = threadIdx.x;

    if (which == 3) {
        int flat = cta * 8 + c;                    // 0..1023
        int row = flat * 4 + (tid >> 6);           // 4096 rows
        int col = (tid & 63) * 8;                  // 512 k
        const float* s = W_ih0 + (size_t)row * 1536 + col;
        float x[8];
        *reinterpret_cast<float4*>(x)     = *reinterpret_cast<const float4*>(s);
        *reinterpret_cast<float4*>(x + 4) = *reinterpret_cast<const float4*>(s + 4);
        P8 p;
#pragma unroll
        for (int u = 0; u < 8; u++) p.h[u] = __float2half(x[u]);
        *reinterpret_cast<uint4*>(g_Wx + (size_t)row * EE + col) = p.v;
        return;
    }

    if (which == 0) {
        int flat = cta * 8 + c;
        if (flat == 0 && tid == 0) { g_bcnt = 0; g_bgen = 0; }
        if (flat < 256) {
            int i = flat * 256 + tid;
            const int n = BB * HH;
            g_h0[0][i] = __float2half(enc_h[i]);
            g_h1[0][i] = __float2half(enc_h[n + i]);
        }
    }

    const float* W = (which == 0) ? W_hh0 : (which == 1) ? W_ih1 : W_hh1;
    const int nloc = tid >> 3, ks = (tid & 7) * 16;
    const int grow = (nloc >> 3) * HH + cta * UPC + (nloc & 7);
    const float* s = W + (size_t)grow * HH + c * 128 + ks;
    float x[16];
#pragma unroll
    for (int i = 0; i < 4; i++)
        *reinterpret_cast<float4*>(x + 4 * i) = *reinterpret_cast<const float4*>(s + 4 * i);
    P8 p0, p1;
#pragma unroll
    for (int u = 0; u < 8; u++) { p0.h[u] = __float2half(x[u]); p1.h[u] = __float2half(x[8 + u]); }
    __half* Gh;
    size_t base;
    if (which == 0) { Gh = g_B0h; base = ((size_t)cta * 8 + c) * 4096; }
    else { Gh = g_B1h; base = ((size_t)cta * 16 + (which == 2 ? 8 : 0) + c) * 4096; }
    *reinterpret_cast<uint4*>(Gh + base + (size_t)nloc * 128 + ks)     = p0.v;
    *reinterpret_cast<uint4*>(Gh + base + (size_t)nloc * 128 + ks + 8) = p1.v;
}

// =====================================================================
// k_pre: HMMA input-gate precompute.
// grid (SS, 64): t = bx, 64-gate tile = by. M=64 x N=64, K=512 (4 chunks of 128).
// =====================================================================
__global__ void __launch_bounds__(256) k_pre(const int* __restrict__ tokens) {
    extern __shared__ char sm[];
    const uint32_t smb = smem_u32(sm);
    const int tid = threadIdx.x, lane = tid & 31, warp = tid >> 5;
    const int t = blockIdx.x, n0 = blockIdx.y;
    const int M0 = (warp & 3) * 16, N0 = (warp >> 2) * 32;
    int* sTok = (int*)(sm + PC_TOK);

    if (tid < 64) sTok[tid] = tokens[tid * SS + t];
    __syncthreads();

    float acc[4][4];
#pragma unroll
    for (int i = 0; i < 4; i++)
#pragma unroll
        for (int j = 0; j < 4; j++) acc[i][j] = 0.0f;

    const __half* wb = g_Wx + (size_t)n0 * 64 * EE;

    // 2-stage pipeline, 4 chunks of k=128
#pragma unroll 1
    for (int pre = 0; pre < 2; pre++) {
        const uint32_t sb = smb + pre * PC_STG;
        int kbase = pre * 128;
#pragma unroll
        for (int i = tid; i < 1024; i += 256) {
            int row = i >> 4, s = i & 15;
            uint32_t so = (uint32_t)row * 272 + (s << 4);
            cpa16(sb + so, (const char*)(g_emb16 + (size_t)sTok[row] * EE + kbase) + (s << 4));
            cpa16(sb + 17408 + so, (const char*)(wb + (size_t)row * EE + kbase) + (s << 4));
        }
        CP_COMMIT();
    }

#pragma unroll 1
    for (int c = 0; c < 4; c++) {
        if (c < 3) cp_wait<1>(); else cp_wait<0>();
        __syncthreads();
        const uint32_t sb = smb + (c & 1) * PC_STG;
        const uint32_t aoff = (uint32_t)(M0 + (lane & 15)) * 272 + ((lane >> 4) << 4);
        const uint32_t boff = (uint32_t)(N0 + (((lane >> 4) & 1) << 3) + (lane & 7)) * 272 +
                              (((lane >> 3) & 1) << 4);
#pragma unroll
        for (int ksi = 0; ksi < 8; ksi++) {
            const uint32_t kb = ksi << 5;
            uint32_t ah[4], bh[8];
            ldsm4(ah, sb + aoff + kb);
            ldsm4(bh, sb + 17408 + boff + kb);
            ldsm4(bh + 4, sb + 17408 + boff + 4352 + kb);
#pragma unroll
            for (int nt = 0; nt < 4; nt++)
                mma_f16(acc[nt], ah, bh[2 * nt], bh[2 * nt + 1]);
        }
        __syncthreads();
        if (c + 2 < 4) {
            const uint32_t sb2 = smb + ((c + 2) & 1) * PC_STG;
            int kbase = (c + 2) * 128;
#pragma unroll
            for (int i = tid; i < 1024; i += 256) {
                int row = i >> 4, s = i & 15;
                uint32_t so = (uint32_t)row * 272 + (s << 4);
                cpa16(sb2 + so, (const char*)(g_emb16 + (size_t)sTok[row] * EE + kbase) + (s << 4));
                cpa16(sb2 + 17408 + so, (const char*)(wb + (size_t)row * EE + kbase) + (s << 4));
            }
            CP_COMMIT();
        }
    }

    // epilogue: add static part, write P0
    const int r0 = M0 + (lane >> 2);
#pragma unroll
    for (int nt = 0; nt < 4; nt++) {
        int col = n0 * 64 + N0 + nt * 8 + (lane & 3) * 2;
        size_t o0 = ((size_t)t * BB + r0) * GG + col;
        size_t o1 = ((size_t)t * BB + r0 + 8) * GG + col;
        const float* sp0 = g_sp + r0 * GG + col;
        const float* sp1 = g_sp + (r0 + 8) * GG + col;
        *reinterpret_cast<float2*>(g_P0 + o0) =
            make_float2(acc[nt][0] + sp0[0], acc[nt][1] + sp0[1]);
        *reinterpret_cast<float2*>(g_P0 + o1) =
            make_float2(acc[nt][2] + sp1[0], acc[nt][3] + sp1[1]);
    }
}

// =====================================================================
// persistent step-kernel building blocks (M=64, N=32; warp tile 16x16; KC=128)
// =====================================================================
__device__ __forceinline__ void copy_chunk(
    uint32_t smb, int stage, int tid,
    const __half* gA, int kbase, const __half* gBh) {
    const uint32_t sb = smb + stage * STGSZ;
#pragma unroll
    for (int i = tid; i < 1024; i += 256) {
        int row = i >> 4, s = i & 15;
        uint32_t so = (uint32_t)row * 272 + (s << 4);
        cpa16(sb + so, (const char*)(gA + (size_t)row * HH + kbase) + (s << 4));
    }
#pragma unroll
    for (int i = tid; i < 512; i += 256) {
        int row = i >> 4, s = i & 15;
        uint32_t so = (uint32_t)row * 272 + (s << 4);
        cpa16(sb + 17408 + so, (const char*)gBh + ((size_t)i << 4));
    }
}

__device__ __forceinline__ void compute_chunk(uint32_t smb, int stage, int lane,
                                              int M0, int N0, float acc[2][4]) {
    const uint32_t sb = smb + stage * STGSZ;
    const uint32_t aoff = (uint32_t)(M0 + (lane & 15)) * 272 + ((lane >> 4) << 4);
    const uint32_t boff = (uint32_t)(N0 + (((lane >> 4) & 1) << 3) + (lane & 7)) * 272 +
                          (((lane >> 3) & 1) << 4);
#pragma unroll
    for (int ksi = 0; ksi < 8; ksi++) {
        const uint32_t kb = ksi << 5;
        uint32_t ah[4], bh[4];
        ldsm4(ah, sb + aoff + kb);
        ldsm4(bh, sb + 17408 + boff + kb);
#pragma unroll
        for (int nt = 0; nt < 2; nt++)
            mma_f16(acc[nt], ah, bh[2 * nt], bh[2 * nt + 1]);
    }
}

__device__ __forceinline__ void store_accums(char* sm, int lane, int M0, int N0,
                                             float acc[2][4]) {
    float* sD = (float*)(sm + SD_OFF);
    int r0 = M0 + (lane >> 2);
#pragma unroll
    for (int nt = 0; nt < 2; nt++) {
        int col = N0 + nt * 8 + (lane & 3) * 2;
        *reinterpret_cast<float2*>(&sD[r0 * 34 + col]) = make_float2(acc[nt][0], acc[nt][1]);
        *reinterpret_cast<float2*>(&sD[(r0 + 8) * 34 + col]) = make_float2(acc[nt][2], acc[nt][3]);
    }
}

// =====================================================================
// k_steps: persistent recurrent kernel. grid 128, 256 threads.
// ONE grid barrier per step (after L0).
// =====================================================================
__global__ void __launch_bounds__(256, 1) k_steps(
    const float* __restrict__ enc_c,
    const float* __restrict__ b_ih1, const float* __restrict__ b_hh1,
    float* __restrict__ out) {
    extern __shared__ char sm[];
    const uint32_t smb = smem_u32(sm);
    const int tid = threadIdx.x, lane = tid & 31, warp = tid >> 5;
    const int cta = blockIdx.x, hu0 = cta * UPC;
    const int M0 = (warp & 3) * 16, N0 = (warp >> 2) * 16;

    float* sD  = (float*)(sm + SD_OFF);
    float* sP  = (float*)(sm + SP_OFF);
    float* sc0 = (float*)(sm + SC0_OFF);
    float* sc1 = (float*)(sm + SC1_OFF);
    float* sB1 = (float*)(sm + SB1_OFF);

    for (int i = tid; i < 512; i += 256) {
        int m = i >> 3, u = i & 7;
        sc0[i] = enc_c[m * HH + hu0 + u];
        sc1[i] = enc_c[BB * HH + m * HH + hu0 + u];
    }
    if (tid < 32) {
        int col = (tid >> 3) * HH + hu0 + (tid & 7);
        sB1[tid] = b_ih1[col] + b_hh1[col];
    }
    __syncthreads();

    const __half* gB0h = g_B0h + (size_t)cta * 8 * 4096;
    const __half* gB1h = g_B1h + (size_t)cta * 16 * 4096;

    const int ep_m = tid >> 2, ep_u0 = (tid & 3) * 2;

#pragma unroll 1
    for (int t = 0; t < SS; t++) {
        const int rd = t & 1, wrb = 1 - rd;

        // ================= phase L0 (8 chunks of k=128) =================
        {
            const __half* gA = g_h0[rd];
            float acc[2][4];
#pragma unroll
            for (int i = 0; i < 2; i++)
#pragma unroll
                for (int j = 0; j < 4; j++) acc[i][j] = 0.0f;

            copy_chunk(smb, 0, tid, gA, 0, gB0h);
            {
                const float* src = g_P0 + ((size_t)t * BB + ep_m) * GG +
                                   (tid & 3) * HH + hu0;
                uint32_t dst = smb + SP_OFF + (uint32_t)tid * 32;
                cpa16(dst, src);
                cpa16(dst + 16, src + 4);
            }
            CP_COMMIT();
            copy_chunk(smb, 1, tid, gA, 128, gB0h + 4096);
            CP_COMMIT();

#pragma unroll 1
            for (int c = 0; c < 8; c++) {
                if (c < 7) cp_wait<1>(); else cp_wait<0>();
                __syncthreads();
                compute_chunk(smb, c % 3, lane, M0, N0, acc);
                if (c + 2 < 8) {
                    copy_chunk(smb, (c + 2) % 3, tid, gA, (c + 2) * 128,
                               gB0h + (size_t)(c + 2) * 4096);
                    CP_COMMIT();
                }
            }
            store_accums(sm, lane, M0, N0, acc);
            __syncthreads();

            const float* sDr = sD + ep_m * 34;
            const float* sPm = sP + ep_m * 32;
            float hv[2];
#pragma unroll
            for (int e = 0; e < 2; e++) {
                int u = ep_u0 + e;
                float gi = sDr[u]      + sPm[u];
                float gf = sDr[8 + u]  + sPm[8 + u];
                float gg = sDr[16 + u] + sPm[16 + u];
                float go = sDr[24 + u] + sPm[24 + u];
                float cn = sigf(gf) * sc0[ep_m * 8 + u] + sigf(gi) * tanhf(gg);
                sc0[ep_m * 8 + u] = cn;
                hv[e] = sigf(go) * tanhf(cn);
            }
            unsigned hp = (unsigned)__half_as_ushort(__float2half(hv[0])) |
                          ((unsigned)__half_as_ushort(__float2half(hv[1])) << 16);
            *reinterpret_cast<unsigned*>(&g_h0[wrb][ep_m * HH + hu0 + ep_u0]) = hp;
        }
        grid_bar(tid, (unsigned)(t + 1));

        // ================= phase L1 (16 chunks of k=128) =================
        {
            const __half* Ah[2] = { g_h0[wrb], g_h1[rd] };
            float acc[2][4];
#pragma unroll
            for (int i = 0; i < 2; i++)
#pragma unroll
                for (int j = 0; j < 4; j++) acc[i][j] = 0.0f;

            copy_chunk(smb, 0, tid, Ah[0], 0, gB1h);
            CP_COMMIT();
            copy_chunk(smb, 1, tid, Ah[0], 128, gB1h + 4096);
            CP_COMMIT();

#pragma unroll 1
            for (int c = 0; c < 16; c++) {
                if (c < 15) cp_wait<1>(); else cp_wait<0>();
                __syncthreads();
                compute_chunk(smb, c % 3, lane, M0, N0, acc);
                if (c + 2 < 16) {
                    int cn = c + 2, ph = cn >> 3, kb = (cn & 7) * 128;
                    copy_chunk(smb, cn % 3, tid, Ah[ph], kb,
                               gB1h + (size_t)cn * 4096);
                    CP_COMMIT();
                }
            }
            store_accums(sm, lane, M0, N0, acc);
            __syncthreads();

            const float* sDr = sD + ep_m * 34;
            float hv[2];
#pragma unroll
            for (int e = 0; e < 2; e++) {
                int u = ep_u0 + e;
                float gi = sDr[u]      + sB1[u];
                float gf = sDr[8 + u]  + sB1[8 + u];
                float gg = sDr[16 + u] + sB1[16 + u];
                float go = sDr[24 + u] + sB1[24 + u];
                float cn = sigf(gf) * sc1[ep_m * 8 + u] + sigf(gi) * tanhf(gg);
                sc1[ep_m * 8 + u] = cn;
                hv[e] = sigf(go) * tanhf(cn);
            }
            unsigned hp = (unsigned)__half_as_ushort(__float2half(hv[0])) |
                          ((unsigned)__half_as_ushort(__float2half(hv[1])) << 16);
            int hidx = ep_m * HH + hu0 + ep_u0;
            *reinterpret_cast<unsigned*>(&g_h1[wrb][hidx]) = hp;
            *reinterpret_cast<float2*>(out + (size_t)t * BB * HH + hidx) =
                make_float2(hv[0], hv[1]);
        }
        // no barrier: next step's after-L0 barrier orders h1 for L1(t+1)
    }
}

// =====================================================================
extern "C" void kernel_launch(void* const* d_in, const int* in_sizes, int n_in,
                              void* d_out, int out_size) {
    const int*   tok      = (const int*)d_in[0];
    const int*   src      = (const int*)d_in[1];
    const float* enc_outs = (const float*)d_in[2];
    const float* enc_h    = (const float*)d_in[3];
    const float* enc_c    = (const float*)d_in[4];
    const float* embed    = (const float*)d_in[5];
    const float* W_ih0    = (const float*)d_in[6];
    const float* W_hh0    = (const float*)d_in[7];
    const float* b_ih0    = (const float*)d_in[8];
    const float* b_hh0    = (const float*)d_in[9];
    const float* W_ih1    = (const float*)d_in[10];
    const float* W_hh1    = (const float*)d_in[11];
    const float* b_ih1    = (const float*)d_in[12];
    const float* b_hh1    = (const float*)d_in[13];
    float* out = (float*)d_out;

    cudaFuncSetAttribute(k_steps, cudaFuncAttributeMaxDynamicSharedMemorySize, DYN_STEPS);
    cudaFuncSetAttribute(k_pre, cudaFuncAttributeMaxDynamicSharedMemorySize, DYN_PRE);

    k_emb16<<<32000 * EE / 2048, 256>>>(embed);
    k_static<<<dim3(GG / 256, BB / 8), 256>>>(enc_outs, src, embed, W_ih0, b_ih0, b_hh0);
    k_prep<<<dim3(8, NCTA, 4), 256>>>(W_hh0, W_ih1, W_hh1, W_ih0, enc_h);
    k_pre<<<dim3(SS, 64), 256, DYN_PRE>>>(tok);
    k_steps<<<NCTA, 256, DYN_STEPS>>>(enc_c, b_ih1, b_hh1, out);
}

// round 14
// speedup vs baseline: 5.5614x; 1.1171x over previous
#include <cuda_runtime.h>
#include <cuda_bf16.h>
#include <cuda_fp16.h>
#include <math.h>
#include <stdint.h>

#define BB 64
#define SS 256
#define HH 1024
#define EE 512
#define GG 4096
#define NCTA 128
#define UPC 8     // hidden units per CTA (N = 32 gate cols)

// ---- k_steps smem (KC=128): 6 stages (3 per kgroup) of 26112:
//   stage s at s*26112: Ah(64 rows x 272B) | Bh(32 x 272B) at +17408
#define STGSZ 26112
#define SD_OFF  156672  // 2 partial D tiles, each 64 x 34 f32 = 8704 B
#define SP_OFF  174080  // P0 prefetch 64 x 32 f32 = 8192
#define SC0_OFF 182272  // c0 state 512 f32
#define SC1_OFF 184320  // c1 state 512 f32
#define SB1_OFF 186368  // layer1 bias 32 f32
#define DYN_STEPS 186496

// ---- k_pre smem: 2 stages of 34816 (A 64x272 | B 64x272 at +17408), tokens after
#define PC_STG 34816
#define PC_TOK 69632
#define DYN_PRE 69888

// -------- device-global scratch --------
__device__ float g_P0[(size_t)SS * BB * GG];
__device__ float g_sp[BB * GG];
__device__ __half g_h0[2][BB * HH];
__device__ __half g_h1[2][BB * HH];
__device__ __align__(16) __half g_emb16[(size_t)32000 * EE];
__device__ __align__(16) __half g_Wx[(size_t)GG * EE];          // W_ih0 x-part fp16
// pre-gathered dense fp16 weight tiles, KC=128: [cta][slot][32n x 128k]
__device__ __align__(16) __half g_B0h[(size_t)NCTA * 8 * 4096];
__device__ __align__(16) __half g_B1h[(size_t)NCTA * 16 * 4096];
// grid barrier state
__device__ unsigned g_bcnt;
__device__ unsigned g_bgen;

union P8 { __half h[8]; uint4 v; };

__device__ __forceinline__ float sigf(float x) { return 1.0f / (1.0f + expf(-x)); }

__device__ __forceinline__ uint32_t smem_u32(const void* p) {
    uint32_t a;
    asm("{ .reg .u64 t; cvta.to.shared.u64 t, %1; cvt.u32.u64 %0, t; }" : "=r"(a) : "l"(p));
    return a;
}
__device__ __forceinline__ void cpa16(uint32_t d, const void* s) {
    asm volatile("cp.async.cg.shared.global [%0], [%1], 16;" :: "r"(d), "l"(s));
}
#define CP_COMMIT() asm volatile("cp.async.commit_group;" ::: "memory")
template<int N> __device__ __forceinline__ void cp_wait() {
    asm volatile("cp.async.wait_group %0;" :: "n"(N) : "memory");
}
__device__ __forceinline__ void bar_kg(int kg) {
    asm volatile("bar.sync %0, 256;" :: "r"(kg + 1) : "memory");
}

__device__ __forceinline__ void ldsm4(uint32_t* r, uint32_t a) {
    asm volatile("ldmatrix.sync.aligned.m8n8.x4.shared.b16 {%0,%1,%2,%3}, [%4];"
                 : "=r"(r[0]), "=r"(r[1]), "=r"(r[2]), "=r"(r[3]) : "r"(a));
}
__device__ __forceinline__ void mma_f16(float* d, const uint32_t* a, uint32_t b0, uint32_t b1) {
    asm volatile(
        "mma.sync.aligned.m16n8k16.row.col.f32.f16.f16.f32 "
        "{%0,%1,%2,%3}, {%4,%5,%6,%7}, {%8,%9}, {%0,%1,%2,%3};"
        : "+f"(d[0]), "+f"(d[1]), "+f"(d[2]), "+f"(d[3])
        : "r"(a[0]), "r"(a[1]), "r"(a[2]), "r"(a[3]), "r"(b0), "r"(b1));
}

// grid-wide barrier: all 128 CTAs co-resident (1/SM on 148 SMs).
__device__ __forceinline__ void grid_bar(int tid, unsigned gen) {
    __threadfence();
    __syncthreads();
    if (tid == 0) {
        if (atomicAdd(&g_bcnt, 1u) == NCTA - 1) {
            atomicExch(&g_bcnt, 0u);
            __threadfence();
            atomicExch(&g_bgen, gen);
        } else {
            while (atomicOr(&g_bgen, 0u) < gen) {}
            __threadfence();
        }
    }
    __syncthreads();
}

// =====================================================================
// k_emb16: embed fp32 -> fp16 (one-time)
// =====================================================================
__global__ void __launch_bounds__(256) k_emb16(const float* __restrict__ embed) {
    size_t i = ((size_t)blockIdx.x * 256 + threadIdx.x) * 8;
    float x[8];
    *reinterpret_cast<float4*>(x)     = *reinterpret_cast<const float4*>(embed + i);
    *reinterpret_cast<float4*>(x + 4) = *reinterpret_cast<const float4*>(embed + i + 4);
    P8 p;
#pragma unroll
    for (int u = 0; u < 8; u++) p.h[u] = __float2half(x[u]);
    *reinterpret_cast<uint4*>(g_emb16 + i) = p.v;
}

// =====================================================================
// k_static (proven, unchanged)
// =====================================================================
__global__ void __launch_bounds__(256) k_static(
    const float* __restrict__ enc_outs, const int* __restrict__ src_lang,
    const float* __restrict__ embed, const float* __restrict__ W0,
    const float* __restrict__ b_ih0, const float* __restrict__ b_hh0) {
    __shared__ float sC[8][EE];
    __shared__ float sL[8][EE];
    const int tid = threadIdx.x;
    const int b0 = blockIdx.y * 8;
    for (int i = tid; i < 8 * EE; i += 256) {
        int b = i >> 9, k = i & (EE - 1);
        sC[b][k] = enc_outs[((size_t)(b0 + b) * 128 + 127) * EE + k];
        sL[b][k] = embed[(size_t)src_lang[b0 + b] * EE + k];
    }
    __syncthreads();
    const int g = blockIdx.x * 256 + tid;
    const float* wr = W0 + (size_t)g * 1536;
    float acc[8];
#pragma unroll
    for (int i = 0; i < 8; i++) acc[i] = 0.0f;
    for (int k = 0; k < EE; k += 4) {
        float4 wc = *reinterpret_cast<const float4*>(wr + 512 + k);
        float4 wl = *reinterpret_cast<const float4*>(wr + 1024 + k);
#pragma unroll
        for (int b = 0; b < 8; b++) {
            float4 c4 = *reinterpret_cast<const float4*>(&sC[b][k]);
            float4 l4 = *reinterpret_cast<const float4*>(&sL[b][k]);
            acc[b] += wc.x * c4.x + wc.y * c4.y + wc.z * c4.z + wc.w * c4.w;
            acc[b] += wl.x * l4.x + wl.y * l4.y + wl.z * l4.z + wl.w * l4.w;
        }
    }
    float bias = b_ih0[g] + b_hh0[g];
#pragma unroll
    for (int b = 0; b < 8; b++) g_sp[(b0 + b) * GG + g] = acc[b] + bias;
}

// =====================================================================
// k_prep: grid (8, NCTA, 4)  (unchanged from R13)
// =====================================================================
__global__ void __launch_bounds__(256) k_prep(
    const float* __restrict__ W_hh0, const float* __restrict__ W_ih1,
    const float* __restrict__ W_hh1, const float* __restrict__ W_ih0,
    const float* __restrict__ enc_h) {
    const int c = blockIdx.x, cta = blockIdx.y, which = blockIdx.z, tid = threadIdx.x;

    if (which == 3) {
        int flat = cta * 8 + c;
        int row = flat * 4 + (tid >> 6);
        int col = (tid & 63) * 8;
        const float* s = W_ih0 + (size_t)row * 1536 + col;
        float x[8];
        *reinterpret_cast<float4*>(x)     = *reinterpret_cast<const float4*>(s);
        *reinterpret_cast<float4*>(x + 4) = *reinterpret_cast<const float4*>(s + 4);
        P8 p;
#pragma unroll
        for (int u = 0; u < 8; u++) p.h[u] = __float2half(x[u]);
        *reinterpret_cast<uint4*>(g_Wx + (size_t)row * EE + col) = p.v;
        return;
    }

    if (which == 0) {
        int flat = cta * 8 + c;
        if (flat == 0 && tid == 0) { g_bcnt = 0; g_bgen = 0; }
        if (flat < 256) {
            int i = flat * 256 + tid;
            const int n = BB * HH;
            g_h0[0][i] = __float2half(enc_h[i]);
            g_h1[0][i] = __float2half(enc_h[n + i]);
        }
    }

    const float* W = (which == 0) ? W_hh0 : (which == 1) ? W_ih1 : W_hh1;
    const int nloc = tid >> 3, ks = (tid & 7) * 16;
    const int grow = (nloc >> 3) * HH + cta * UPC + (nloc & 7);
    const float* s = W + (size_t)grow * HH + c * 128 + ks;
    float x[16];
#pragma unroll
    for (int i = 0; i < 4; i++)
        *reinterpret_cast<float4*>(x + 4 * i) = *reinterpret_cast<const float4*>(s + 4 * i);
    P8 p0, p1;
#pragma unroll
    for (int u = 0; u < 8; u++) { p0.h[u] = __float2half(x[u]); p1.h[u] = __float2half(x[8 + u]); }
    __half* Gh;
    size_t base;
    if (which == 0) { Gh = g_B0h; base = ((size_t)cta * 8 + c) * 4096; }
    else { Gh = g_B1h; base = ((size_t)cta * 16 + (which == 2 ? 8 : 0) + c) * 4096; }
    *reinterpret_cast<uint4*>(Gh + base + (size_t)nloc * 128 + ks)     = p0.v;
    *reinterpret_cast<uint4*>(Gh + base + (size_t)nloc * 128 + ks + 8) = p1.v;
}

// =====================================================================
// k_pre: HMMA input-gate precompute (proven R13, unchanged)
// =====================================================================
__global__ void __launch_bounds__(256) k_pre(const int* __restrict__ tokens) {
    extern __shared__ char sm[];
    const uint32_t smb = smem_u32(sm);
    const int tid = threadIdx.x, lane = tid & 31, warp = tid >> 5;
    const int t = blockIdx.x, n0 = blockIdx.y;
    const int M0 = (warp & 3) * 16, N0 = (warp >> 2) * 32;
    int* sTok = (int*)(sm + PC_TOK);

    if (tid < 64) sTok[tid] = tokens[tid * SS + t];
    __syncthreads();

    float acc[4][4];
#pragma unroll
    for (int i = 0; i < 4; i++)
#pragma unroll
        for (int j = 0; j < 4; j++) acc[i][j] = 0.0f;

    const __half* wb = g_Wx + (size_t)n0 * 64 * EE;

#pragma unroll 1
    for (int pre = 0; pre < 2; pre++) {
        const uint32_t sb = smb + pre * PC_STG;
        int kbase = pre * 128;
#pragma unroll
        for (int i = tid; i < 1024; i += 256) {
            int row = i >> 4, s = i & 15;
            uint32_t so = (uint32_t)row * 272 + (s << 4);
            cpa16(sb + so, (const char*)(g_emb16 + (size_t)sTok[row] * EE + kbase) + (s << 4));
            cpa16(sb + 17408 + so, (const char*)(wb + (size_t)row * EE + kbase) + (s << 4));
        }
        CP_COMMIT();
    }

#pragma unroll 1
    for (int c = 0; c < 4; c++) {
        if (c < 3) cp_wait<1>(); else cp_wait<0>();
        __syncthreads();
        const uint32_t sb = smb + (c & 1) * PC_STG;
        const uint32_t aoff = (uint32_t)(M0 + (lane & 15)) * 272 + ((lane >> 4) << 4);
        const uint32_t boff = (uint32_t)(N0 + (((lane >> 4) & 1) << 3) + (lane & 7)) * 272 +
                              (((lane >> 3) & 1) << 4);
#pragma unroll
        for (int ksi = 0; ksi < 8; ksi++) {
            const uint32_t kb = ksi << 5;
            uint32_t ah[4], bh[8];
            ldsm4(ah, sb + aoff + kb);
            ldsm4(bh, sb + 17408 + boff + kb);
            ldsm4(bh + 4, sb + 17408 + boff + 4352 + kb);
#pragma unroll
            for (int nt = 0; nt < 4; nt++)
                mma_f16(acc[nt], ah, bh[2 * nt], bh[2 * nt + 1]);
        }
        __syncthreads();
        if (c + 2 < 4) {
            const uint32_t sb2 = smb + ((c + 2) & 1) * PC_STG;
            int kbase = (c + 2) * 128;
#pragma unroll
            for (int i = tid; i < 1024; i += 256) {
                int row = i >> 4, s = i & 15;
                uint32_t so = (uint32_t)row * 272 + (s << 4);
                cpa16(sb2 + so, (const char*)(g_emb16 + (size_t)sTok[row] * EE + kbase) + (s << 4));
                cpa16(sb2 + 17408 + so, (const char*)(wb + (size_t)row * EE + kbase) + (s << 4));
            }
            CP_COMMIT();
        }
    }

    const int r0 = M0 + (lane >> 2);
#pragma unroll
    for (int nt = 0; nt < 4; nt++) {
        int col = n0 * 64 + N0 + nt * 8 + (lane & 3) * 2;
        size_t o0 = ((size_t)t * BB + r0) * GG + col;
        size_t o1 = ((size_t)t * BB + r0 + 8) * GG + col;
        const float* sp0 = g_sp + r0 * GG + col;
        const float* sp1 = g_sp + (r0 + 8) * GG + col;
        *reinterpret_cast<float2*>(g_P0 + o0) =
            make_float2(acc[nt][0] + sp0[0], acc[nt][1] + sp0[1]);
        *reinterpret_cast<float2*>(g_P0 + o1) =
            make_float2(acc[nt][2] + sp1[0], acc[nt][3] + sp1[1]);
    }
}

// =====================================================================
// k_steps building blocks (M=64, N=32; warp tile 16x16; KC=128)
// =====================================================================
__device__ __forceinline__ void copy_chunk(
    uint32_t smb, int stage, int ktid,
    const __half* gA, int kbase, const __half* gBh) {
    const uint32_t sb = smb + stage * STGSZ;
#pragma unroll
    for (int i = ktid; i < 1024; i += 256) {
        int row = i >> 4, s = i & 15;
        uint32_t so = (uint32_t)row * 272 + (s << 4);
        cpa16(sb + so, (const char*)(gA + (size_t)row * HH + kbase) + (s << 4));
    }
#pragma unroll
    for (int i = ktid; i < 512; i += 256) {
        int row = i >> 4, s = i & 15;
        uint32_t so = (uint32_t)row * 272 + (s << 4);
        cpa16(sb + 17408 + so, (const char*)gBh + ((size_t)i << 4));
    }
}

__device__ __forceinline__ void compute_chunk(uint32_t smb, int stage, int lane,
                                              int M0, int N0, float acc[2][4]) {
    const uint32_t sb = smb + stage * STGSZ;
    const uint32_t aoff = (uint32_t)(M0 + (lane & 15)) * 272 + ((lane >> 4) << 4);
    const uint32_t boff = (uint32_t)(N0 + (((lane >> 4) & 1) << 3) + (lane & 7)) * 272 +
                          (((lane >> 3) & 1) << 4);
#pragma unroll
    for (int ksi = 0; ksi < 8; ksi++) {
        const uint32_t kb = ksi << 5;
        uint32_t ah[4], bh[4];
        ldsm4(ah, sb + aoff + kb);
        ldsm4(bh, sb + 17408 + boff + kb);
#pragma unroll
        for (int nt = 0; nt < 2; nt++)
            mma_f16(acc[nt], ah, bh[2 * nt], bh[2 * nt + 1]);
    }
}

__device__ __forceinline__ void store_accums(char* sm, int kg, int lane, int M0, int N0,
                                             float acc[2][4]) {
    float* sD = (float*)(sm + SD_OFF) + kg * 2176;
    int r0 = M0 + (lane >> 2);
#pragma unroll
    for (int nt = 0; nt < 2; nt++) {
        int col = N0 + nt * 8 + (lane & 3) * 2;
        *reinterpret_cast<float2*>(&sD[r0 * 34 + col]) = make_float2(acc[nt][0], acc[nt][1]);
        *reinterpret_cast<float2*>(&sD[(r0 + 8) * 34 + col]) = make_float2(acc[nt][2], acc[nt][3]);
    }
}

// =====================================================================
// k_steps: persistent recurrent kernel. grid 128, 512 threads.
// Two 8-warp k-groups run independent 3-stage pipelines over alternating
// k-chunks (split-K); partial D tiles summed in the 512-thread epilogue.
// ONE grid barrier per step (after L0).
// =====================================================================
__global__ void __launch_bounds__(512, 1) k_steps(
    const float* __restrict__ enc_c,
    const float* __restrict__ b_ih1, const float* __restrict__ b_hh1,
    float* __restrict__ out) {
    extern __shared__ char sm[];
    const uint32_t smb = smem_u32(sm);
    const int tid = threadIdx.x, lane = tid & 31, warp = tid >> 5;
    const int kg = warp >> 3, wl = warp & 7, ktid = tid & 255;
    const int cta = blockIdx.x, hu0 = cta * UPC;
    const int M0 = (wl & 3) * 16, N0 = (wl >> 2) * 16;

    float* sD  = (float*)(sm + SD_OFF);
    float* sP  = (float*)(sm + SP_OFF);
    float* sc0 = (float*)(sm + SC0_OFF);
    float* sc1 = (float*)(sm + SC1_OFF);
    float* sB1 = (float*)(sm + SB1_OFF);

    // CTA-private state: 512 cells, one per thread
    {
        int m = tid >> 3, u = tid & 7;
        sc0[tid] = enc_c[m * HH + hu0 + u];
        sc1[tid] = enc_c[BB * HH + m * HH + hu0 + u];
    }
    if (tid < 32) {
        int col = (tid >> 3) * HH + hu0 + (tid & 7);
        sB1[tid] = b_ih1[col] + b_hh1[col];
    }
    __syncthreads();

    const __half* gB0h = g_B0h + (size_t)cta * 8 * 4096;
    const __half* gB1h = g_B1h + (size_t)cta * 16 * 4096;

    const int ep_m = tid >> 3, ep_u = tid & 7;

#pragma unroll 1
    for (int t = 0; t < SS; t++) {
        const int rd = t & 1, wrb = 1 - rd;

        // ================= phase L0: 8 chunks, 4 per kgroup =================
        {
            const __half* gA = g_h0[rd];
            float acc[2][4];
#pragma unroll
            for (int i = 0; i < 2; i++)
#pragma unroll
                for (int j = 0; j < 4; j++) acc[i][j] = 0.0f;

            // prefetch i=0 (+ P0 row prefetch by every thread)
            copy_chunk(smb, kg * 3, ktid, gA, kg * 128, gB0h + (size_t)kg * 4096);
            {
                int j = tid & 7, q = j >> 1, off = (j & 1) * 4;
                const float* src = g_P0 + ((size_t)t * BB + ep_m) * GG + q * HH + hu0 + off;
                cpa16(smb + SP_OFF + (uint32_t)tid * 16, src);
            }
            CP_COMMIT();
            // prefetch i=1
            copy_chunk(smb, kg * 3 + 1, ktid, gA, (kg + 2) * 128,
                       gB0h + (size_t)(kg + 2) * 4096);
            CP_COMMIT();

#pragma unroll 1
            for (int i = 0; i < 4; i++) {
                if (i < 3) cp_wait<1>(); else cp_wait<0>();
                bar_kg(kg);
                compute_chunk(smb, kg * 3 + (i % 3), lane, M0, N0, acc);
                if (i + 2 < 4) {
                    int c = kg + (i + 2) * 2;
                    copy_chunk(smb, kg * 3 + ((i + 2) % 3), ktid, gA, c * 128,
                               gB0h + (size_t)c * 4096);
                    CP_COMMIT();
                }
            }
            store_accums(sm, kg, lane, M0, N0, acc);
            __syncthreads();

            // epilogue: 512 threads, 1 cell each, summing the two partials
            const float* d0 = sD + ep_m * 34;
            const float* d1 = sD + 2176 + ep_m * 34;
            const float* sPm = sP + ep_m * 32;
            float gi = d0[ep_u]      + d1[ep_u]      + sPm[ep_u];
            float gf = d0[8 + ep_u]  + d1[8 + ep_u]  + sPm[8 + ep_u];
            float gg = d0[16 + ep_u] + d1[16 + ep_u] + sPm[16 + ep_u];
            float go = d0[24 + ep_u] + d1[24 + ep_u] + sPm[24 + ep_u];
            float cn = sigf(gf) * sc0[tid] + sigf(gi) * tanhf(gg);
            sc0[tid] = cn;
            float hv = sigf(go) * tanhf(cn);
            g_h0[wrb][ep_m * HH + hu0 + ep_u] = __float2half(hv);
        }
        grid_bar(tid, (unsigned)(t + 1));

        // ================= phase L1: 16 chunks, 8 per kgroup =================
        {
            const __half* Ah[2] = { g_h0[wrb], g_h1[rd] };
            float acc[2][4];
#pragma unroll
            for (int i = 0; i < 2; i++)
#pragma unroll
                for (int j = 0; j < 4; j++) acc[i][j] = 0.0f;

            copy_chunk(smb, kg * 3, ktid, Ah[kg >> 3] + 0, kg * 128,
                       gB1h + (size_t)kg * 4096);
            CP_COMMIT();
            {
                int c = kg + 2;
                copy_chunk(smb, kg * 3 + 1, ktid, Ah[c >> 3], (c & 7) * 128,
                           gB1h + (size_t)c * 4096);
            }
            CP_COMMIT();

#pragma unroll 1
            for (int i = 0; i < 8; i++) {
                if (i < 7) cp_wait<1>(); else cp_wait<0>();
                bar_kg(kg);
                compute_chunk(smb, kg * 3 + (i % 3), lane, M0, N0, acc);
                if (i + 2 < 8) {
                    int c = kg + (i + 2) * 2;
                    copy_chunk(smb, kg * 3 + ((i + 2) % 3), ktid, Ah[c >> 3],
                               (c & 7) * 128, gB1h + (size_t)c * 4096);
                    CP_COMMIT();
                }
            }
            store_accums(sm, kg, lane, M0, N0, acc);
            __syncthreads();

            const float* d0 = sD + ep_m * 34;
            const float* d1 = sD + 2176 + ep_m * 34;
            float gi = d0[ep_u]      + d1[ep_u]      + sB1[ep_u];
            float gf = d0[8 + ep_u]  + d1[8 + ep_u]  + sB1[8 + ep_u];
            float gg = d0[16 + ep_u] + d1[16 + ep_u] + sB1[16 + ep_u];
            float go = d0[24 + ep_u] + d1[24 + ep_u] + sB1[24 + ep_u];
            float cn = sigf(gf) * sc1[tid] + sigf(gi) * tanhf(gg);
            sc1[tid] = cn;
            float hv = sigf(go) * tanhf(cn);
            int hidx = ep_m * HH + hu0 + ep_u;
            g_h1[wrb][hidx] = __float2half(hv);
            out[(size_t)t * BB * HH + hidx] = hv;
        }
        // no barrier: next step's after-L0 barrier orders h1 for L1(t+1)
    }
}

// =====================================================================
extern "C" void kernel_launch(void* const* d_in, const int* in_sizes, int n_in,
                              void* d_out, int out_size) {
    const int*   tok      = (const int*)d_in[0];
    const int*   src      = (const int*)d_in[1];
    const float* enc_outs = (const float*)d_in[2];
    const float* enc_h    = (const float*)d_in[3];
    const float* enc_c    = (const float*)d_in[4];
    const float* embed    = (const float*)d_in[5];
    const float* W_ih0    = (const float*)d_in[6];
    const float* W_hh0    = (const float*)d_in[7];
    const float* b_ih0    = (const float*)d_in[8];
    const float* b_hh0    = (const float*)d_in[9];
    const float* W_ih1    = (const float*)d_in[10];
    const float* W_hh1    = (const float*)d_in[11];
    const float* b_ih1    = (const float*)d_in[12];
    const float* b_hh1    = (const float*)d_in[13];
    float* out = (float*)d_out;

    cudaFuncSetAttribute(k_steps, cudaFuncAttributeMaxDynamicSharedMemorySize, DYN_STEPS);
    cudaFuncSetAttribute(k_pre, cudaFuncAttributeMaxDynamicSharedMemorySize, DYN_PRE);

    k_emb16<<<32000 * EE / 2048, 256>>>(embed);
    k_static<<<dim3(GG / 256, BB / 8), 256>>>(enc_outs, src, embed, W_ih0, b_ih0, b_hh0);
    k_prep<<<dim3(8, NCTA, 4), 256>>>(W_hh0, W_ih1, W_hh1, W_ih0, enc_h);
    k_pre<<<dim3(SS, 64), 256, DYN_PRE>>>(tok);
    k_steps<<<NCTA, 512, DYN_STEPS>>>(enc_c, b_ih1, b_hh1, out);
}

// round 15
// speedup vs baseline: 6.0644x; 1.0904x over previous
#include <cuda_runtime.h>
#include <cuda_bf16.h>
#include <cuda_fp16.h>
#include <math.h>
#include <stdint.h>

#define BB 64
#define SS 256
#define HH 1024
#define EE 512
#define GG 4096
#define NCTA 128
#define UPC 8     // hidden units per CTA

// ---- k_steps smem: 6 stages (3 per kgroup) of 34816:
//   stage: A(64 x 272B) | B(64 x 272B) at +17408
// Partial-D tiles are OVERLAID on stage buffers (valid only between the
// post-loop __syncthreads and the grid barrier):
//   D1(kg) 64x66 f32 at stage kg*3 + 0;  D2(kg) 64x34 f32 at +16896
#define STG64 34816
#define SP_OFF  208896  // P0 prefetch 64 x 32 f32 = 8192
#define SC0_OFF 217088  // c0 state 512 f32
#define SC1_OFF 219136  // c1 state 512 f32
#define SB1_OFF 221184  // layer1 bias 32 f32
#define DYN_STEPS 221312

// ---- k_pre smem: 2 stages of 34816, tokens after
#define PC_STG 34816
#define PC_TOK 69632
#define DYN_PRE 69888

// -------- device-global scratch --------
__device__ float g_P0[(size_t)SS * BB * GG];
__device__ float g_sp[BB * GG];
__device__ __half g_h0[2][BB * HH];
__device__ __half g_h1[2][BB * HH];
__device__ __align__(16) __half g_emb16[(size_t)32000 * EE];
__device__ __align__(16) __half g_Wx[(size_t)GG * EE];
// combined G1 tile: [cta][chunk 0..7][64n x 128k]  (rows 0-31 W_hh0, 32-63 W_ih1)
__device__ __align__(16) __half g_BW01[(size_t)NCTA * 8 * 8192];
// G2 tile: [cta][chunk 0..7][32n x 128k]  (W_hh1)
__device__ __align__(16) __half g_BW11[(size_t)NCTA * 8 * 4096];
// grid barrier state
__device__ unsigned g_bcnt;
__device__ unsigned g_bgen;

union P8 { __half h[8]; uint4 v; };

__device__ __forceinline__ float sigf(float x) { return 1.0f / (1.0f + expf(-x)); }

__device__ __forceinline__ uint32_t smem_u32(const void* p) {
    uint32_t a;
    asm("{ .reg .u64 t; cvta.to.shared.u64 t, %1; cvt.u32.u64 %0, t; }" : "=r"(a) : "l"(p));
    return a;
}
__device__ __forceinline__ void cpa16(uint32_t d, const void* s) {
    asm volatile("cp.async.cg.shared.global [%0], [%1], 16;" :: "r"(d), "l"(s));
}
#define CP_COMMIT() asm volatile("cp.async.commit_group;" ::: "memory")
template<int N> __device__ __forceinline__ void cp_wait() {
    asm volatile("cp.async.wait_group %0;" :: "n"(N) : "memory");
}
__device__ __forceinline__ void bar_kg(int kg) {
    asm volatile("bar.sync %0, 256;" :: "r"(kg + 1) : "memory");
}

__device__ __forceinline__ void ldsm4(uint32_t* r, uint32_t a) {
    asm volatile("ldmatrix.sync.aligned.m8n8.x4.shared.b16 {%0,%1,%2,%3}, [%4];"
                 : "=r"(r[0]), "=r"(r[1]), "=r"(r[2]), "=r"(r[3]) : "r"(a));
}
__device__ __forceinline__ void mma_f16(float* d, const uint32_t* a, uint32_t b0, uint32_t b1) {
    asm volatile(
        "mma.sync.aligned.m16n8k16.row.col.f32.f16.f16.f32 "
        "{%0,%1,%2,%3}, {%4,%5,%6,%7}, {%8,%9}, {%0,%1,%2,%3};"
        : "+f"(d[0]), "+f"(d[1]), "+f"(d[2]), "+f"(d[3])
        : "r"(a[0]), "r"(a[1]), "r"(a[2]), "r"(a[3]), "r"(b0), "r"(b1));
}

// grid-wide barrier: all 128 CTAs co-resident (1/SM on 148 SMs).
__device__ __forceinline__ void grid_bar(int tid, unsigned gen) {
    __threadfence();
    __syncthreads();
    if (tid == 0) {
        if (atomicAdd(&g_bcnt, 1u) == NCTA - 1) {
            atomicExch(&g_bcnt, 0u);
            __threadfence();
            atomicExch(&g_bgen, gen);
        } else {
            while (atomicOr(&g_bgen, 0u) < gen) {}
            __threadfence();
        }
    }
    __syncthreads();
}

// =====================================================================
// k_emb16: embed fp32 -> fp16 (one-time)
// =====================================================================
__global__ void __launch_bounds__(256) k_emb16(const float* __restrict__ embed) {
    size_t i = ((size_t)blockIdx.x * 256 + threadIdx.x) * 8;
    float x[8];
    *reinterpret_cast<float4*>(x)     = *reinterpret_cast<const float4*>(embed + i);
    *reinterpret_cast<float4*>(x + 4) = *reinterpret_cast<const float4*>(embed + i + 4);
    P8 p;
#pragma unroll
    for (int u = 0; u < 8; u++) p.h[u] = __float2half(x[u]);
    *reinterpret_cast<uint4*>(g_emb16 + i) = p.v;
}

// =====================================================================
// k_static (proven, unchanged)
// =====================================================================
__global__ void __launch_bounds__(256) k_static(
    const float* __restrict__ enc_outs, const int* __restrict__ src_lang,
    const float* __restrict__ embed, const float* __restrict__ W0,
    const float* __restrict__ b_ih0, const float* __restrict__ b_hh0) {
    __shared__ float sC[8][EE];
    __shared__ float sL[8][EE];
    const int tid = threadIdx.x;
    const int b0 = blockIdx.y * 8;
    for (int i = tid; i < 8 * EE; i += 256) {
        int b = i >> 9, k = i & (EE - 1);
        sC[b][k] = enc_outs[((size_t)(b0 + b) * 128 + 127) * EE + k];
        sL[b][k] = embed[(size_t)src_lang[b0 + b] * EE + k];
    }
    __syncthreads();
    const int g = blockIdx.x * 256 + tid;
    const float* wr = W0 + (size_t)g * 1536;
    float acc[8];
#pragma unroll
    for (int i = 0; i < 8; i++) acc[i] = 0.0f;
    for (int k = 0; k < EE; k += 4) {
        float4 wc = *reinterpret_cast<const float4*>(wr + 512 + k);
        float4 wl = *reinterpret_cast<const float4*>(wr + 1024 + k);
#pragma unroll
        for (int b = 0; b < 8; b++) {
            float4 c4 = *reinterpret_cast<const float4*>(&sC[b][k]);
            float4 l4 = *reinterpret_cast<const float4*>(&sL[b][k]);
            acc[b] += wc.x * c4.x + wc.y * c4.y + wc.z * c4.z + wc.w * c4.w;
            acc[b] += wl.x * l4.x + wl.y * l4.y + wl.z * l4.z + wl.w * l4.w;
        }
    }
    float bias = b_ih0[g] + b_hh0[g];
#pragma unroll
    for (int b = 0; b < 8; b++) g_sp[(b0 + b) * GG + g] = acc[b] + bias;
}

// =====================================================================
// k_prep: grid (8, NCTA, 4).
//  z=0: W_hh0 -> g_BW01 rows [0,32)    (+ h-init into buf 1, barrier reset)
//  z=1: W_ih1 -> g_BW01 rows [32,64)
//  z=2: W_hh1 -> g_BW11
//  z=3: W_ih0 x-part -> g_Wx
// =====================================================================
__global__ void __launch_bounds__(256) k_prep(
    const float* __restrict__ W_hh0, const float* __restrict__ W_ih1,
    const float* __restrict__ W_hh1, const float* __restrict__ W_ih0,
    const float* __restrict__ enc_h) {
    const int c = blockIdx.x, cta = blockIdx.y, which = blockIdx.z, tid = threadIdx.x;

    if (which == 3) {
        int flat = cta * 8 + c;
        int row = flat * 4 + (tid >> 6);
        int col = (tid & 63) * 8;
        const float* s = W_ih0 + (size_t)row * 1536 + col;
        float x[8];
        *reinterpret_cast<float4*>(x)     = *reinterpret_cast<const float4*>(s);
        *reinterpret_cast<float4*>(x + 4) = *reinterpret_cast<const float4*>(s + 4);
        P8 p;
#pragma unroll
        for (int u = 0; u < 8; u++) p.h[u] = __float2half(x[u]);
        *reinterpret_cast<uint4*>(g_Wx + (size_t)row * EE + col) = p.v;
        return;
    }

    if (which == 0) {
        int flat = cta * 8 + c;
        if (flat == 0 && tid == 0) { g_bcnt = 0; g_bgen = 0; }
        if (flat < 256) {
            int i = flat * 256 + tid;
            const int n = BB * HH;
            g_h0[1][i] = __float2half(enc_h[i]);      // H0[-1] lives in buf 1
            g_h1[1][i] = __float2half(enc_h[n + i]);  // H1[-1] lives in buf 1
        }
    }

    const float* W = (which == 0) ? W_hh0 : (which == 1) ? W_ih1 : W_hh1;
    const int nloc = tid >> 3, ks = (tid & 7) * 16;
    const int grow = (nloc >> 3) * HH + cta * UPC + (nloc & 7);
    const float* s = W + (size_t)grow * HH + c * 128 + ks;
    float x[16];
#pragma unroll
    for (int i = 0; i < 4; i++)
        *reinterpret_cast<float4*>(x + 4 * i) = *reinterpret_cast<const float4*>(s + 4 * i);
    P8 p0, p1;
#pragma unroll
    for (int u = 0; u < 8; u++) { p0.h[u] = __float2half(x[u]); p1.h[u] = __float2half(x[8 + u]); }
    __half* G;
    size_t base;
    if (which == 0)      { G = g_BW01; base = ((size_t)cta * 8 + c) * 8192; }
    else if (which == 1) { G = g_BW01; base = ((size_t)cta * 8 + c) * 8192 + 4096; }
    else                 { G = g_BW11; base = ((size_t)cta * 8 + c) * 4096; }
    *reinterpret_cast<uint4*>(G + base + (size_t)nloc * 128 + ks)     = p0.v;
    *reinterpret_cast<uint4*>(G + base + (size_t)nloc * 128 + ks + 8) = p1.v;
}

// =====================================================================
// k_pre: HMMA input-gate precompute (proven R13, unchanged)
// =====================================================================
__global__ void __launch_bounds__(256) k_pre(const int* __restrict__ tokens) {
    extern __shared__ char sm[];
    const uint32_t smb = smem_u32(sm);
    const int tid = threadIdx.x, lane = tid & 31, warp = tid >> 5;
    const int t = blockIdx.x, n0 = blockIdx.y;
    const int M0 = (warp & 3) * 16, N0 = (warp >> 2) * 32;
    int* sTok = (int*)(sm + PC_TOK);

    if (tid < 64) sTok[tid] = tokens[tid * SS + t];
    __syncthreads();

    float acc[4][4];
#pragma unroll
    for (int i = 0; i < 4; i++)
#pragma unroll
        for (int j = 0; j < 4; j++) acc[i][j] = 0.0f;

    const __half* wb = g_Wx + (size_t)n0 * 64 * EE;

#pragma unroll 1
    for (int pre = 0; pre < 2; pre++) {
        const uint32_t sb = smb + pre * PC_STG;
        int kbase = pre * 128;
#pragma unroll
        for (int i = tid; i < 1024; i += 256) {
            int row = i >> 4, s = i & 15;
            uint32_t so = (uint32_t)row * 272 + (s << 4);
            cpa16(sb + so, (const char*)(g_emb16 + (size_t)sTok[row] * EE + kbase) + (s << 4));
            cpa16(sb + 17408 + so, (const char*)(wb + (size_t)row * EE + kbase) + (s << 4));
        }
        CP_COMMIT();
    }

#pragma unroll 1
    for (int c = 0; c < 4; c++) {
        if (c < 3) cp_wait<1>(); else cp_wait<0>();
        __syncthreads();
        const uint32_t sb = smb + (c & 1) * PC_STG;
        const uint32_t aoff = (uint32_t)(M0 + (lane & 15)) * 272 + ((lane >> 4) << 4);
        const uint32_t boff = (uint32_t)(N0 + (((lane >> 4) & 1) << 3) + (lane & 7)) * 272 +
                              (((lane >> 3) & 1) << 4);
#pragma unroll
        for (int ksi = 0; ksi < 8; ksi++) {
            const uint32_t kb = ksi << 5;
            uint32_t ah[4], bh[8];
            ldsm4(ah, sb + aoff + kb);
            ldsm4(bh, sb + 17408 + boff + kb);
            ldsm4(bh + 4, sb + 17408 + boff + 4352 + kb);
#pragma unroll
            for (int nt = 0; nt < 4; nt++)
                mma_f16(acc[nt], ah, bh[2 * nt], bh[2 * nt + 1]);
        }
        __syncthreads();
        if (c + 2 < 4) {
            const uint32_t sb2 = smb + ((c + 2) & 1) * PC_STG;
            int kbase = (c + 2) * 128;
#pragma unroll
            for (int i = tid; i < 1024; i += 256) {
                int row = i >> 4, s = i & 15;
                uint32_t so = (uint32_t)row * 272 + (s << 4);
                cpa16(sb2 + so, (const char*)(g_emb16 + (size_t)sTok[row] * EE + kbase) + (s << 4));
                cpa16(sb2 + 17408 + so, (const char*)(wb + (size_t)row * EE + kbase) + (s << 4));
            }
            CP_COMMIT();
        }
    }

    const int r0 = M0 + (lane >> 2);
#pragma unroll
    for (int nt = 0; nt < 4; nt++) {
        int col = n0 * 64 + N0 + nt * 8 + (lane & 3) * 2;
        size_t o0 = ((size_t)t * BB + r0) * GG + col;
        size_t o1 = ((size_t)t * BB + r0 + 8) * GG + col;
        const float* sp0 = g_sp + r0 * GG + col;
        const float* sp1 = g_sp + (r0 + 8) * GG + col;
        *reinterpret_cast<float2*>(g_P0 + o0) =
            make_float2(acc[nt][0] + sp0[0], acc[nt][1] + sp0[1]);
        *reinterpret_cast<float2*>(g_P0 + o1) =
            make_float2(acc[nt][2] + sp1[0], acc[nt][3] + sp1[1]);
    }
}

// =====================================================================
// k_steps building blocks
// =====================================================================
__device__ __forceinline__ void copy_g1(uint32_t sb, int ktid,
                                        const __half* gA, int kbase, const __half* gB) {
#pragma unroll
    for (int i = ktid; i < 1024; i += 256) {
        int row = i >> 4, s = i & 15;
        uint32_t so = (uint32_t)row * 272 + (s << 4);
        cpa16(sb + so, (const char*)(gA + (size_t)row * HH + kbase) + (s << 4));
        cpa16(sb + 17408 + so, (const char*)gB + ((size_t)i << 4));
    }
}
__device__ __forceinline__ void copy_g2(uint32_t sb, int ktid,
                                        const __half* gA, int kbase, const __half* gB) {
#pragma unroll
    for (int i = ktid; i < 1024; i += 256) {
        int row = i >> 4, s = i & 15;
        uint32_t so = (uint32_t)row * 272 + (s << 4);
        cpa16(sb + so, (const char*)(gA + (size_t)row * HH + kbase) + (s << 4));
    }
#pragma unroll
    for (int i = ktid; i < 512; i += 256) {
        int row = i >> 4, s = i & 15;
        uint32_t so = (uint32_t)row * 272 + (s << 4);
        cpa16(sb + 17408 + so, (const char*)gB + ((size_t)i << 4));
    }
}

__device__ __forceinline__ void compute64(uint32_t sb, int lane, int M0, int N0,
                                          float acc[4][4]) {
    const uint32_t aoff = (uint32_t)(M0 + (lane & 15)) * 272 + ((lane >> 4) << 4);
    const uint32_t boff = (uint32_t)(N0 + (((lane >> 4) & 1) << 3) + (lane & 7)) * 272 +
                          (((lane >> 3) & 1) << 4);
#pragma unroll
    for (int ksi = 0; ksi < 8; ksi++) {
        const uint32_t kb = ksi << 5;
        uint32_t ah[4], bh[8];
        ldsm4(ah, sb + aoff + kb);
        ldsm4(bh, sb + 17408 + boff + kb);
        ldsm4(bh + 4, sb + 17408 + boff + 4352 + kb);
#pragma unroll
        for (int nt = 0; nt < 4; nt++)
            mma_f16(acc[nt], ah, bh[2 * nt], bh[2 * nt + 1]);
    }
}
__device__ __forceinline__ void compute32(uint32_t sb, int lane, int M0, int N0,
                                          float acc[2][4]) {
    const uint32_t aoff = (uint32_t)(M0 + (lane & 15)) * 272 + ((lane >> 4) << 4);
    const uint32_t boff = (uint32_t)(N0 + (((lane >> 4) & 1) << 3) + (lane & 7)) * 272 +
                          (((lane >> 3) & 1) << 4);
#pragma unroll
    for (int ksi = 0; ksi < 8; ksi++) {
        const uint32_t kb = ksi << 5;
        uint32_t ah[4], bh[4];
        ldsm4(ah, sb + aoff + kb);
        ldsm4(bh, sb + 17408 + boff + kb);
#pragma unroll
        for (int nt = 0; nt < 2; nt++)
            mma_f16(acc[nt], ah, bh[2 * nt], bh[2 * nt + 1]);
    }
}

// =====================================================================
// k_steps: persistent fused-phase kernel. grid 128, 512 threads.
// Phase p (p=-1..255): GEMM1 = H0[p] @ [W_hh0|W_ih1] (N=64),
//                      GEMM2 = H1[p-1] @ W_hh1      (N=32, p>=0),
// one split-K pipeline (2 kgroups x 3 stages), ONE grid barrier per phase.
// Epilogue updates c0/H0[p+1] (gates = D1[:,0:32]+P0[p+1]) and
// c1/H1[p]/out[p]            (gates = D1[:,32:64]+D2+b1).
// =====================================================================
__global__ void __launch_bounds__(512, 1) k_steps(
    const float* __restrict__ enc_c,
    const float* __restrict__ b_ih1, const float* __restrict__ b_hh1,
    float* __restrict__ out) {
    extern __shared__ char sm[];
    const uint32_t smb = smem_u32(sm);
    const int tid = threadIdx.x, lane = tid & 31, warp = tid >> 5;
    const int kg = warp >> 3, wl = warp & 7, ktid = tid & 255;
    const int cta = blockIdx.x, hu0 = cta * UPC;
    const int M0 = (wl & 3) * 16;
    const int N64 = (wl >> 2) * 32, N32 = (wl >> 2) * 16;

    float* sP  = (float*)(sm + SP_OFF);
    float* sc0 = (float*)(sm + SC0_OFF);
    float* sc1 = (float*)(sm + SC1_OFF);
    float* sB1 = (float*)(sm + SB1_OFF);

    {
        int m = tid >> 3, u = tid & 7;
        sc0[tid] = enc_c[m * HH + hu0 + u];
        sc1[tid] = enc_c[BB * HH + m * HH + hu0 + u];
    }
    if (tid < 32) {
        int col = (tid >> 3) * HH + hu0 + (tid & 7);
        sB1[tid] = b_ih1[col] + b_hh1[col];
    }
    __syncthreads();

    const __half* gBW01 = g_BW01 + (size_t)cta * 8 * 8192;
    const __half* gBW11 = g_BW11 + (size_t)cta * 8 * 4096;

    const int ep_m = tid >> 3, ep_u = tid & 7;
    // D overlays (on stage buffers; valid post-loop only)
    float* D1[2] = { (float*)sm, (float*)(sm + 3 * STG64) };
    float* D2[2] = { (float*)(sm + 16896), (float*)(sm + 3 * STG64 + 16896) };

#pragma unroll 1
    for (int p = -1; p < SS; p++) {
        const int nch = (p < 0) ? 4 : 8;
        const __half* A1 = g_h0[p & 1];
        const __half* A2 = g_h1[(p - 1) & 1];
        const int tP = (p + 1 < SS) ? p + 1 : SS - 1;

        float acc1[4][4], acc2[2][4];
#pragma unroll
        for (int i = 0; i < 4; i++)
#pragma unroll
            for (int j = 0; j < 4; j++) acc1[i][j] = 0.0f;
#pragma unroll
        for (int i = 0; i < 2; i++)
#pragma unroll
            for (int j = 0; j < 4; j++) acc2[i][j] = 0.0f;

        // issue chunk idx: idx<4 -> GEMM1 kchunk 2*idx+kg; else GEMM2 kchunk 2*(idx-4)+kg
        // prefetch idx 0 (+ P0 row prefetch), then idx 1
        {
            int c = kg;
            copy_g1(smb + (kg * 3) * STG64, ktid, A1, c * 128, gBW01 + (size_t)c * 8192);
            int j = tid & 7, q = j >> 1, off = (j & 1) * 4;
            const float* src = g_P0 + ((size_t)tP * BB + ep_m) * GG + q * HH + hu0 + off;
            cpa16(smb + SP_OFF + (uint32_t)tid * 16, src);
            CP_COMMIT();
            c = kg + 2;
            copy_g1(smb + (kg * 3 + 1) * STG64, ktid, A1, c * 128, gBW01 + (size_t)c * 8192);
            CP_COMMIT();
        }

#pragma unroll 1
        for (int idx = 0; idx < nch; idx++) {
            if (idx < nch - 1) cp_wait<1>(); else cp_wait<0>();
            bar_kg(kg);
            uint32_t sb = smb + (kg * 3 + (idx % 3)) * STG64;
            if (idx < 4) compute64(sb, lane, M0, N64, acc1);
            else         compute32(sb, lane, M0, N32, acc2);
            if (idx + 2 < nch) {
                int nx = idx + 2;
                uint32_t sb2 = smb + (kg * 3 + (nx % 3)) * STG64;
                if (nx < 4) {
                    int c = 2 * nx + kg;
                    copy_g1(sb2, ktid, A1, c * 128, gBW01 + (size_t)c * 8192);
                } else {
                    int c = 2 * (nx - 4) + kg;
                    copy_g2(sb2, ktid, A2, c * 128, gBW11 + (size_t)c * 4096);
                }
                CP_COMMIT();
            }
        }
        __syncthreads();   // all stage reads done -> overlay D on stage mem

        {
            float* d1 = D1[kg];
            int r0 = M0 + (lane >> 2);
#pragma unroll
            for (int nt = 0; nt < 4; nt++) {
                int col = N64 + nt * 8 + (lane & 3) * 2;
                *reinterpret_cast<float2*>(&d1[r0 * 66 + col]) =
                    make_float2(acc1[nt][0], acc1[nt][1]);
                *reinterpret_cast<float2*>(&d1[(r0 + 8) * 66 + col]) =
                    make_float2(acc1[nt][2], acc1[nt][3]);
            }
            if (p >= 0) {
                float* d2 = D2[kg];
#pragma unroll
                for (int nt = 0; nt < 2; nt++) {
                    int col = N32 + nt * 8 + (lane & 3) * 2;
                    *reinterpret_cast<float2*>(&d2[r0 * 34 + col]) =
                        make_float2(acc2[nt][0], acc2[nt][1]);
                    *reinterpret_cast<float2*>(&d2[(r0 + 8) * 34 + col]) =
                        make_float2(acc2[nt][2], acc2[nt][3]);
                }
            }
        }
        __syncthreads();

        // ---- epilogue: layer0 (step p+1) ----
        {
            const float* a = D1[0] + ep_m * 66;
            const float* b = D1[1] + ep_m * 66;
            const float* sPm = sP + ep_m * 32;
            float gi = a[ep_u]      + b[ep_u]      + sPm[ep_u];
            float gf = a[8 + ep_u]  + b[8 + ep_u]  + sPm[8 + ep_u];
            float gg = a[16 + ep_u] + b[16 + ep_u] + sPm[16 + ep_u];
            float go = a[24 + ep_u] + b[24 + ep_u] + sPm[24 + ep_u];
            float cn = sigf(gf) * sc0[tid] + sigf(gi) * tanhf(gg);
            sc0[tid] = cn;
            g_h0[(p + 1) & 1][ep_m * HH + hu0 + ep_u] =
                __float2half(sigf(go) * tanhf(cn));
        }
        // ---- epilogue: layer1 (step p) ----
        if (p >= 0) {
            const float* a = D1[0] + ep_m * 66 + 32;
            const float* b = D1[1] + ep_m * 66 + 32;
            const float* c2a = D2[0] + ep_m * 34;
            const float* c2b = D2[1] + ep_m * 34;
            float gi = a[ep_u]      + b[ep_u]      + c2a[ep_u]      + c2b[ep_u]      + sB1[ep_u];
            float gf = a[8 + ep_u]  + b[8 + ep_u]  + c2a[8 + ep_u]  + c2b[8 + ep_u]  + sB1[8 + ep_u];
            float gg = a[16 + ep_u] + b[16 + ep_u] + c2a[16 + ep_u] + c2b[16 + ep_u] + sB1[16 + ep_u];
            float go = a[24 + ep_u] + b[24 + ep_u] + c2a[24 + ep_u] + c2b[24 + ep_u] + sB1[24 + ep_u];
            float cn = sigf(gf) * sc1[tid] + sigf(gi) * tanhf(gg);
            sc1[tid] = cn;
            float hv = sigf(go) * tanhf(cn);
            int hidx = ep_m * HH + hu0 + ep_u;
            g_h1[p & 1][hidx] = __float2half(hv);
            out[(size_t)p * BB * HH + hidx] = hv;
        }
        grid_bar(tid, (unsigned)(p + 2));
    }
}

// =====================================================================
extern "C" void kernel_launch(void* const* d_in, const int* in_sizes, int n_in,
                              void* d_out, int out_size) {
    const int*   tok      = (const int*)d_in[0];
    const int*   src      = (const int*)d_in[1];
    const float* enc_outs = (const float*)d_in[2];
    const float* enc_h    = (const float*)d_in[3];
    const float* enc_c    = (const float*)d_in[4];
    const float* embed    = (const float*)d_in[5];
    const float* W_ih0    = (const float*)d_in[6];
    const float* W_hh0    = (const float*)d_in[7];
    const float* b_ih0    = (const float*)d_in[8];
    const float* b_hh0    = (const float*)d_in[9];
    const float* W_ih1    = (const float*)d_in[10];
    const float* W_hh1    = (const float*)d_in[11];
    const float* b_ih1    = (const float*)d_in[12];
    const float* b_hh1    = (const float*)d_in[13];
    float* out = (float*)d_out;

    cudaFuncSetAttribute(k_steps, cudaFuncAttributeMaxDynamicSharedMemorySize, DYN_STEPS);
    cudaFuncSetAttribute(k_pre, cudaFuncAttributeMaxDynamicSharedMemorySize, DYN_PRE);

    k_emb16<<<32000 * EE / 2048, 256>>>(embed);
    k_static<<<dim3(GG / 256, BB / 8), 256>>>(enc_outs, src, embed, W_ih0, b_ih0, b_hh0);
    k_prep<<<dim3(8, NCTA, 4), 256>>>(W_hh0, W_ih1, W_hh1, W_ih0, enc_h);
    k_pre<<<dim3(SS, 64), 256, DYN_PRE>>>(tok);
    k_steps<<<NCTA, 512, DYN_STEPS>>>(enc_c, b_ih1, b_hh1, out);
}